// round 1
// baseline (speedup 1.0000x reference)
#include <cuda_runtime.h>
#include <math.h>

#define NDET 256
#define MTRK 256
#define VN   512
#define PPTS 512
#define TSTE 10

// ---------------- device scratch (static, allocation-free) ----------------
__device__ float g_h[VN*128];
__device__ float g_Th[VN*128];
__device__ float g_Q[VN*128];
__device__ float g_P[NDET*64];
__device__ float g_wtT[4*128*128];
__device__ float g_wdT[4*128*128];
__device__ float g_bsum[4*128];
__device__ float g_w1T[128*64];
__device__ unsigned g_mask[VN*16];

// ---------------- prep: transposes + mask bits ----------------
__global__ void prep_kernel(const float* gc_wt, const float* gc_bt,
                            const float* gc_wp, const float* gc_bp,
                            const float* er_w1, const int* adj) {
    int idx = blockIdx.x*blockDim.x + threadIdx.x;
    int stride = gridDim.x*blockDim.x;
    for (int i = idx; i < 4*128*128; i += stride) {
        int l = i >> 14, r = (i >> 7) & 127, k = i & 127;
        float wt = gc_wt[i], wp = gc_wp[i];
        g_wtT[l*16384 + k*128 + r] = wt;
        g_wdT[l*16384 + k*128 + r] = wp - wt;
    }
    for (int i = idx; i < 4*128; i += stride) g_bsum[i] = gc_bt[i] + gc_bp[i];
    for (int i = idx; i < 64*128; i += stride) {
        int r = i >> 7, k = i & 127;
        g_w1T[k*64 + r] = er_w1[i];
    }
    for (int w = idx; w < VN*16; w += stride) {
        int i = w >> 4, wo = w & 15;
        unsigned bits = 0;
        #pragma unroll
        for (int b = 0; b < 32; b++) {
            int j = wo*32 + b;
            if (adj[j*VN + i] != 0 || j == i) bits |= (1u << b);
        }
        g_mask[w] = bits;
    }
}

// ---------------- PointNet: fused 3-layer MLP + maxpool, one item per CTA ----------------
// smem floats: W1 320 | B1 64 | W2 8192 | B2 128 | W3 8192 | B3 64 | H1 128*65 | H2 128*132 | Red 1024
#define PN_SMEM_FLOATS (320+64+8192+128+8192+64+128*65+128*132+1024)

__global__ void pointnet_kernel(const float* det_pts, const float* trk_pts,
                                const float* w1, const float* b1,
                                const float* w2, const float* b2,
                                const float* w3, const float* b3) {
    extern __shared__ float sm[];
    float* sW1 = sm;              // [c][o] 5x64
    float* sB1 = sW1 + 320;
    float* sW2 = sB1 + 64;        // [k][j] 64x128
    float* sB2 = sW2 + 8192;
    float* sW3 = sB2 + 128;       // [k][o] 128x64
    float* sB3 = sW3 + 8192;
    float* sH1 = sB3 + 64;        // [p][o] stride 65
    float* sH2 = sH1 + 128*65;    // [p][j] stride 132
    float* sRed = sH2 + 128*132;  // [16][64]

    int tid = threadIdx.x;
    int item = blockIdx.x;
    const float* pts = (item < NDET) ? det_pts + (size_t)item*PPTS*5
                                     : trk_pts + (size_t)(item-NDET)*PPTS*5;

    for (int i = tid; i < 320; i += 256) { int o = i/5, c = i%5; sW1[c*64+o] = w1[i]; }
    for (int i = tid; i < 8192; i += 256) { int j = i>>6, k = i&63;  sW2[k*128+j] = w2[i]; }
    for (int i = tid; i < 8192; i += 256) { int o = i>>7, k = i&127; sW3[k*64+o]  = w3[i]; }
    if (tid < 64)  sB1[tid] = b1[tid];
    if (tid < 128) sB2[tid] = b2[tid];
    if (tid < 64)  sB3[tid] = b3[tid];
    __syncthreads();

    int ty = tid >> 4, tx = tid & 15;
    float rmax[4] = {-3.4e38f, -3.4e38f, -3.4e38f, -3.4e38f};

    for (int tile = 0; tile < 4; tile++) {
        // ---- layer 1: 5 -> 64, relu ----
        {
            int p = tid & 127, half = tid >> 7;
            const float* xp = pts + (size_t)(tile*128 + p)*5;
            float x0 = xp[0], x1 = xp[1], x2 = xp[2], x3 = xp[3], x4 = xp[4];
            int ob = half*32;
            #pragma unroll
            for (int o = 0; o < 32; o++) {
                int oo = ob + o;
                float a = sB1[oo] + x0*sW1[oo] + x1*sW1[64+oo] + x2*sW1[128+oo]
                                  + x3*sW1[192+oo] + x4*sW1[256+oo];
                sH1[p*65 + oo] = fmaxf(a, 0.f);
            }
        }
        __syncthreads();
        // ---- layer 2: 64 -> 128, relu; 8x8 register tile per thread ----
        {
            float acc[8][8];
            #pragma unroll
            for (int i = 0; i < 8; i++)
                #pragma unroll
                for (int j = 0; j < 8; j++) acc[i][j] = 0.f;
            for (int k = 0; k < 64; k++) {
                float a[8];
                #pragma unroll
                for (int i = 0; i < 8; i++) a[i] = sH1[(8*ty + i)*65 + k];
                float4 bv0 = *(const float4*)&sW2[k*128 + 8*tx];
                float4 bv1 = *(const float4*)&sW2[k*128 + 8*tx + 4];
                float b[8] = {bv0.x, bv0.y, bv0.z, bv0.w, bv1.x, bv1.y, bv1.z, bv1.w};
                #pragma unroll
                for (int i = 0; i < 8; i++)
                    #pragma unroll
                    for (int j = 0; j < 8; j++) acc[i][j] += a[i]*b[j];
            }
            #pragma unroll
            for (int i = 0; i < 8; i++) {
                float4 v0, v1;
                v0.x = fmaxf(acc[i][0] + sB2[8*tx+0], 0.f);
                v0.y = fmaxf(acc[i][1] + sB2[8*tx+1], 0.f);
                v0.z = fmaxf(acc[i][2] + sB2[8*tx+2], 0.f);
                v0.w = fmaxf(acc[i][3] + sB2[8*tx+3], 0.f);
                v1.x = fmaxf(acc[i][4] + sB2[8*tx+4], 0.f);
                v1.y = fmaxf(acc[i][5] + sB2[8*tx+5], 0.f);
                v1.z = fmaxf(acc[i][6] + sB2[8*tx+6], 0.f);
                v1.w = fmaxf(acc[i][7] + sB2[8*tx+7], 0.f);
                *(float4*)&sH2[(8*ty + i)*132 + 8*tx]     = v0;
                *(float4*)&sH2[(8*ty + i)*132 + 8*tx + 4] = v1;
            }
        }
        __syncthreads();
        // ---- layer 3: 128 -> 64 (no relu), per-thread column max ----
        {
            float acc[8][4];
            #pragma unroll
            for (int i = 0; i < 8; i++)
                #pragma unroll
                for (int j = 0; j < 4; j++) acc[i][j] = 0.f;
            for (int k = 0; k < 128; k++) {
                float a[8];
                #pragma unroll
                for (int i = 0; i < 8; i++) a[i] = sH2[(8*ty + i)*132 + k];
                float4 b = *(const float4*)&sW3[k*64 + 4*tx];
                #pragma unroll
                for (int i = 0; i < 8; i++) {
                    acc[i][0] += a[i]*b.x; acc[i][1] += a[i]*b.y;
                    acc[i][2] += a[i]*b.z; acc[i][3] += a[i]*b.w;
                }
            }
            #pragma unroll
            for (int j = 0; j < 4; j++) {
                float mm = acc[0][j];
                #pragma unroll
                for (int i = 1; i < 8; i++) mm = fmaxf(mm, acc[i][j]);
                rmax[j] = fmaxf(rmax[j], mm);
            }
        }
        // no extra sync needed: next tile's post-layer1 sync separates the hazards
    }
    #pragma unroll
    for (int j = 0; j < 4; j++) sRed[ty*64 + 4*tx + j] = rmax[j];
    __syncthreads();
    if (tid < 64) {
        float mm = -3.4e38f;
        #pragma unroll
        for (int t = 0; t < 16; t++) mm = fmaxf(mm, sRed[t*64 + tid]);
        g_h[item*128 + tid] = mm + sB3[tid];   // bias after max (per-channel const)
    }
}

// ---------------- det motion MLP: 9 -> 32 relu -> 64 ----------------
__global__ void detmot_kernel(const float* boxes, const float* w1, const float* b1,
                              const float* w2, const float* b2) {
    int i = blockIdx.x*blockDim.x + threadIdx.x;
    if (i >= NDET) return;
    float x[9];
    #pragma unroll
    for (int c = 0; c < 9; c++) x[c] = boxes[i*9 + c];
    float h[32];
    #pragma unroll
    for (int r = 0; r < 32; r++) {
        float a = b1[r];
        #pragma unroll
        for (int c = 0; c < 9; c++) a += x[c]*w1[r*9 + c];
        h[r] = fmaxf(a, 0.f);
    }
    for (int o = 0; o < 64; o++) {
        float a = b2[o];
        #pragma unroll
        for (int r = 0; r < 32; r++) a += h[r]*w2[o*32 + r];
        g_h[i*128 + 64 + o] = a;
    }
}

// ---------------- 2-layer LSTM, 2 tracks per CTA, weights transposed in smem ----------------
#define LSTM_SMEM_FLOATS (9*256 + 3*64*256 + 256 + 256 + 128 + 2*640)

__device__ __forceinline__ float sigmf(float x) { return 1.f/(1.f + expf(-x)); }

__global__ void lstm_kernel(const float* tb,
                            const float* wih0, const float* whh0,
                            const float* bih0, const float* bhh0,
                            const float* wih1, const float* whh1,
                            const float* bih1, const float* bhh1) {
    extern __shared__ float sm[];
    float* sWih0 = sm;                 // [c][r] 9x256
    float* sWhh0 = sWih0 + 9*256;      // [k][r] 64x256
    float* sWih1 = sWhh0 + 64*256;     // [k][r] 64x256
    float* sWhh1 = sWih1 + 64*256;     // [k][r] 64x256
    float* sB0   = sWhh1 + 64*256;     // 256 (bih+bhh)
    float* sB1   = sB0 + 256;          // 256
    float* sH    = sB1 + 256;          // [2][64]
    float* sHs0  = sH + 128;           // [2][10*64]

    int tid = threadIdx.x;
    for (int i = tid; i < 2304; i += 128)  { int r = i/9,  c = i%9;   sWih0[c*256+r] = wih0[i]; }
    for (int i = tid; i < 16384; i += 128) { int r = i>>6, k = i&63;  sWhh0[k*256+r] = whh0[i]; }
    for (int i = tid; i < 16384; i += 128) { int r = i>>6, k = i&63;  sWih1[k*256+r] = wih1[i]; }
    for (int i = tid; i < 16384; i += 128) { int r = i>>6, k = i&63;  sWhh1[k*256+r] = whh1[i]; }
    for (int i = tid; i < 256; i += 128) { sB0[i] = bih0[i]+bhh0[i]; sB1[i] = bih1[i]+bhh1[i]; }

    int sub = tid >> 6, u = tid & 63;
    int m = blockIdx.x*2 + sub;
    sH[sub*64 + u] = 0.f;
    __syncthreads();

    float cc = 0.f;
    // layer 0
    for (int t = 0; t < TSTE; t++) {
        const float* x = tb + (size_t)(m*TSTE + t)*9;
        float xr[9];
        #pragma unroll
        for (int c = 0; c < 9; c++) xr[c] = x[c];
        float g[4];
        #pragma unroll
        for (int gi = 0; gi < 4; gi++) {
            int r = gi*64 + u;
            float a = sB0[r];
            #pragma unroll
            for (int c = 0; c < 9; c++) a += xr[c]*sWih0[c*256 + r];
            for (int k = 0; k < 64; k++) a += sH[sub*64 + k]*sWhh0[k*256 + r];
            g[gi] = a;
        }
        float ig = sigmf(g[0]), fg = sigmf(g[1]), gg = tanhf(g[2]), og = sigmf(g[3]);
        cc = fg*cc + ig*gg;
        float hn = og*tanhf(cc);
        __syncthreads();
        sH[sub*64 + u] = hn;
        sHs0[sub*640 + t*64 + u] = hn;
        __syncthreads();
    }
    // layer 1
    sH[sub*64 + u] = 0.f;
    cc = 0.f;
    __syncthreads();
    float hn = 0.f;
    for (int t = 0; t < TSTE; t++) {
        float g[4];
        #pragma unroll
        for (int gi = 0; gi < 4; gi++) {
            int r = gi*64 + u;
            float a = sB1[r];
            for (int k = 0; k < 64; k++) a += sHs0[sub*640 + t*64 + k]*sWih1[k*256 + r];
            for (int k = 0; k < 64; k++) a += sH[sub*64 + k]*sWhh1[k*256 + r];
            g[gi] = a;
        }
        float ig = sigmf(g[0]), fg = sigmf(g[1]), gg = tanhf(g[2]), og = sigmf(g[3]);
        cc = fg*cc + ig*gg;
        hn = og*tanhf(cc);
        __syncthreads();
        sH[sub*64 + u] = hn;
        __syncthreads();
    }
    g_h[(NDET + m)*128 + 64 + u] = hn;
}

// ---------------- EdgeConv part A: Th = h@Wt^T,  Q = h@(Wp-Wt)^T + bt+bp ----------------
__global__ void thq_kernel(int l) {
    __shared__ float sh[128];
    int i = blockIdx.x, c = threadIdx.x;
    sh[c] = g_h[i*128 + c];
    __syncthreads();
    const float* wt = g_wtT + l*16384;
    const float* wd = g_wdT + l*16384;
    float th = 0.f, q = 0.f;
    #pragma unroll 8
    for (int k = 0; k < 128; k++) {
        float hv = sh[k];
        th += hv*wt[k*128 + c];
        q  += hv*wd[k*128 + c];
    }
    g_Th[i*128 + c] = th;
    g_Q[i*128 + c]  = q + g_bsum[l*128 + c];
}

// ---------------- EdgeConv part B: masked neighbor max + relu, 4 nodes per CTA ----------------
__global__ void edge_kernel() {
    __shared__ float sTh[64*128];
    __shared__ unsigned smask[64];
    int c = threadIdx.x;
    int i0 = blockIdx.x*4;
    if (c < 64) smask[c] = g_mask[i0*16 + c];
    float m0 = -3.4e38f, m1 = m0, m2 = m0, m3 = m0;
    for (int jc = 0; jc < 8; jc++) {
        __syncthreads();
        for (int t = c; t < 8192; t += 128) sTh[t] = g_Th[jc*8192 + t];
        __syncthreads();
        #pragma unroll
        for (int half = 0; half < 2; half++) {
            int wi = jc*2 + half;
            unsigned w0 = smask[0*16 + wi], w1 = smask[1*16 + wi];
            unsigned w2 = smask[2*16 + wi], w3 = smask[3*16 + wi];
            #pragma unroll 8
            for (int jj = 0; jj < 32; jj++) {
                float v = sTh[(half*32 + jj)*128 + c];
                unsigned bit = 1u << jj;
                if (w0 & bit) m0 = fmaxf(m0, v);
                if (w1 & bit) m1 = fmaxf(m1, v);
                if (w2 & bit) m2 = fmaxf(m2, v);
                if (w3 & bit) m3 = fmaxf(m3, v);
            }
        }
    }
    g_h[(i0+0)*128 + c] = fmaxf(m0 + g_Q[(i0+0)*128 + c], 0.f);
    g_h[(i0+1)*128 + c] = fmaxf(m1 + g_Q[(i0+1)*128 + c], 0.f);
    g_h[(i0+2)*128 + c] = fmaxf(m2 + g_Q[(i0+2)*128 + c], 0.f);
    g_h[(i0+3)*128 + c] = fmaxf(m3 + g_Q[(i0+3)*128 + c], 0.f);
}

// ---------------- affinity: P = h[:256] @ er_w1^T ----------------
__global__ void pproj_kernel() {
    __shared__ float sh[128];
    int i = blockIdx.x, c = threadIdx.x;  // 64 threads
    sh[c]      = g_h[i*128 + c];
    sh[64 + c] = g_h[i*128 + 64 + c];
    __syncthreads();
    float a = 0.f;
    #pragma unroll 8
    for (int k = 0; k < 128; k++) a += sh[k]*g_w1T[k*64 + c];
    g_P[i*64 + c] = a;
}

// ---------------- affinity: pairwise relu + w2 dot + sigmoid ----------------
__global__ void pair_kernel(const float* b1, const float* w2, const float* b2, float* out) {
    __shared__ float sPi[16*65], sPj[16*65], sw2[64], sb1v[64];
    int tid = threadIdx.x;
    int ib = (blockIdx.x >> 4)*16, jb = (blockIdx.x & 15)*16;
    for (int t = tid; t < 1024; t += 256) {
        int r = t >> 6, c = t & 63;
        sPi[r*65 + c] = g_P[(ib + r)*64 + c];
        sPj[r*65 + c] = g_P[(jb + r)*64 + c];
    }
    if (tid < 64) { sw2[tid] = w2[tid]; sb1v[tid] = b1[tid]; }
    __syncthreads();
    int ti = tid >> 4, tj = tid & 15;
    float s = b2[0];
    #pragma unroll 8
    for (int c = 0; c < 64; c++)
        s += sw2[c]*fmaxf(sPj[tj*65 + c] - sPi[ti*65 + c] + sb1v[c], 0.f);
    out[(ib + ti)*256 + jb + tj] = 1.f/(1.f + expf(-s));
}

// ---------------- launch ----------------
extern "C" void kernel_launch(void* const* d_in, const int* in_sizes, int n_in,
                              void* d_out, int out_size) {
    const float* det_pts   = (const float*)d_in[0];
    const float* det_boxes = (const float*)d_in[1];
    const float* trk_pts   = (const float*)d_in[2];
    const float* trk_boxes = (const float*)d_in[3];
    const int*   adj       = (const int*)  d_in[4];
    const float* pn_w1 = (const float*)d_in[5];
    const float* pn_b1 = (const float*)d_in[6];
    const float* pn_w2 = (const float*)d_in[7];
    const float* pn_b2 = (const float*)d_in[8];
    const float* pn_w3 = (const float*)d_in[9];
    const float* pn_b3 = (const float*)d_in[10];
    const float* dm_w1 = (const float*)d_in[11];
    const float* dm_b1 = (const float*)d_in[12];
    const float* dm_w2 = (const float*)d_in[13];
    const float* dm_b2 = (const float*)d_in[14];
    const float* l0_wih = (const float*)d_in[15];
    const float* l0_whh = (const float*)d_in[16];
    const float* l0_bih = (const float*)d_in[17];
    const float* l0_bhh = (const float*)d_in[18];
    const float* l1_wih = (const float*)d_in[19];
    const float* l1_whh = (const float*)d_in[20];
    const float* l1_bih = (const float*)d_in[21];
    const float* l1_bhh = (const float*)d_in[22];
    const float* gc_wt = (const float*)d_in[23];
    const float* gc_bt = (const float*)d_in[24];
    const float* gc_wp = (const float*)d_in[25];
    const float* gc_bp = (const float*)d_in[26];
    const float* er_w1 = (const float*)d_in[27];
    const float* er_b1 = (const float*)d_in[28];
    const float* er_w2 = (const float*)d_in[29];
    const float* er_b2 = (const float*)d_in[30];
    float* out = (float*)d_out;

    cudaFuncSetAttribute(pointnet_kernel, cudaFuncAttributeMaxDynamicSharedMemorySize,
                         PN_SMEM_FLOATS*4);
    cudaFuncSetAttribute(lstm_kernel, cudaFuncAttributeMaxDynamicSharedMemorySize,
                         LSTM_SMEM_FLOATS*4);

    prep_kernel<<<256, 256>>>(gc_wt, gc_bt, gc_wp, gc_bp, er_w1, adj);
    pointnet_kernel<<<512, 256, PN_SMEM_FLOATS*4>>>(det_pts, trk_pts,
        pn_w1, pn_b1, pn_w2, pn_b2, pn_w3, pn_b3);
    detmot_kernel<<<2, 128>>>(det_boxes, dm_w1, dm_b1, dm_w2, dm_b2);
    lstm_kernel<<<128, 128, LSTM_SMEM_FLOATS*4>>>(trk_boxes,
        l0_wih, l0_whh, l0_bih, l0_bhh, l1_wih, l1_whh, l1_bih, l1_bhh);

    for (int l = 0; l < 4; l++) {
        thq_kernel<<<512, 128>>>(l);
        edge_kernel<<<128, 128>>>();
        if (l == 0) {
            pproj_kernel<<<256, 64>>>();
            pair_kernel<<<256, 256>>>(er_b1, er_w2, er_b2, out);
        }
    }
    pproj_kernel<<<256, 64>>>();
    pair_kernel<<<256, 256>>>(er_b1, er_w2, er_b2, out + 65536);
}

// round 2
// speedup vs baseline: 1.0212x; 1.0212x over previous
#include <cuda_runtime.h>
#include <math.h>

#define NDET 256
#define MTRK 256
#define VN   512
#define PPTS 512
#define TSTE 10

typedef unsigned long long ull;

__device__ __forceinline__ void fma2(ull &d, ull a, ull b) {
    asm("fma.rn.f32x2 %0, %1, %2, %0;" : "+l"(d) : "l"(a), "l"(b));
}
__device__ __forceinline__ ull pack2(float x, float y) {
    ull r; asm("mov.b64 %0, {%1, %2};" : "=l"(r) : "f"(x), "f"(y)); return r;
}
__device__ __forceinline__ float2 unpack2(ull v) {
    float2 r; asm("mov.b64 {%0, %1}, %2;" : "=f"(r.x), "=f"(r.y) : "l"(v)); return r;
}
__device__ __forceinline__ float ex2a(float x) { float y; asm("ex2.approx.f32 %0, %1;" : "=f"(y) : "f"(x)); return y; }
__device__ __forceinline__ float rcpa(float x) { float y; asm("rcp.approx.f32 %0, %1;" : "=f"(y) : "f"(x)); return y; }
__device__ __forceinline__ float sigmf(float x) { return rcpa(1.f + ex2a(-1.4426950408889634f * x)); }
__device__ __forceinline__ float tanhf_(float x) { return 2.f * sigmf(2.f * x) - 1.f; }

// ---------------- device scratch (static, allocation-free) ----------------
__device__ float g_h[VN*128];
__device__ float g_Th[VN*128];
__device__ float g_Q[VN*128];
__device__ float g_P[NDET*64];
__device__ float g_wtd[4*128*128*2];   // [l][k][c][{wt, wp-wt}]
__device__ float g_bsum[4*128];
__device__ float g_w1p[64*128];        // [k/2][c][2]
__device__ unsigned g_mask[VN*16];
__device__ float g_pnpart[VN*128];     // [item][half][64]

// ---------------- prep: transposes + mask bits ----------------
__global__ void prep_kernel(const float* gc_wt, const float* gc_bt,
                            const float* gc_wp, const float* gc_bp,
                            const float* er_w1, const int* adj) {
    int idx = blockIdx.x*blockDim.x + threadIdx.x;
    int stride = gridDim.x*blockDim.x;
    for (int i = idx; i < 4*128*128; i += stride) {
        int l = i >> 14, r = (i >> 7) & 127, k = i & 127;
        float wt = gc_wt[i], wp = gc_wp[i];
        g_wtd[l*32768 + (k*128 + r)*2 + 0] = wt;
        g_wtd[l*32768 + (k*128 + r)*2 + 1] = wp - wt;
    }
    for (int i = idx; i < 4*128; i += stride) g_bsum[i] = gc_bt[i] + gc_bp[i];
    for (int i = idx; i < 64*128; i += stride) {
        int r = i >> 7, k = i & 127;
        g_w1p[((k >> 1)*64 + r)*2 + (k & 1)] = er_w1[i];
    }
    for (int w = idx; w < VN*16; w += stride) {
        int i = w >> 4, wo = w & 15;
        unsigned bits = 0;
        #pragma unroll
        for (int b = 0; b < 32; b++) {
            int j = wo*32 + b;
            if (adj[j*VN + i] != 0 || j == i) bits |= (1u << b);
        }
        g_mask[w] = bits;
    }
}

// ---------------- PointNet: fused 3-layer MLP + maxpool, 2 tiles per CTA ----------------
#define PN_SMEM_FLOATS (320+64+8192+128+8192+64+128*65+128*132+1024)

__global__ void pointnet_kernel(const float* det_pts, const float* trk_pts,
                                const float* w1, const float* b1,
                                const float* w2, const float* b2,
                                const float* w3, const float* b3) {
    extern __shared__ float sm[];
    float* sW1 = sm;              // [c][o] 5x64
    float* sB1 = sW1 + 320;
    float* sW2 = sB1 + 64;        // [k][j] 64x128
    float* sB2 = sW2 + 8192;
    float* sW3 = sB2 + 128;       // [k][o] 128x64
    float* sB3 = sW3 + 8192;
    float* sH1 = sB3 + 64;        // [p][o] stride 65
    float* sH2 = sH1 + 128*65;    // [p][j] stride 132
    float* sRed = sH2 + 128*132;  // [16][64]

    int tid = threadIdx.x;
    int item = blockIdx.x >> 1;
    int half = blockIdx.x & 1;
    const float* pts = (item < NDET) ? det_pts + (size_t)item*PPTS*5
                                     : trk_pts + (size_t)(item-NDET)*PPTS*5;

    for (int i = tid; i < 320; i += 256) { int o = i/5, c = i%5; sW1[c*64+o] = w1[i]; }
    for (int i = tid; i < 8192; i += 256) { int j = i>>6, k = i&63;  sW2[k*128+j] = w2[i]; }
    for (int i = tid; i < 8192; i += 256) { int o = i>>7, k = i&127; sW3[k*64+o]  = w3[i]; }
    if (tid < 64)  sB1[tid] = b1[tid];
    if (tid < 128) sB2[tid] = b2[tid];
    __syncthreads();

    int ty = tid >> 4, tx = tid & 15;
    float rmax[4] = {-3.4e38f, -3.4e38f, -3.4e38f, -3.4e38f};

    for (int tile = 0; tile < 2; tile++) {
        int tileIdx = half*2 + tile;
        // ---- layer 1: 5 -> 64, relu ----
        {
            int p = tid & 127, hh = tid >> 7;
            const float* xp = pts + (size_t)(tileIdx*128 + p)*5;
            float x0 = xp[0], x1 = xp[1], x2 = xp[2], x3 = xp[3], x4 = xp[4];
            int ob = hh*32;
            #pragma unroll
            for (int o = 0; o < 32; o++) {
                int oo = ob + o;
                float a = sB1[oo] + x0*sW1[oo] + x1*sW1[64+oo] + x2*sW1[128+oo]
                                  + x3*sW1[192+oo] + x4*sW1[256+oo];
                sH1[p*65 + oo] = fmaxf(a, 0.f);
            }
        }
        __syncthreads();
        // ---- layer 2: 64 -> 128, relu; f32x2 packed, 8x8 tile per thread ----
        {
            ull acc[8][4];
            #pragma unroll
            for (int i = 0; i < 8; i++)
                #pragma unroll
                for (int j = 0; j < 4; j++) acc[i][j] = 0ULL;
            for (int k = 0; k < 64; k++) {
                ull aa[8];
                #pragma unroll
                for (int i = 0; i < 8; i++) {
                    float a = sH1[(8*ty + i)*65 + k];
                    aa[i] = pack2(a, a);
                }
                ulonglong2 bA = *(const ulonglong2*)&sW2[k*128 + 8*tx];
                ulonglong2 bB = *(const ulonglong2*)&sW2[k*128 + 8*tx + 4];
                #pragma unroll
                for (int i = 0; i < 8; i++) {
                    fma2(acc[i][0], aa[i], bA.x);
                    fma2(acc[i][1], aa[i], bA.y);
                    fma2(acc[i][2], aa[i], bB.x);
                    fma2(acc[i][3], aa[i], bB.y);
                }
            }
            #pragma unroll
            for (int i = 0; i < 8; i++) {
                float4 v0, v1;
                float2 p0 = unpack2(acc[i][0]), p1 = unpack2(acc[i][1]);
                float2 p2 = unpack2(acc[i][2]), p3 = unpack2(acc[i][3]);
                v0.x = fmaxf(p0.x + sB2[8*tx+0], 0.f);
                v0.y = fmaxf(p0.y + sB2[8*tx+1], 0.f);
                v0.z = fmaxf(p1.x + sB2[8*tx+2], 0.f);
                v0.w = fmaxf(p1.y + sB2[8*tx+3], 0.f);
                v1.x = fmaxf(p2.x + sB2[8*tx+4], 0.f);
                v1.y = fmaxf(p2.y + sB2[8*tx+5], 0.f);
                v1.z = fmaxf(p3.x + sB2[8*tx+6], 0.f);
                v1.w = fmaxf(p3.y + sB2[8*tx+7], 0.f);
                *(float4*)&sH2[(8*ty + i)*132 + 8*tx]     = v0;
                *(float4*)&sH2[(8*ty + i)*132 + 8*tx + 4] = v1;
            }
        }
        __syncthreads();
        // ---- layer 3: 128 -> 64 (no relu), f32x2, per-thread column max ----
        {
            ull acc[8][2];
            #pragma unroll
            for (int i = 0; i < 8; i++) { acc[i][0] = 0ULL; acc[i][1] = 0ULL; }
            for (int k = 0; k < 128; k++) {
                ull aa[8];
                #pragma unroll
                for (int i = 0; i < 8; i++) {
                    float a = sH2[(8*ty + i)*132 + k];
                    aa[i] = pack2(a, a);
                }
                ulonglong2 b = *(const ulonglong2*)&sW3[k*64 + 4*tx];
                #pragma unroll
                for (int i = 0; i < 8; i++) {
                    fma2(acc[i][0], aa[i], b.x);
                    fma2(acc[i][1], aa[i], b.y);
                }
            }
            #pragma unroll
            for (int jp = 0; jp < 2; jp++) {
                float2 m = unpack2(acc[0][jp]);
                #pragma unroll
                for (int i = 1; i < 8; i++) {
                    float2 q = unpack2(acc[i][jp]);
                    m.x = fmaxf(m.x, q.x); m.y = fmaxf(m.y, q.y);
                }
                rmax[2*jp]   = fmaxf(rmax[2*jp],   m.x);
                rmax[2*jp+1] = fmaxf(rmax[2*jp+1], m.y);
            }
        }
    }
    #pragma unroll
    for (int j = 0; j < 4; j++) sRed[ty*64 + 4*tx + j] = rmax[j];
    __syncthreads();
    if (tid < 64) {
        float mm = -3.4e38f;
        #pragma unroll
        for (int t = 0; t < 16; t++) mm = fmaxf(mm, sRed[t*64 + tid]);
        g_pnpart[item*128 + half*64 + tid] = mm;
    }
}

// combine the two per-item halves, add bias
__global__ void pnfinish_kernel(const float* b3) {
    int idx = blockIdx.x*blockDim.x + threadIdx.x;  // 512*64
    int item = idx >> 6, c = idx & 63;
    float v = fmaxf(g_pnpart[item*128 + c], g_pnpart[item*128 + 64 + c]);
    g_h[item*128 + c] = v + b3[c];
}

// ---------------- det motion MLP: 9 -> 32 relu -> 64 ----------------
__global__ void detmot_kernel(const float* boxes, const float* w1, const float* b1,
                              const float* w2, const float* b2) {
    int i = blockIdx.x*blockDim.x + threadIdx.x;
    if (i >= NDET) return;
    float x[9];
    #pragma unroll
    for (int c = 0; c < 9; c++) x[c] = boxes[i*9 + c];
    float h[32];
    #pragma unroll
    for (int r = 0; r < 32; r++) {
        float a = b1[r];
        #pragma unroll
        for (int c = 0; c < 9; c++) a += x[c]*w1[r*9 + c];
        h[r] = fmaxf(a, 0.f);
    }
    for (int o = 0; o < 64; o++) {
        float a = b2[o];
        #pragma unroll
        for (int r = 0; r < 32; r++) a += h[r]*w2[o*32 + r];
        g_h[i*128 + 64 + o] = a;
    }
}

// ---------------- 2-layer LSTM: 128 CTAs x 256 threads, row-per-thread, f32x2 ----------------
// smem layout (floats):
//   sWih0p 2048 | sWih0s 256 | sWhh0p 16384 | sWih1p 16384 | sWhh1p 16384
//   sB0 256 | sB1 256 | sH 128 | sHs0 1280 | sX 200 | sG 512  -> total 54088
#define LSTM_SMEM_FLOATS 54088

__global__ void lstm_kernel(const float* tb,
                            const float* wih0, const float* whh0,
                            const float* bih0, const float* bhh0,
                            const float* wih1, const float* whh1,
                            const float* bih1, const float* bhh1) {
    extern __shared__ float sm[];
    float* sWih0p = sm;            // [c/2][r][2]  (c 0..7)
    float* sWih0s = sm + 2048;     // [r] (c == 8)
    float* sWhh0p = sm + 2304;     // [k/2][r][2]
    float* sWih1p = sm + 18688;    // [k/2][r][2]
    float* sWhh1p = sm + 35072;    // [k/2][r][2]
    float* sB0    = sm + 51456;
    float* sB1    = sm + 51712;
    float* sH     = sm + 51968;    // [2][64]
    float* sHs0   = sm + 52096;    // [2][10][64]
    float* sX     = sm + 53376;    // [2][10][10] (stride 10 for alignment)
    float* sG     = sm + 53576;    // [2][256]

    int tid = threadIdx.x;         // 256
    int m0 = blockIdx.x*2;

    for (int i = tid; i < 2304; i += 256) {
        int r = i/9, c = i%9; float v = wih0[i];
        if (c < 8) sWih0p[((c>>1)*256 + r)*2 + (c&1)] = v; else sWih0s[r] = v;
    }
    for (int i = tid; i < 16384; i += 256) { int r = i>>6, k = i&63; sWhh0p[((k>>1)*256+r)*2+(k&1)] = whh0[i]; }
    for (int i = tid; i < 16384; i += 256) { int r = i>>6, k = i&63; sWih1p[((k>>1)*256+r)*2+(k&1)] = wih1[i]; }
    for (int i = tid; i < 16384; i += 256) { int r = i>>6, k = i&63; sWhh1p[((k>>1)*256+r)*2+(k&1)] = whh1[i]; }
    if (tid < 256) { sB0[tid] = bih0[tid]+bhh0[tid]; sB1[tid] = bih1[tid]+bhh1[tid]; }
    for (int i = tid; i < 180; i += 256) {
        int tr = i/90, rest = i%90, t = rest/9, c = rest%9;
        sX[tr*100 + t*10 + c] = tb[(size_t)(m0+tr)*TSTE*9 + t*9 + c];
    }
    if (tid < 128) sH[tid] = 0.f;
    __syncthreads();

    int r = tid;
    int utr = tid >> 6, uu = tid & 63;   // for update threads (tid<128)
    float cc = 0.f;

    // ---- layer 0 ----
    for (int t = 0; t < TSTE; t++) {
        ull a0 = 0ULL, a1 = 0ULL;
        const float* xb0 = sX + t*10;
        const float* xb1 = sX + 100 + t*10;
        #pragma unroll
        for (int c2 = 0; c2 < 4; c2++) {
            ull w = *(const ull*)&sWih0p[(c2*256 + r)*2];
            fma2(a0, *(const ull*)&xb0[2*c2], w);
            fma2(a1, *(const ull*)&xb1[2*c2], w);
        }
        float s0 = xb0[8]*sWih0s[r], s1 = xb1[8]*sWih0s[r];
        #pragma unroll 8
        for (int k2 = 0; k2 < 32; k2++) {
            ull w = *(const ull*)&sWhh0p[(k2*256 + r)*2];
            fma2(a0, *(const ull*)&sH[2*k2], w);
            fma2(a1, *(const ull*)&sH[64 + 2*k2], w);
        }
        float2 p0 = unpack2(a0), p1 = unpack2(a1);
        sG[r]     = p0.x + p0.y + s0 + sB0[r];
        sG[256+r] = p1.x + p1.y + s1 + sB0[r];
        __syncthreads();
        if (tid < 128) {
            float gi = sigmf(sG[utr*256 + uu]);
            float gf = sigmf(sG[utr*256 + 64 + uu]);
            float gg = tanhf_(sG[utr*256 + 128 + uu]);
            float go = sigmf(sG[utr*256 + 192 + uu]);
            cc = gf*cc + gi*gg;
            float hn = go*tanhf_(cc);
            sH[tid] = hn;
            sHs0[utr*640 + t*64 + uu] = hn;
        }
        __syncthreads();
    }
    // ---- layer 1 ----
    if (tid < 128) sH[tid] = 0.f;
    cc = 0.f;
    __syncthreads();
    float hlast = 0.f;
    for (int t = 0; t < TSTE; t++) {
        ull a0 = 0ULL, a1 = 0ULL;
        #pragma unroll 8
        for (int k2 = 0; k2 < 32; k2++) {
            ull w = *(const ull*)&sWih1p[(k2*256 + r)*2];
            fma2(a0, *(const ull*)&sHs0[t*64 + 2*k2], w);
            fma2(a1, *(const ull*)&sHs0[640 + t*64 + 2*k2], w);
        }
        #pragma unroll 8
        for (int k2 = 0; k2 < 32; k2++) {
            ull w = *(const ull*)&sWhh1p[(k2*256 + r)*2];
            fma2(a0, *(const ull*)&sH[2*k2], w);
            fma2(a1, *(const ull*)&sH[64 + 2*k2], w);
        }
        float2 p0 = unpack2(a0), p1 = unpack2(a1);
        sG[r]     = p0.x + p0.y + sB1[r];
        sG[256+r] = p1.x + p1.y + sB1[r];
        __syncthreads();
        if (tid < 128) {
            float gi = sigmf(sG[utr*256 + uu]);
            float gf = sigmf(sG[utr*256 + 64 + uu]);
            float gg = tanhf_(sG[utr*256 + 128 + uu]);
            float go = sigmf(sG[utr*256 + 192 + uu]);
            cc = gf*cc + gi*gg;
            hlast = go*tanhf_(cc);
            sH[tid] = hlast;
        }
        __syncthreads();
    }
    if (tid < 128) g_h[(NDET + m0 + utr)*128 + 64 + uu] = hlast;
}

// ---------------- EdgeConv part A: Th = h@Wt^T, Q = h@(Wp-Wt)^T + bt+bp (f32x2) ----------------
__global__ void thq_kernel(int l) {
    __shared__ float sh[128];
    int i = blockIdx.x, c = threadIdx.x;
    sh[c] = g_h[i*128 + c];
    __syncthreads();
    const float* wtd = g_wtd + l*32768;
    ull acc = 0ULL;
    #pragma unroll 8
    for (int k = 0; k < 128; k++) {
        float hv = sh[k];
        ull w = *(const ull*)&wtd[(k*128 + c)*2];
        fma2(acc, pack2(hv, hv), w);
    }
    float2 p = unpack2(acc);
    g_Th[i*128 + c] = p.x;
    g_Q[i*128 + c]  = p.y + g_bsum[l*128 + c];
}

// ---------------- EdgeConv part B: masked neighbor max + relu, 4 nodes per CTA ----------------
__global__ void edge_kernel() {
    __shared__ float sTh[64*128];
    __shared__ unsigned smask[64];
    int c = threadIdx.x;
    int i0 = blockIdx.x*4;
    if (c < 64) smask[c] = g_mask[i0*16 + c];
    float m0 = -3.4e38f, m1 = m0, m2 = m0, m3 = m0;
    for (int jc = 0; jc < 8; jc++) {
        __syncthreads();
        for (int t = c; t < 8192; t += 128) sTh[t] = g_Th[jc*8192 + t];
        __syncthreads();
        #pragma unroll
        for (int hf = 0; hf < 2; hf++) {
            int wi = jc*2 + hf;
            unsigned w0 = smask[0*16 + wi], w1 = smask[1*16 + wi];
            unsigned w2 = smask[2*16 + wi], w3 = smask[3*16 + wi];
            #pragma unroll 8
            for (int jj = 0; jj < 32; jj++) {
                float v = sTh[(hf*32 + jj)*128 + c];
                unsigned bit = 1u << jj;
                if (w0 & bit) m0 = fmaxf(m0, v);
                if (w1 & bit) m1 = fmaxf(m1, v);
                if (w2 & bit) m2 = fmaxf(m2, v);
                if (w3 & bit) m3 = fmaxf(m3, v);
            }
        }
    }
    g_h[(i0+0)*128 + c] = fmaxf(m0 + g_Q[(i0+0)*128 + c], 0.f);
    g_h[(i0+1)*128 + c] = fmaxf(m1 + g_Q[(i0+1)*128 + c], 0.f);
    g_h[(i0+2)*128 + c] = fmaxf(m2 + g_Q[(i0+2)*128 + c], 0.f);
    g_h[(i0+3)*128 + c] = fmaxf(m3 + g_Q[(i0+3)*128 + c], 0.f);
}

// ---------------- affinity: P = h[:256] @ er_w1^T (f32x2) ----------------
__global__ void pproj_kernel() {
    __shared__ float sh[128];
    int i = blockIdx.x, c = threadIdx.x;  // 64 threads
    sh[c]      = g_h[i*128 + c];
    sh[64 + c] = g_h[i*128 + 64 + c];
    __syncthreads();
    ull acc = 0ULL;
    #pragma unroll 8
    for (int k2 = 0; k2 < 64; k2++) {
        ull hv = *(const ull*)&sh[2*k2];
        ull w = *(const ull*)&g_w1p[(k2*64 + c)*2];
        fma2(acc, hv, w);
    }
    float2 p = unpack2(acc);
    g_P[i*64 + c] = p.x + p.y;
}

// ---------------- affinity: pairwise relu + w2 dot + sigmoid ----------------
__global__ void pair_kernel(const float* b1, const float* w2, const float* b2, float* out) {
    __shared__ float sPi[16*65], sPj[16*65], sw2[64], sb1v[64];
    int tid = threadIdx.x;
    int ib = (blockIdx.x >> 4)*16, jb = (blockIdx.x & 15)*16;
    for (int t = tid; t < 1024; t += 256) {
        int r = t >> 6, c = t & 63;
        sPi[r*65 + c] = g_P[(ib + r)*64 + c];
        sPj[r*65 + c] = g_P[(jb + r)*64 + c];
    }
    if (tid < 64) { sw2[tid] = w2[tid]; sb1v[tid] = b1[tid]; }
    __syncthreads();
    int ti = tid >> 4, tj = tid & 15;
    float s = b2[0];
    #pragma unroll 8
    for (int c = 0; c < 64; c++)
        s += sw2[c]*fmaxf(sPj[tj*65 + c] - sPi[ti*65 + c] + sb1v[c], 0.f);
    out[(ib + ti)*256 + jb + tj] = sigmf(s);
}

// ---------------- launch ----------------
extern "C" void kernel_launch(void* const* d_in, const int* in_sizes, int n_in,
                              void* d_out, int out_size) {
    const float* det_pts   = (const float*)d_in[0];
    const float* det_boxes = (const float*)d_in[1];
    const float* trk_pts   = (const float*)d_in[2];
    const float* trk_boxes = (const float*)d_in[3];
    const int*   adj       = (const int*)  d_in[4];
    const float* pn_w1 = (const float*)d_in[5];
    const float* pn_b1 = (const float*)d_in[6];
    const float* pn_w2 = (const float*)d_in[7];
    const float* pn_b2 = (const float*)d_in[8];
    const float* pn_w3 = (const float*)d_in[9];
    const float* pn_b3 = (const float*)d_in[10];
    const float* dm_w1 = (const float*)d_in[11];
    const float* dm_b1 = (const float*)d_in[12];
    const float* dm_w2 = (const float*)d_in[13];
    const float* dm_b2 = (const float*)d_in[14];
    const float* l0_wih = (const float*)d_in[15];
    const float* l0_whh = (const float*)d_in[16];
    const float* l0_bih = (const float*)d_in[17];
    const float* l0_bhh = (const float*)d_in[18];
    const float* l1_wih = (const float*)d_in[19];
    const float* l1_whh = (const float*)d_in[20];
    const float* l1_bih = (const float*)d_in[21];
    const float* l1_bhh = (const float*)d_in[22];
    const float* gc_wt = (const float*)d_in[23];
    const float* gc_bt = (const float*)d_in[24];
    const float* gc_wp = (const float*)d_in[25];
    const float* gc_bp = (const float*)d_in[26];
    const float* er_w1 = (const float*)d_in[27];
    const float* er_b1 = (const float*)d_in[28];
    const float* er_w2 = (const float*)d_in[29];
    const float* er_b2 = (const float*)d_in[30];
    float* out = (float*)d_out;

    cudaFuncSetAttribute(pointnet_kernel, cudaFuncAttributeMaxDynamicSharedMemorySize,
                         PN_SMEM_FLOATS*4);
    cudaFuncSetAttribute(lstm_kernel, cudaFuncAttributeMaxDynamicSharedMemorySize,
                         LSTM_SMEM_FLOATS*4);

    prep_kernel<<<256, 256>>>(gc_wt, gc_bt, gc_wp, gc_bp, er_w1, adj);
    pointnet_kernel<<<1024, 256, PN_SMEM_FLOATS*4>>>(det_pts, trk_pts,
        pn_w1, pn_b1, pn_w2, pn_b2, pn_w3, pn_b3);
    detmot_kernel<<<2, 128>>>(det_boxes, dm_w1, dm_b1, dm_w2, dm_b2);
    lstm_kernel<<<128, 256, LSTM_SMEM_FLOATS*4>>>(trk_boxes,
        l0_wih, l0_whh, l0_bih, l0_bhh, l1_wih, l1_whh, l1_bih, l1_bhh);
    pnfinish_kernel<<<128, 256>>>(pn_b3);

    for (int l = 0; l < 4; l++) {
        thq_kernel<<<512, 128>>>(l);
        edge_kernel<<<128, 128>>>();
        if (l == 0) {
            pproj_kernel<<<256, 64>>>();
            pair_kernel<<<256, 256>>>(er_b1, er_w2, er_b2, out);
        }
    }
    pproj_kernel<<<256, 64>>>();
    pair_kernel<<<256, 256>>>(er_b1, er_w2, er_b2, out + 65536);
}

// round 4
// speedup vs baseline: 1.2582x; 1.2321x over previous
#include <cuda_runtime.h>
#include <cuda_bf16.h>
#include <mma.h>
#include <math.h>
#include <stdint.h>

using namespace nvcuda;

#define NDET 256
#define MTRK 256
#define VN   512
#define PPTS 512
#define TSTE 10

typedef unsigned long long ull;

__device__ __forceinline__ void fma2(ull &d, ull a, ull b) {
    asm("fma.rn.f32x2 %0, %1, %2, %0;" : "+l"(d) : "l"(a), "l"(b));
}
__device__ __forceinline__ ull pack2(float x, float y) {
    ull r; asm("mov.b64 %0, {%1, %2};" : "=l"(r) : "f"(x), "f"(y)); return r;
}
__device__ __forceinline__ float2 unpack2(ull v) {
    float2 r; asm("mov.b64 {%0, %1}, %2;" : "=f"(r.x), "=f"(r.y) : "l"(v)); return r;
}
__device__ __forceinline__ float ex2a(float x) { float y; asm("ex2.approx.f32 %0, %1;" : "=f"(y) : "f"(x)); return y; }
__device__ __forceinline__ float rcpa(float x) { float y; asm("rcp.approx.f32 %0, %1;" : "=f"(y) : "f"(x)); return y; }
__device__ __forceinline__ float sigmf(float x) { return rcpa(1.f + ex2a(-1.4426950408889634f * x)); }
__device__ __forceinline__ float tanhf_(float x) { return 2.f * sigmf(2.f * x) - 1.f; }

// ---------------- device scratch ----------------
__device__ float g_h[VN*128];
__device__ float g_Th[VN*128];
__device__ float g_Q[VN*128];
__device__ float g_P[NDET*64];
__device__ float g_wtd[4*128*128*2];
__device__ float g_bsum[4*128];
__device__ float g_w1p[64*128];
__device__ unsigned g_mask[VN*16];
__device__ float g_pnpart[VN*128];

// ---------------- prep ----------------
__global__ void prep_kernel(const float* gc_wt, const float* gc_bt,
                            const float* gc_wp, const float* gc_bp,
                            const float* er_w1, const int* adj) {
    int idx = blockIdx.x*blockDim.x + threadIdx.x;
    int stride = gridDim.x*blockDim.x;
    for (int i = idx; i < 4*128*128; i += stride) {
        int l = i >> 14, r = (i >> 7) & 127, k = i & 127;
        float wt = gc_wt[i], wp = gc_wp[i];
        g_wtd[l*32768 + (k*128 + r)*2 + 0] = wt;
        g_wtd[l*32768 + (k*128 + r)*2 + 1] = wp - wt;
    }
    for (int i = idx; i < 4*128; i += stride) g_bsum[i] = gc_bt[i] + gc_bp[i];
    for (int i = idx; i < 64*128; i += stride) {
        int r = i >> 7, k = i & 127;
        g_w1p[((k >> 1)*64 + r)*2 + (k & 1)] = er_w1[i];
    }
    for (int w = idx; w < VN*16; w += stride) {
        int i = w >> 4, wo = w & 15;
        unsigned bits = 0;
        #pragma unroll
        for (int b = 0; b < 32; b++) {
            int j = wo*32 + b;
            if (adj[j*VN + i] != 0 || j == i) bits |= (1u << b);
        }
        g_mask[w] = bits;
    }
}

// ---------------- PointNet via wmma bf16 (split-bf16 emulated fp32) ----------------
// smem byte offsets (all 16B-aligned)
#define PN_A1H   0         // [128][72] bf16
#define PN_A1L   18432
#define PN_W2H   36864     // [128][72] bf16 (j rows, k cols)
#define PN_W2L   55296
#define PN_A2H   73728     // [128][136] bf16
#define PN_A2L   108544
#define PN_W3H   143360    // [64][136] bf16 (o rows, k cols)
#define PN_W3L   160768
#define PN_STG   178176    // [128][68] fp32
#define PN_AUX   212992
#define PN_SMEM  216576

#define LDA1 72
#define LDW2 72
#define LDA2 136
#define LDW3 136
#define LDS_ 68

__device__ __forceinline__ void bfsplit(float v, __nv_bfloat16 &hb, __nv_bfloat16 &lb) {
    hb = __float2bfloat16(v);
    lb = __float2bfloat16(v - __bfloat162float(hb));
}

__global__ __launch_bounds__(256) void pointnet_wmma_kernel(
    const float* det_pts, const float* trk_pts,
    const float* w1, const float* b1,
    const float* w2, const float* b2,
    const float* w3) {
    extern __shared__ char smc[];
    __nv_bfloat16* A1H = (__nv_bfloat16*)(smc + PN_A1H);
    __nv_bfloat16* A1L = (__nv_bfloat16*)(smc + PN_A1L);
    __nv_bfloat16* W2H = (__nv_bfloat16*)(smc + PN_W2H);
    __nv_bfloat16* W2L = (__nv_bfloat16*)(smc + PN_W2L);
    __nv_bfloat16* A2H = (__nv_bfloat16*)(smc + PN_A2H);
    __nv_bfloat16* A2L = (__nv_bfloat16*)(smc + PN_A2L);
    __nv_bfloat16* W3H = (__nv_bfloat16*)(smc + PN_W3H);
    __nv_bfloat16* W3L = (__nv_bfloat16*)(smc + PN_W3L);
    float* STG = (float*)(smc + PN_STG);
    float* sW1 = (float*)(smc + PN_AUX);          // 320
    float* sB1 = sW1 + 320;                       // 64
    float* sB2 = sB1 + 64;                        // 128
    float* sRED = sB2 + 128;                      // 256

    int tid = threadIdx.x;          // 256
    int warp = tid >> 5;
    int item = blockIdx.x >> 1, halfI = blockIdx.x & 1;
    const float* pts = (item < NDET) ? det_pts + (size_t)item*PPTS*5
                                     : trk_pts + (size_t)(item-NDET)*PPTS*5;

    for (int i = tid; i < 320; i += 256) { int o = i/5, c = i%5; sW1[c*64+o] = w1[i]; }
    if (tid < 64)  sB1[tid] = b1[tid];
    if (tid < 128) sB2[tid] = b2[tid];
    for (int i = tid; i < 8192; i += 256) {
        int j = i >> 6, k = i & 63;
        __nv_bfloat16 hb, lb; bfsplit(w2[i], hb, lb);
        W2H[j*LDW2 + k] = hb; W2L[j*LDW2 + k] = lb;
    }
    for (int i = tid; i < 8192; i += 256) {
        int o = i >> 7, k = i & 127;
        __nv_bfloat16 hb, lb; bfsplit(w3[i], hb, lb);
        W3H[o*LDW3 + k] = hb; W3L[o*LDW3 + k] = lb;
    }
    __syncthreads();

    int band = warp*16;
    int mc = tid & 63, mq = tid >> 6;   // max-reduce ownership
    float rmaxv = -3.4e38f;

    for (int tile = 0; tile < 2; tile++) {
        int tI = halfI*2 + tile;
        // ---- layer 1 (scalar): 5->64 relu, split into A1 ----
        {
            int p = tid & 127, hh = tid >> 7;
            const float* xp = pts + (size_t)(tI*128 + p)*5;
            float x0 = xp[0], x1 = xp[1], x2 = xp[2], x3 = xp[3], x4 = xp[4];
            int ob = hh*32;
            #pragma unroll
            for (int o = 0; o < 32; o++) {
                int oo = ob + o;
                float v = sB1[oo] + x0*sW1[oo] + x1*sW1[64+oo] + x2*sW1[128+oo]
                                  + x3*sW1[192+oo] + x4*sW1[256+oo];
                v = fmaxf(v, 0.f);
                __nv_bfloat16 hb, lb; bfsplit(v, hb, lb);
                A1H[p*LDA1 + oo] = hb; A1L[p*LDA1 + oo] = lb;
            }
        }
        __syncthreads();
        // ---- layer 2: D1[128x128] = A1[128x64] @ W2^T ----
        {
            wmma::fragment<wmma::matrix_a, 16, 16, 16, __nv_bfloat16, wmma::row_major> Ah[4], Al[4];
            #pragma unroll
            for (int k = 0; k < 4; k++) {
                wmma::load_matrix_sync(Ah[k], &A1H[band*LDA1 + k*16], LDA1);
                wmma::load_matrix_sync(Al[k], &A1L[band*LDA1 + k*16], LDA1);
            }
            for (int h = 0; h < 2; h++) {
                #pragma unroll
                for (int nt = 0; nt < 4; nt++) {
                    wmma::fragment<wmma::accumulator, 16, 16, 16, float> C;
                    wmma::fill_fragment(C, 0.f);
                    #pragma unroll
                    for (int k = 0; k < 4; k++) {
                        wmma::fragment<wmma::matrix_b, 16, 16, 16, __nv_bfloat16, wmma::col_major> Bh, Bl;
                        wmma::load_matrix_sync(Bh, &W2H[(h*64 + nt*16)*LDW2 + k*16], LDW2);
                        wmma::load_matrix_sync(Bl, &W2L[(h*64 + nt*16)*LDW2 + k*16], LDW2);
                        wmma::mma_sync(C, Ah[k], Bh, C);
                        wmma::mma_sync(C, Al[k], Bh, C);
                        wmma::mma_sync(C, Ah[k], Bl, C);
                    }
                    wmma::store_matrix_sync(&STG[band*LDS_ + nt*16], C, LDS_, wmma::mem_row_major);
                }
                __syncthreads();
                // convert half h: bias+relu+split into A2
                for (int i = tid; i < 8192; i += 256) {
                    int p = i >> 6, c = i & 63;
                    float v = fmaxf(STG[p*LDS_ + c] + sB2[h*64 + c], 0.f);
                    __nv_bfloat16 hb, lb; bfsplit(v, hb, lb);
                    A2H[p*LDA2 + h*64 + c] = hb; A2L[p*LDA2 + h*64 + c] = lb;
                }
                __syncthreads();
            }
        }
        // ---- layer 3: D2[128x64] = A2[128x128] @ W3^T ----
        {
            wmma::fragment<wmma::matrix_a, 16, 16, 16, __nv_bfloat16, wmma::row_major> Ah[8], Al[8];
            #pragma unroll
            for (int k = 0; k < 8; k++) {
                wmma::load_matrix_sync(Ah[k], &A2H[band*LDA2 + k*16], LDA2);
                wmma::load_matrix_sync(Al[k], &A2L[band*LDA2 + k*16], LDA2);
            }
            #pragma unroll
            for (int nt = 0; nt < 4; nt++) {
                wmma::fragment<wmma::accumulator, 16, 16, 16, float> C;
                wmma::fill_fragment(C, 0.f);
                #pragma unroll
                for (int k = 0; k < 8; k++) {
                    wmma::fragment<wmma::matrix_b, 16, 16, 16, __nv_bfloat16, wmma::col_major> Bh, Bl;
                    wmma::load_matrix_sync(Bh, &W3H[nt*16*LDW3 + k*16], LDW3);
                    wmma::load_matrix_sync(Bl, &W3L[nt*16*LDW3 + k*16], LDW3);
                    wmma::mma_sync(C, Ah[k], Bh, C);
                    wmma::mma_sync(C, Al[k], Bh, C);
                    wmma::mma_sync(C, Ah[k], Bl, C);
                }
                wmma::store_matrix_sync(&STG[band*LDS_ + nt*16], C, LDS_, wmma::mem_row_major);
            }
        }
        __syncthreads();
        // column max over this tile's 128 points (thread owns col mc, rows mq*32..)
        #pragma unroll 8
        for (int r = 0; r < 32; r++)
            rmaxv = fmaxf(rmaxv, STG[(mq*32 + r)*LDS_ + mc]);
        __syncthreads();
    }
    sRED[mq*64 + mc] = rmaxv;
    __syncthreads();
    if (tid < 64) {
        float m = fmaxf(fmaxf(sRED[tid], sRED[64+tid]), fmaxf(sRED[128+tid], sRED[192+tid]));
        g_pnpart[item*128 + halfI*64 + tid] = m;
    }
}

// combine halves + bias
__global__ void pnfinish_kernel(const float* b3) {
    int idx = blockIdx.x*blockDim.x + threadIdx.x;
    int item = idx >> 6, c = idx & 63;
    float v = fmaxf(g_pnpart[item*128 + c], g_pnpart[item*128 + 64 + c]);
    g_h[item*128 + c] = v + b3[c];
}

// ---------------- det motion MLP ----------------
__global__ void detmot_kernel(const float* boxes, const float* w1, const float* b1,
                              const float* w2, const float* b2) {
    int i = blockIdx.x*blockDim.x + threadIdx.x;
    if (i >= NDET) return;
    float x[9];
    #pragma unroll
    for (int c = 0; c < 9; c++) x[c] = boxes[i*9 + c];
    float h[32];
    #pragma unroll
    for (int r = 0; r < 32; r++) {
        float a = b1[r];
        #pragma unroll
        for (int c = 0; c < 9; c++) a += x[c]*w1[r*9 + c];
        h[r] = fmaxf(a, 0.f);
    }
    for (int o = 0; o < 64; o++) {
        float a = b2[o];
        #pragma unroll
        for (int r = 0; r < 32; r++) a += h[r]*w2[o*32 + r];
        g_h[i*128 + 64 + o] = a;
    }
}

// ---------------- 2-layer LSTM ----------------
#define LSTM_SMEM_FLOATS 54088

__global__ void lstm_kernel(const float* tb,
                            const float* wih0, const float* whh0,
                            const float* bih0, const float* bhh0,
                            const float* wih1, const float* whh1,
                            const float* bih1, const float* bhh1) {
    extern __shared__ float sm[];
    float* sWih0p = sm;
    float* sWih0s = sm + 2048;
    float* sWhh0p = sm + 2304;
    float* sWih1p = sm + 18688;
    float* sWhh1p = sm + 35072;
    float* sB0    = sm + 51456;
    float* sB1    = sm + 51712;
    float* sH     = sm + 51968;
    float* sHs0   = sm + 52096;
    float* sX     = sm + 53376;
    float* sG     = sm + 53576;

    int tid = threadIdx.x;
    int m0 = blockIdx.x*2;

    for (int i = tid; i < 2304; i += 256) {
        int r = i/9, c = i%9; float v = wih0[i];
        if (c < 8) sWih0p[((c>>1)*256 + r)*2 + (c&1)] = v; else sWih0s[r] = v;
    }
    for (int i = tid; i < 16384; i += 256) { int r = i>>6, k = i&63; sWhh0p[((k>>1)*256+r)*2+(k&1)] = whh0[i]; }
    for (int i = tid; i < 16384; i += 256) { int r = i>>6, k = i&63; sWih1p[((k>>1)*256+r)*2+(k&1)] = wih1[i]; }
    for (int i = tid; i < 16384; i += 256) { int r = i>>6, k = i&63; sWhh1p[((k>>1)*256+r)*2+(k&1)] = whh1[i]; }
    if (tid < 256) { sB0[tid] = bih0[tid]+bhh0[tid]; sB1[tid] = bih1[tid]+bhh1[tid]; }
    for (int i = tid; i < 180; i += 256) {
        int tr = i/90, rest = i%90, t = rest/9, c = rest%9;
        sX[tr*100 + t*10 + c] = tb[(size_t)(m0+tr)*TSTE*9 + t*9 + c];
    }
    if (tid < 128) sH[tid] = 0.f;
    __syncthreads();

    int r = tid;
    int utr = tid >> 6, uu = tid & 63;
    float cc = 0.f;

    for (int t = 0; t < TSTE; t++) {
        ull a0 = 0ULL, a1 = 0ULL;
        const float* xb0 = sX + t*10;
        const float* xb1 = sX + 100 + t*10;
        #pragma unroll
        for (int c2 = 0; c2 < 4; c2++) {
            ull w = *(const ull*)&sWih0p[(c2*256 + r)*2];
            fma2(a0, *(const ull*)&xb0[2*c2], w);
            fma2(a1, *(const ull*)&xb1[2*c2], w);
        }
        float s0 = xb0[8]*sWih0s[r], s1 = xb1[8]*sWih0s[r];
        #pragma unroll 8
        for (int k2 = 0; k2 < 32; k2++) {
            ull w = *(const ull*)&sWhh0p[(k2*256 + r)*2];
            fma2(a0, *(const ull*)&sH[2*k2], w);
            fma2(a1, *(const ull*)&sH[64 + 2*k2], w);
        }
        float2 p0 = unpack2(a0), p1 = unpack2(a1);
        sG[r]     = p0.x + p0.y + s0 + sB0[r];
        sG[256+r] = p1.x + p1.y + s1 + sB0[r];
        __syncthreads();
        if (tid < 128) {
            float gi = sigmf(sG[utr*256 + uu]);
            float gf = sigmf(sG[utr*256 + 64 + uu]);
            float gg = tanhf_(sG[utr*256 + 128 + uu]);
            float go = sigmf(sG[utr*256 + 192 + uu]);
            cc = gf*cc + gi*gg;
            float hn = go*tanhf_(cc);
            sH[tid] = hn;
            sHs0[utr*640 + t*64 + uu] = hn;
        }
        __syncthreads();
    }
    if (tid < 128) sH[tid] = 0.f;
    cc = 0.f;
    __syncthreads();
    float hlast = 0.f;
    for (int t = 0; t < TSTE; t++) {
        ull a0 = 0ULL, a1 = 0ULL;
        #pragma unroll 8
        for (int k2 = 0; k2 < 32; k2++) {
            ull w = *(const ull*)&sWih1p[(k2*256 + r)*2];
            fma2(a0, *(const ull*)&sHs0[t*64 + 2*k2], w);
            fma2(a1, *(const ull*)&sHs0[640 + t*64 + 2*k2], w);
        }
        #pragma unroll 8
        for (int k2 = 0; k2 < 32; k2++) {
            ull w = *(const ull*)&sWhh1p[(k2*256 + r)*2];
            fma2(a0, *(const ull*)&sH[2*k2], w);
            fma2(a1, *(const ull*)&sH[64 + 2*k2], w);
        }
        float2 p0 = unpack2(a0), p1 = unpack2(a1);
        sG[r]     = p0.x + p0.y + sB1[r];
        sG[256+r] = p1.x + p1.y + sB1[r];
        __syncthreads();
        if (tid < 128) {
            float gi = sigmf(sG[utr*256 + uu]);
            float gf = sigmf(sG[utr*256 + 64 + uu]);
            float gg = tanhf_(sG[utr*256 + 128 + uu]);
            float go = sigmf(sG[utr*256 + 192 + uu]);
            cc = gf*cc + gi*gg;
            hlast = go*tanhf_(cc);
            sH[tid] = hlast;
        }
        __syncthreads();
    }
    if (tid < 128) g_h[(NDET + m0 + utr)*128 + 64 + uu] = hlast;
}

// ---------------- EdgeConv A ----------------
__global__ void thq_kernel(int l) {
    __shared__ float sh[128];
    int i = blockIdx.x, c = threadIdx.x;
    sh[c] = g_h[i*128 + c];
    __syncthreads();
    const float* wtd = g_wtd + l*32768;
    ull acc = 0ULL;
    #pragma unroll 8
    for (int k = 0; k < 128; k++) {
        float hv = sh[k];
        ull w = *(const ull*)&wtd[(k*128 + c)*2];
        fma2(acc, pack2(hv, hv), w);
    }
    float2 p = unpack2(acc);
    g_Th[i*128 + c] = p.x;
    g_Q[i*128 + c]  = p.y + g_bsum[l*128 + c];
}

// ---------------- EdgeConv B ----------------
__global__ void edge_kernel() {
    __shared__ float sTh[64*128];
    __shared__ unsigned smask[64];
    int c = threadIdx.x;
    int i0 = blockIdx.x*4;
    if (c < 64) smask[c] = g_mask[i0*16 + c];
    float m0 = -3.4e38f, m1 = m0, m2 = m0, m3 = m0;
    for (int jc = 0; jc < 8; jc++) {
        __syncthreads();
        for (int t = c; t < 8192; t += 128) sTh[t] = g_Th[jc*8192 + t];
        __syncthreads();
        #pragma unroll
        for (int hf = 0; hf < 2; hf++) {
            int wi = jc*2 + hf;
            unsigned w0 = smask[0*16 + wi], w1 = smask[1*16 + wi];
            unsigned w2 = smask[2*16 + wi], w3 = smask[3*16 + wi];
            #pragma unroll 8
            for (int jj = 0; jj < 32; jj++) {
                float v = sTh[(hf*32 + jj)*128 + c];
                unsigned bit = 1u << jj;
                if (w0 & bit) m0 = fmaxf(m0, v);
                if (w1 & bit) m1 = fmaxf(m1, v);
                if (w2 & bit) m2 = fmaxf(m2, v);
                if (w3 & bit) m3 = fmaxf(m3, v);
            }
        }
    }
    g_h[(i0+0)*128 + c] = fmaxf(m0 + g_Q[(i0+0)*128 + c], 0.f);
    g_h[(i0+1)*128 + c] = fmaxf(m1 + g_Q[(i0+1)*128 + c], 0.f);
    g_h[(i0+2)*128 + c] = fmaxf(m2 + g_Q[(i0+2)*128 + c], 0.f);
    g_h[(i0+3)*128 + c] = fmaxf(m3 + g_Q[(i0+3)*128 + c], 0.f);
}

// ---------------- affinity projection ----------------
__global__ void pproj_kernel() {
    __shared__ float sh[128];
    int i = blockIdx.x, c = threadIdx.x;
    sh[c]      = g_h[i*128 + c];
    sh[64 + c] = g_h[i*128 + 64 + c];
    __syncthreads();
    ull acc = 0ULL;
    #pragma unroll 8
    for (int k2 = 0; k2 < 64; k2++) {
        ull hv = *(const ull*)&sh[2*k2];
        ull w = *(const ull*)&g_w1p[(k2*64 + c)*2];
        fma2(acc, hv, w);
    }
    float2 p = unpack2(acc);
    g_P[i*64 + c] = p.x + p.y;
}

// ---------------- pairwise head ----------------
__global__ void pair_kernel(const float* b1, const float* w2, const float* b2, float* out) {
    __shared__ float sPi[16*65], sPj[16*65], sw2[64], sb1v[64];
    int tid = threadIdx.x;
    int ib = (blockIdx.x >> 4)*16, jb = (blockIdx.x & 15)*16;
    for (int t = tid; t < 1024; t += 256) {
        int r = t >> 6, c = t & 63;
        sPi[r*65 + c] = g_P[(ib + r)*64 + c];
        sPj[r*65 + c] = g_P[(jb + r)*64 + c];
    }
    if (tid < 64) { sw2[tid] = w2[tid]; sb1v[tid] = b1[tid]; }
    __syncthreads();
    int ti = tid >> 4, tj = tid & 15;
    float s = b2[0];
    #pragma unroll 8
    for (int c = 0; c < 64; c++)
        s += sw2[c]*fmaxf(sPj[tj*65 + c] - sPi[ti*65 + c] + sb1v[c], 0.f);
    out[(ib + ti)*256 + jb + tj] = sigmf(s);
}

// ---------------- launch ----------------
extern "C" void kernel_launch(void* const* d_in, const int* in_sizes, int n_in,
                              void* d_out, int out_size) {
    const float* det_pts   = (const float*)d_in[0];
    const float* det_boxes = (const float*)d_in[1];
    const float* trk_pts   = (const float*)d_in[2];
    const float* trk_boxes = (const float*)d_in[3];
    const int*   adj       = (const int*)  d_in[4];
    const float* pn_w1 = (const float*)d_in[5];
    const float* pn_b1 = (const float*)d_in[6];
    const float* pn_w2 = (const float*)d_in[7];
    const float* pn_b2 = (const float*)d_in[8];
    const float* pn_w3 = (const float*)d_in[9];
    const float* pn_b3 = (const float*)d_in[10];
    const float* dm_w1 = (const float*)d_in[11];
    const float* dm_b1 = (const float*)d_in[12];
    const float* dm_w2 = (const float*)d_in[13];
    const float* dm_b2 = (const float*)d_in[14];
    const float* l0_wih = (const float*)d_in[15];
    const float* l0_whh = (const float*)d_in[16];
    const float* l0_bih = (const float*)d_in[17];
    const float* l0_bhh = (const float*)d_in[18];
    const float* l1_wih = (const float*)d_in[19];
    const float* l1_whh = (const float*)d_in[20];
    const float* l1_bih = (const float*)d_in[21];
    const float* l1_bhh = (const float*)d_in[22];
    const float* gc_wt = (const float*)d_in[23];
    const float* gc_bt = (const float*)d_in[24];
    const float* gc_wp = (const float*)d_in[25];
    const float* gc_bp = (const float*)d_in[26];
    const float* er_w1 = (const float*)d_in[27];
    const float* er_b1 = (const float*)d_in[28];
    const float* er_w2 = (const float*)d_in[29];
    const float* er_b2 = (const float*)d_in[30];
    float* out = (float*)d_out;

    cudaFuncSetAttribute(pointnet_wmma_kernel, cudaFuncAttributeMaxDynamicSharedMemorySize,
                         PN_SMEM);
    cudaFuncSetAttribute(lstm_kernel, cudaFuncAttributeMaxDynamicSharedMemorySize,
                         LSTM_SMEM_FLOATS*4);

    prep_kernel<<<256, 256>>>(gc_wt, gc_bt, gc_wp, gc_bp, er_w1, adj);
    pointnet_wmma_kernel<<<1024, 256, PN_SMEM>>>(det_pts, trk_pts,
        pn_w1, pn_b1, pn_w2, pn_b2, pn_w3);
    detmot_kernel<<<2, 128>>>(det_boxes, dm_w1, dm_b1, dm_w2, dm_b2);
    lstm_kernel<<<128, 256, LSTM_SMEM_FLOATS*4>>>(trk_boxes,
        l0_wih, l0_whh, l0_bih, l0_bhh, l1_wih, l1_whh, l1_bih, l1_bhh);
    pnfinish_kernel<<<128, 256>>>(pn_b3);

    for (int l = 0; l < 4; l++) {
        thq_kernel<<<512, 128>>>(l);
        edge_kernel<<<128, 128>>>();
        if (l == 0) {
            pproj_kernel<<<256, 64>>>();
            pair_kernel<<<256, 256>>>(er_b1, er_w2, er_b2, out);
        }
    }
    pproj_kernel<<<256, 64>>>();
    pair_kernel<<<256, 256>>>(er_b1, er_w2, er_b2, out + 65536);
}

// round 5
// speedup vs baseline: 1.5019x; 1.1936x over previous
#include <cuda_runtime.h>
#include <cuda_bf16.h>
#include <mma.h>
#include <math.h>
#include <stdint.h>

using namespace nvcuda;

#define NDET 256
#define MTRK 256
#define VN   512
#define PPTS 512
#define TSTE 10

typedef unsigned long long ull;

__device__ __forceinline__ void fma2(ull &d, ull a, ull b) {
    asm("fma.rn.f32x2 %0, %1, %2, %0;" : "+l"(d) : "l"(a), "l"(b));
}
__device__ __forceinline__ ull pack2(float x, float y) {
    ull r; asm("mov.b64 %0, {%1, %2};" : "=l"(r) : "f"(x), "f"(y)); return r;
}
__device__ __forceinline__ float2 unpack2(ull v) {
    float2 r; asm("mov.b64 {%0, %1}, %2;" : "=f"(r.x), "=f"(r.y) : "l"(v)); return r;
}
__device__ __forceinline__ float ex2a(float x) { float y; asm("ex2.approx.f32 %0, %1;" : "=f"(y) : "f"(x)); return y; }
__device__ __forceinline__ float rcpa(float x) { float y; asm("rcp.approx.f32 %0, %1;" : "=f"(y) : "f"(x)); return y; }
__device__ __forceinline__ float sigmf(float x) { return rcpa(1.f + ex2a(-1.4426950408889634f * x)); }
__device__ __forceinline__ float tanhf_(float x) { return 2.f * sigmf(2.f * x) - 1.f; }
// pack two fp32 -> bf16x2 (low half = first arg)
__device__ __forceinline__ uint32_t cvt2bf(float v_even, float v_odd) {
    uint32_t r; asm("cvt.rn.bf16x2.f32 %0, %1, %2;" : "=r"(r) : "f"(v_odd), "f"(v_even)); return r;
}

// ---------------- device scratch ----------------
__device__ float g_h[VN*128];
__device__ float g_Th[VN*128];
__device__ float g_Q[VN*128];
__device__ float g_P[NDET*64];
__device__ float g_wtd[4*128*128*2];
__device__ float g_bsum[4*128];
__device__ float g_w1p[64*128];
__device__ unsigned g_mask[VN*16];

// ---------------- prep ----------------
__global__ void prep_kernel(const float* gc_wt, const float* gc_bt,
                            const float* gc_wp, const float* gc_bp,
                            const float* er_w1, const int* adj) {
    int idx = blockIdx.x*blockDim.x + threadIdx.x;
    int stride = gridDim.x*blockDim.x;
    for (int i = idx; i < 4*128*128; i += stride) {
        int l = i >> 14, r = (i >> 7) & 127, k = i & 127;
        float wt = gc_wt[i], wp = gc_wp[i];
        g_wtd[l*32768 + (k*128 + r)*2 + 0] = wt;
        g_wtd[l*32768 + (k*128 + r)*2 + 1] = wp - wt;
    }
    for (int i = idx; i < 4*128; i += stride) g_bsum[i] = gc_bt[i] + gc_bp[i];
    for (int i = idx; i < 64*128; i += stride) {
        int r = i >> 7, k = i & 127;
        g_w1p[((k >> 1)*64 + r)*2 + (k & 1)] = er_w1[i];
    }
    for (int w = idx; w < VN*16; w += stride) {
        int i = w >> 4, wo = w & 15;
        unsigned bits = 0;
        #pragma unroll
        for (int b = 0; b < 32; b++) {
            int j = wo*32 + b;
            if (adj[j*VN + i] != 0 || j == i) bits |= (1u << b);
        }
        g_mask[w] = bits;
    }
}

// ---------------- PointNet smem layout (bytes) ----------------
#define PN_A1H   0
#define PN_A1L   18432
#define PN_W2H   36864
#define PN_W2L   55296
#define PN_A2H   73728
#define PN_A2L   108544
#define PN_W3H   143360
#define PN_W3L   160768
#define PN_SCR   178176   // 8 warps * 320 fp32
#define PN_AUX   188416

#define LDA1 72
#define LDW2 72
#define LDA2 136
#define LDW3 136
#define LDSC 20

#define MEGA_SMEM 216352  // max(pointnet 192512, lstm 54088*4)

__device__ __forceinline__ void bfsplit(float v, __nv_bfloat16 &hb, __nv_bfloat16 &lb) {
    hb = __float2bfloat16(v);
    lb = __float2bfloat16(v - __bfloat162float(hb));
}

// ---------------- pointnet body: barrier-free per-warp pipeline ----------------
__device__ void pointnet_body(char* smc, int item,
                              const float* det_pts, const float* trk_pts,
                              const float* w1, const float* b1,
                              const float* w2, const float* b2,
                              const float* w3, const float* b3) {
    __nv_bfloat16* A1H = (__nv_bfloat16*)(smc + PN_A1H);
    __nv_bfloat16* A1L = (__nv_bfloat16*)(smc + PN_A1L);
    __nv_bfloat16* W2H = (__nv_bfloat16*)(smc + PN_W2H);
    __nv_bfloat16* W2L = (__nv_bfloat16*)(smc + PN_W2L);
    __nv_bfloat16* A2H = (__nv_bfloat16*)(smc + PN_A2H);
    __nv_bfloat16* A2L = (__nv_bfloat16*)(smc + PN_A2L);
    __nv_bfloat16* W3H = (__nv_bfloat16*)(smc + PN_W3H);
    __nv_bfloat16* W3L = (__nv_bfloat16*)(smc + PN_W3L);
    float* SCR = (float*)(smc + PN_SCR);
    float* sW1 = (float*)(smc + PN_AUX);     // 320
    float* sB1 = sW1 + 320;                  // 64
    float* sB2 = sB1 + 64;                   // 128
    float* sRED = sB2 + 128;                 // 512

    int tid = threadIdx.x, warp = tid >> 5, lane = tid & 31;
    const float* pts = (item < NDET) ? det_pts + (size_t)item*PPTS*5
                                     : trk_pts + (size_t)(item-NDET)*PPTS*5;

    for (int i = tid; i < 320; i += 256) { int o = i/5, c = i%5; sW1[c*64+o] = w1[i]; }
    if (tid < 64)  sB1[tid] = b1[tid];
    if (tid < 128) sB2[tid] = b2[tid];
    for (int i = tid; i < 8192; i += 256) {
        int j = i >> 6, k = i & 63;
        __nv_bfloat16 hb, lb; bfsplit(w2[i], hb, lb);
        W2H[j*LDW2 + k] = hb; W2L[j*LDW2 + k] = lb;
    }
    for (int i = tid; i < 8192; i += 256) {
        int o = i >> 7, k = i & 127;
        __nv_bfloat16 hb, lb; bfsplit(w3[i], hb, lb);
        W3H[o*LDW3 + k] = hb; W3L[o*LDW3 + k] = lb;
    }
    __syncthreads();

    int band = warp*16;
    float* scr = SCR + warp*320;   // 16 x 20 fp32
    int rrow = lane & 15, rcolh = lane >> 4;
    float rmax[4] = {-3.4e38f, -3.4e38f, -3.4e38f, -3.4e38f};

    for (int t = 0; t < 4; t++) {
        // ---- L1: 5->64 relu, warp-private rows ----
        {
            const float* xp = pts + (size_t)(t*128 + band + rrow)*5;
            float x0 = xp[0], x1 = xp[1], x2 = xp[2], x3 = xp[3], x4 = xp[4];
            int ob = rcolh*32;
            int rowb = (band + rrow)*LDA1;
            #pragma unroll
            for (int o2 = 0; o2 < 16; o2++) {
                int o = ob + 2*o2;
                float v0 = sB1[o]   + x0*sW1[o]     + x1*sW1[64+o]     + x2*sW1[128+o]
                                    + x3*sW1[192+o] + x4*sW1[256+o];
                float v1 = sB1[o+1] + x0*sW1[o+1]   + x1*sW1[64+o+1]   + x2*sW1[128+o+1]
                                    + x3*sW1[192+o+1] + x4*sW1[256+o+1];
                v0 = fmaxf(v0, 0.f); v1 = fmaxf(v1, 0.f);
                uint32_t hp = cvt2bf(v0, v1);
                float h0 = __uint_as_float(hp << 16);
                float h1 = __uint_as_float(hp & 0xffff0000u);
                uint32_t lp = cvt2bf(v0 - h0, v1 - h1);
                *(uint32_t*)&A1H[rowb + o] = hp;
                *(uint32_t*)&A1L[rowb + o] = lp;
            }
        }
        __syncwarp();
        // ---- L2: rows band x 128 cols = A1 @ W2^T (split bf16, 3 passes) ----
        {
            wmma::fragment<wmma::matrix_a, 16, 16, 16, __nv_bfloat16, wmma::row_major> Ah[4], Al[4];
            #pragma unroll
            for (int k = 0; k < 4; k++) {
                wmma::load_matrix_sync(Ah[k], &A1H[band*LDA1 + k*16], LDA1);
                wmma::load_matrix_sync(Al[k], &A1L[band*LDA1 + k*16], LDA1);
            }
            int r2 = lane >> 1, cb = (lane & 1)*8;
            #pragma unroll
            for (int j = 0; j < 8; j++) {
                wmma::fragment<wmma::accumulator, 16, 16, 16, float> C;
                wmma::fill_fragment(C, 0.f);
                #pragma unroll
                for (int k = 0; k < 4; k++) {
                    wmma::fragment<wmma::matrix_b, 16, 16, 16, __nv_bfloat16, wmma::col_major> Bh, Bl;
                    wmma::load_matrix_sync(Bh, &W2H[j*16*LDW2 + k*16], LDW2);
                    wmma::load_matrix_sync(Bl, &W2L[j*16*LDW2 + k*16], LDW2);
                    wmma::mma_sync(C, Ah[k], Bh, C);
                    wmma::mma_sync(C, Al[k], Bh, C);
                    wmma::mma_sync(C, Ah[k], Bl, C);
                }
                wmma::store_matrix_sync(scr, C, LDSC, wmma::mem_row_major);
                __syncwarp();
                int rowb = (band + r2)*LDA2 + j*16 + cb;
                #pragma unroll
                for (int cc = 0; cc < 8; cc += 2) {
                    float v0 = fmaxf(scr[r2*LDSC + cb + cc]     + sB2[j*16 + cb + cc],     0.f);
                    float v1 = fmaxf(scr[r2*LDSC + cb + cc + 1] + sB2[j*16 + cb + cc + 1], 0.f);
                    uint32_t hp = cvt2bf(v0, v1);
                    float h0 = __uint_as_float(hp << 16);
                    float h1 = __uint_as_float(hp & 0xffff0000u);
                    uint32_t lp = cvt2bf(v0 - h0, v1 - h1);
                    *(uint32_t*)&A2H[rowb + cc] = hp;
                    *(uint32_t*)&A2L[rowb + cc] = lp;
                }
                __syncwarp();
            }
        }
        // ---- L3: rows band x 64 cols = A2 @ W3^T, column max ----
        {
            wmma::fragment<wmma::matrix_a, 16, 16, 16, __nv_bfloat16, wmma::row_major> Ah[8], Al[8];
            #pragma unroll
            for (int k = 0; k < 8; k++) {
                wmma::load_matrix_sync(Ah[k], &A2H[band*LDA2 + k*16], LDA2);
                wmma::load_matrix_sync(Al[k], &A2L[band*LDA2 + k*16], LDA2);
            }
            #pragma unroll
            for (int nt = 0; nt < 4; nt++) {
                wmma::fragment<wmma::accumulator, 16, 16, 16, float> C;
                wmma::fill_fragment(C, 0.f);
                #pragma unroll
                for (int k = 0; k < 8; k++) {
                    wmma::fragment<wmma::matrix_b, 16, 16, 16, __nv_bfloat16, wmma::col_major> Bh, Bl;
                    wmma::load_matrix_sync(Bh, &W3H[nt*16*LDW3 + k*16], LDW3);
                    wmma::load_matrix_sync(Bl, &W3L[nt*16*LDW3 + k*16], LDW3);
                    wmma::mma_sync(C, Ah[k], Bh, C);
                    wmma::mma_sync(C, Al[k], Bh, C);
                    wmma::mma_sync(C, Ah[k], Bl, C);
                }
                wmma::store_matrix_sync(scr, C, LDSC, wmma::mem_row_major);
                __syncwarp();
                if (lane < 16) {
                    float m = scr[lane];
                    #pragma unroll
                    for (int r = 1; r < 16; r++) m = fmaxf(m, scr[r*LDSC + lane]);
                    rmax[nt] = fmaxf(rmax[nt], m);
                }
                __syncwarp();
            }
        }
    }
    if (lane < 16) {
        #pragma unroll
        for (int nt = 0; nt < 4; nt++) sRED[warp*64 + nt*16 + lane] = rmax[nt];
    }
    __syncthreads();
    if (tid < 64) {
        float m = sRED[tid];
        #pragma unroll
        for (int w = 1; w < 8; w++) m = fmaxf(m, sRED[w*64 + tid]);
        g_h[item*128 + tid] = m + b3[tid];
    }
}

// ---------------- lstm body ----------------
__device__ void lstm_body(char* smc, int bid, const float* tb,
                          const float* wih0, const float* whh0,
                          const float* bih0, const float* bhh0,
                          const float* wih1, const float* whh1,
                          const float* bih1, const float* bhh1) {
    float* sm = (float*)smc;
    float* sWih0p = sm;
    float* sWih0s = sm + 2048;
    float* sWhh0p = sm + 2304;
    float* sWih1p = sm + 18688;
    float* sWhh1p = sm + 35072;
    float* sB0    = sm + 51456;
    float* sB1    = sm + 51712;
    float* sH     = sm + 51968;
    float* sHs0   = sm + 52096;
    float* sX     = sm + 53376;
    float* sG     = sm + 53576;

    int tid = threadIdx.x;
    int m0 = bid*2;

    for (int i = tid; i < 2304; i += 256) {
        int r = i/9, c = i%9; float v = wih0[i];
        if (c < 8) sWih0p[((c>>1)*256 + r)*2 + (c&1)] = v; else sWih0s[r] = v;
    }
    for (int i = tid; i < 16384; i += 256) { int r = i>>6, k = i&63; sWhh0p[((k>>1)*256+r)*2+(k&1)] = whh0[i]; }
    for (int i = tid; i < 16384; i += 256) { int r = i>>6, k = i&63; sWih1p[((k>>1)*256+r)*2+(k&1)] = wih1[i]; }
    for (int i = tid; i < 16384; i += 256) { int r = i>>6, k = i&63; sWhh1p[((k>>1)*256+r)*2+(k&1)] = whh1[i]; }
    if (tid < 256) { sB0[tid] = bih0[tid]+bhh0[tid]; sB1[tid] = bih1[tid]+bhh1[tid]; }
    for (int i = tid; i < 180; i += 256) {
        int tr = i/90, rest = i%90, t = rest/9, c = rest%9;
        sX[tr*100 + t*10 + c] = tb[(size_t)(m0+tr)*TSTE*9 + t*9 + c];
    }
    if (tid < 128) sH[tid] = 0.f;
    __syncthreads();

    int r = tid;
    int utr = tid >> 6, uu = tid & 63;
    float cc = 0.f;

    for (int t = 0; t < TSTE; t++) {
        ull a0 = 0ULL, a1 = 0ULL;
        const float* xb0 = sX + t*10;
        const float* xb1 = sX + 100 + t*10;
        #pragma unroll
        for (int c2 = 0; c2 < 4; c2++) {
            ull w = *(const ull*)&sWih0p[(c2*256 + r)*2];
            fma2(a0, *(const ull*)&xb0[2*c2], w);
            fma2(a1, *(const ull*)&xb1[2*c2], w);
        }
        float s0 = xb0[8]*sWih0s[r], s1 = xb1[8]*sWih0s[r];
        #pragma unroll 8
        for (int k2 = 0; k2 < 32; k2++) {
            ull w = *(const ull*)&sWhh0p[(k2*256 + r)*2];
            fma2(a0, *(const ull*)&sH[2*k2], w);
            fma2(a1, *(const ull*)&sH[64 + 2*k2], w);
        }
        float2 p0 = unpack2(a0), p1 = unpack2(a1);
        sG[r]     = p0.x + p0.y + s0 + sB0[r];
        sG[256+r] = p1.x + p1.y + s1 + sB0[r];
        __syncthreads();
        if (tid < 128) {
            float gi = sigmf(sG[utr*256 + uu]);
            float gf = sigmf(sG[utr*256 + 64 + uu]);
            float gg = tanhf_(sG[utr*256 + 128 + uu]);
            float go = sigmf(sG[utr*256 + 192 + uu]);
            cc = gf*cc + gi*gg;
            float hn = go*tanhf_(cc);
            sH[tid] = hn;
            sHs0[utr*640 + t*64 + uu] = hn;
        }
        __syncthreads();
    }
    if (tid < 128) sH[tid] = 0.f;
    cc = 0.f;
    __syncthreads();
    float hlast = 0.f;
    for (int t = 0; t < TSTE; t++) {
        ull a0 = 0ULL, a1 = 0ULL;
        #pragma unroll 8
        for (int k2 = 0; k2 < 32; k2++) {
            ull w = *(const ull*)&sWih1p[(k2*256 + r)*2];
            fma2(a0, *(const ull*)&sHs0[t*64 + 2*k2], w);
            fma2(a1, *(const ull*)&sHs0[640 + t*64 + 2*k2], w);
        }
        #pragma unroll 8
        for (int k2 = 0; k2 < 32; k2++) {
            ull w = *(const ull*)&sWhh1p[(k2*256 + r)*2];
            fma2(a0, *(const ull*)&sH[2*k2], w);
            fma2(a1, *(const ull*)&sH[64 + 2*k2], w);
        }
        float2 p0 = unpack2(a0), p1 = unpack2(a1);
        sG[r]     = p0.x + p0.y + sB1[r];
        sG[256+r] = p1.x + p1.y + sB1[r];
        __syncthreads();
        if (tid < 128) {
            float gi = sigmf(sG[utr*256 + uu]);
            float gf = sigmf(sG[utr*256 + 64 + uu]);
            float gg = tanhf_(sG[utr*256 + 128 + uu]);
            float go = sigmf(sG[utr*256 + 192 + uu]);
            cc = gf*cc + gi*gg;
            hlast = go*tanhf_(cc);
            sH[tid] = hlast;
        }
        __syncthreads();
    }
    if (tid < 128) g_h[(NDET + m0 + utr)*128 + 64 + uu] = hlast;
}

// ---------------- detmot body (256 threads, 1 CTA) ----------------
__device__ void detmot_body(const float* boxes, const float* w1, const float* b1,
                            const float* w2, const float* b2) {
    int i = threadIdx.x;
    float x[9];
    #pragma unroll
    for (int c = 0; c < 9; c++) x[c] = boxes[i*9 + c];
    float h[32];
    #pragma unroll
    for (int r = 0; r < 32; r++) {
        float a = b1[r];
        #pragma unroll
        for (int c = 0; c < 9; c++) a += x[c]*w1[r*9 + c];
        h[r] = fmaxf(a, 0.f);
    }
    for (int o = 0; o < 64; o++) {
        float a = b2[o];
        #pragma unroll
        for (int r = 0; r < 32; r++) a += h[r]*w2[o*32 + r];
        g_h[i*128 + 64 + o] = a;
    }
}

// ---------------- mega kernel ----------------
__global__ __launch_bounds__(256) void mega_kernel(
    const float* det_pts, const float* trk_pts,
    const float* pn_w1, const float* pn_b1, const float* pn_w2, const float* pn_b2,
    const float* pn_w3, const float* pn_b3,
    const float* det_boxes, const float* dm_w1, const float* dm_b1,
    const float* dm_w2, const float* dm_b2,
    const float* tb, const float* wih0, const float* whh0,
    const float* bih0, const float* bhh0,
    const float* wih1, const float* whh1,
    const float* bih1, const float* bhh1) {
    extern __shared__ char smc[];
    int bid = blockIdx.x;
    if (bid < 128) {
        lstm_body(smc, bid, tb, wih0, whh0, bih0, bhh0, wih1, whh1, bih1, bhh1);
    } else if (bid == 128) {
        detmot_body(det_boxes, dm_w1, dm_b1, dm_w2, dm_b2);
    } else {
        pointnet_body(smc, bid - 129, det_pts, trk_pts,
                      pn_w1, pn_b1, pn_w2, pn_b2, pn_w3, pn_b3);
    }
}

// ---------------- EdgeConv A ----------------
__global__ void thq_kernel(int l) {
    __shared__ float sh[128];
    int i = blockIdx.x, c = threadIdx.x;
    sh[c] = g_h[i*128 + c];
    __syncthreads();
    const float* wtd = g_wtd + l*32768;
    ull acc = 0ULL;
    #pragma unroll 8
    for (int k = 0; k < 128; k++) {
        float hv = sh[k];
        ull w = *(const ull*)&wtd[(k*128 + c)*2];
        fma2(acc, pack2(hv, hv), w);
    }
    float2 p = unpack2(acc);
    g_Th[i*128 + c] = p.x;
    g_Q[i*128 + c]  = p.y + g_bsum[l*128 + c];
}

// ---------------- EdgeConv B ----------------
__global__ void edge_kernel() {
    __shared__ float sTh[64*128];
    __shared__ unsigned smask[64];
    int c = threadIdx.x;
    int i0 = blockIdx.x*4;
    if (c < 64) smask[c] = g_mask[i0*16 + c];
    float m0 = -3.4e38f, m1 = m0, m2 = m0, m3 = m0;
    for (int jc = 0; jc < 8; jc++) {
        __syncthreads();
        for (int t = c; t < 8192; t += 128) sTh[t] = g_Th[jc*8192 + t];
        __syncthreads();
        #pragma unroll
        for (int hf = 0; hf < 2; hf++) {
            int wi = jc*2 + hf;
            unsigned w0 = smask[0*16 + wi], w1 = smask[1*16 + wi];
            unsigned w2 = smask[2*16 + wi], w3 = smask[3*16 + wi];
            #pragma unroll 8
            for (int jj = 0; jj < 32; jj++) {
                float v = sTh[(hf*32 + jj)*128 + c];
                unsigned bit = 1u << jj;
                if (w0 & bit) m0 = fmaxf(m0, v);
                if (w1 & bit) m1 = fmaxf(m1, v);
                if (w2 & bit) m2 = fmaxf(m2, v);
                if (w3 & bit) m3 = fmaxf(m3, v);
            }
        }
    }
    g_h[(i0+0)*128 + c] = fmaxf(m0 + g_Q[(i0+0)*128 + c], 0.f);
    g_h[(i0+1)*128 + c] = fmaxf(m1 + g_Q[(i0+1)*128 + c], 0.f);
    g_h[(i0+2)*128 + c] = fmaxf(m2 + g_Q[(i0+2)*128 + c], 0.f);
    g_h[(i0+3)*128 + c] = fmaxf(m3 + g_Q[(i0+3)*128 + c], 0.f);
}

// ---------------- affinity projection ----------------
__global__ void pproj_kernel() {
    __shared__ float sh[128];
    int i = blockIdx.x, c = threadIdx.x;
    sh[c]      = g_h[i*128 + c];
    sh[64 + c] = g_h[i*128 + 64 + c];
    __syncthreads();
    ull acc = 0ULL;
    #pragma unroll 8
    for (int k2 = 0; k2 < 64; k2++) {
        ull hv = *(const ull*)&sh[2*k2];
        ull w = *(const ull*)&g_w1p[(k2*64 + c)*2];
        fma2(acc, hv, w);
    }
    float2 p = unpack2(acc);
    g_P[i*64 + c] = p.x + p.y;
}

// ---------------- pairwise head ----------------
__global__ void pair_kernel(const float* b1, const float* w2, const float* b2, float* out) {
    __shared__ float sPi[16*65], sPj[16*65], sw2[64], sb1v[64];
    int tid = threadIdx.x;
    int ib = (blockIdx.x >> 4)*16, jb = (blockIdx.x & 15)*16;
    for (int t = tid; t < 1024; t += 256) {
        int r = t >> 6, c = t & 63;
        sPi[r*65 + c] = g_P[(ib + r)*64 + c];
        sPj[r*65 + c] = g_P[(jb + r)*64 + c];
    }
    if (tid < 64) { sw2[tid] = w2[tid]; sb1v[tid] = b1[tid]; }
    __syncthreads();
    int ti = tid >> 4, tj = tid & 15;
    float s = b2[0];
    #pragma unroll 8
    for (int c = 0; c < 64; c++)
        s += sw2[c]*fmaxf(sPj[tj*65 + c] - sPi[ti*65 + c] + sb1v[c], 0.f);
    out[(ib + ti)*256 + jb + tj] = sigmf(s);
}

// ---------------- launch ----------------
extern "C" void kernel_launch(void* const* d_in, const int* in_sizes, int n_in,
                              void* d_out, int out_size) {
    const float* det_pts   = (const float*)d_in[0];
    const float* det_boxes = (const float*)d_in[1];
    const float* trk_pts   = (const float*)d_in[2];
    const float* trk_boxes = (const float*)d_in[3];
    const int*   adj       = (const int*)  d_in[4];
    const float* pn_w1 = (const float*)d_in[5];
    const float* pn_b1 = (const float*)d_in[6];
    const float* pn_w2 = (const float*)d_in[7];
    const float* pn_b2 = (const float*)d_in[8];
    const float* pn_w3 = (const float*)d_in[9];
    const float* pn_b3 = (const float*)d_in[10];
    const float* dm_w1 = (const float*)d_in[11];
    const float* dm_b1 = (const float*)d_in[12];
    const float* dm_w2 = (const float*)d_in[13];
    const float* dm_b2 = (const float*)d_in[14];
    const float* l0_wih = (const float*)d_in[15];
    const float* l0_whh = (const float*)d_in[16];
    const float* l0_bih = (const float*)d_in[17];
    const float* l0_bhh = (const float*)d_in[18];
    const float* l1_wih = (const float*)d_in[19];
    const float* l1_whh = (const float*)d_in[20];
    const float* l1_bih = (const float*)d_in[21];
    const float* l1_bhh = (const float*)d_in[22];
    const float* gc_wt = (const float*)d_in[23];
    const float* gc_bt = (const float*)d_in[24];
    const float* gc_wp = (const float*)d_in[25];
    const float* gc_bp = (const float*)d_in[26];
    const float* er_w1 = (const float*)d_in[27];
    const float* er_b1 = (const float*)d_in[28];
    const float* er_w2 = (const float*)d_in[29];
    const float* er_b2 = (const float*)d_in[30];
    float* out = (float*)d_out;

    cudaFuncSetAttribute(mega_kernel, cudaFuncAttributeMaxDynamicSharedMemorySize,
                         MEGA_SMEM);

    prep_kernel<<<256, 256>>>(gc_wt, gc_bt, gc_wp, gc_bp, er_w1, adj);
    mega_kernel<<<641, 256, MEGA_SMEM>>>(
        det_pts, trk_pts, pn_w1, pn_b1, pn_w2, pn_b2, pn_w3, pn_b3,
        det_boxes, dm_w1, dm_b1, dm_w2, dm_b2,
        trk_boxes, l0_wih, l0_whh, l0_bih, l0_bhh,
        l1_wih, l1_whh, l1_bih, l1_bhh);

    for (int l = 0; l < 4; l++) {
        thq_kernel<<<512, 128>>>(l);
        edge_kernel<<<128, 128>>>();
        if (l == 0) {
            pproj_kernel<<<256, 64>>>();
            pair_kernel<<<256, 256>>>(er_b1, er_w2, er_b2, out);
        }
    }
    pproj_kernel<<<256, 64>>>();
    pair_kernel<<<256, 256>>>(er_b1, er_w2, er_b2, out + 65536);
}

// round 6
// speedup vs baseline: 1.8993x; 1.2646x over previous
#include <cuda_runtime.h>
#include <cuda_bf16.h>
#include <mma.h>
#include <math.h>
#include <stdint.h>

using namespace nvcuda;

#define NDET 256
#define MTRK 256
#define VN   512
#define PPTS 512
#define TSTE 10

typedef unsigned long long ull;

__device__ __forceinline__ void fma2(ull &d, ull a, ull b) {
    asm("fma.rn.f32x2 %0, %1, %2, %0;" : "+l"(d) : "l"(a), "l"(b));
}
__device__ __forceinline__ ull pack2(float x, float y) {
    ull r; asm("mov.b64 %0, {%1, %2};" : "=l"(r) : "f"(x), "f"(y)); return r;
}
__device__ __forceinline__ float2 unpack2(ull v) {
    float2 r; asm("mov.b64 {%0, %1}, %2;" : "=f"(r.x), "=f"(r.y) : "l"(v)); return r;
}
__device__ __forceinline__ float ex2a(float x) { float y; asm("ex2.approx.f32 %0, %1;" : "=f"(y) : "f"(x)); return y; }
__device__ __forceinline__ float rcpa(float x) { float y; asm("rcp.approx.f32 %0, %1;" : "=f"(y) : "f"(x)); return y; }
__device__ __forceinline__ float sigmf(float x) { return rcpa(1.f + ex2a(-1.4426950408889634f * x)); }
__device__ __forceinline__ float tanhf_(float x) { return 2.f * sigmf(2.f * x) - 1.f; }
__device__ __forceinline__ uint32_t cvt2bf(float v_even, float v_odd) {
    uint32_t r; asm("cvt.rn.bf16x2.f32 %0, %1, %2;" : "=r"(r) : "f"(v_odd), "f"(v_even)); return r;
}

// ---------------- device scratch ----------------
__device__ float g_h[VN*128];
__device__ float g_Th[VN*128];
__device__ float g_Q[VN*128];
__device__ float g_P[NDET*64];
__device__ float g_wtd[4*128*128*2];
__device__ float g_bsum[4*128];
__device__ float g_w1p[64*128];
__device__ unsigned g_mask[VN*16];

// ---------------- prep ----------------
__global__ void prep_kernel(const float* gc_wt, const float* gc_bt,
                            const float* gc_wp, const float* gc_bp,
                            const float* er_w1, const int* adj) {
    int idx = blockIdx.x*blockDim.x + threadIdx.x;
    int stride = gridDim.x*blockDim.x;
    for (int i = idx; i < 4*128*128; i += stride) {
        int l = i >> 14, r = (i >> 7) & 127, k = i & 127;
        float wt = gc_wt[i], wp = gc_wp[i];
        g_wtd[l*32768 + (k*128 + r)*2 + 0] = wt;
        g_wtd[l*32768 + (k*128 + r)*2 + 1] = wp - wt;
    }
    for (int i = idx; i < 4*128; i += stride) g_bsum[i] = gc_bt[i] + gc_bp[i];
    for (int i = idx; i < 64*128; i += stride) {
        int r = i >> 7, k = i & 127;
        g_w1p[((k >> 1)*64 + r)*2 + (k & 1)] = er_w1[i];
    }
    for (int w = idx; w < VN*16; w += stride) {
        int i = w >> 4, wo = w & 15;
        unsigned bits = 0;
        #pragma unroll
        for (int b = 0; b < 32; b++) {
            int j = wo*32 + b;
            if (adj[j*VN + i] != 0 || j == i) bits |= (1u << b);
        }
        g_mask[w] = bits;
    }
}

// ---------------- PointNet smem layout (bytes) ----------------
#define PN_A1H   0
#define PN_A1L   18432
#define PN_W2H   36864
#define PN_W2L   55296
#define PN_A2H   73728
#define PN_A2L   108544
#define PN_W3H   143360
#define PN_W3L   160768
#define PN_SCR   178176
#define PN_AUX   188416

#define LDA1 72
#define LDW2 72
#define LDA2 136
#define LDW3 136
#define LDSC 20

#define MEGA_SMEM 216352

__device__ __forceinline__ void bfsplit(float v, __nv_bfloat16 &hb, __nv_bfloat16 &lb) {
    hb = __float2bfloat16(v);
    lb = __float2bfloat16(v - __bfloat162float(hb));
}

// ---------------- pointnet body ----------------
__device__ void pointnet_body(char* smc, int item,
                              const float* det_pts, const float* trk_pts,
                              const float* w1, const float* b1,
                              const float* w2, const float* b2,
                              const float* w3, const float* b3) {
    __nv_bfloat16* A1H = (__nv_bfloat16*)(smc + PN_A1H);
    __nv_bfloat16* A1L = (__nv_bfloat16*)(smc + PN_A1L);
    __nv_bfloat16* W2H = (__nv_bfloat16*)(smc + PN_W2H);
    __nv_bfloat16* W2L = (__nv_bfloat16*)(smc + PN_W2L);
    __nv_bfloat16* A2H = (__nv_bfloat16*)(smc + PN_A2H);
    __nv_bfloat16* A2L = (__nv_bfloat16*)(smc + PN_A2L);
    __nv_bfloat16* W3H = (__nv_bfloat16*)(smc + PN_W3H);
    __nv_bfloat16* W3L = (__nv_bfloat16*)(smc + PN_W3L);
    float* SCR = (float*)(smc + PN_SCR);
    float* sW1 = (float*)(smc + PN_AUX);
    float* sB1 = sW1 + 320;
    float* sB2 = sB1 + 64;
    float* sRED = sB2 + 128;

    int tid = threadIdx.x, warp = tid >> 5, lane = tid & 31;
    const float* pts = (item < NDET) ? det_pts + (size_t)item*PPTS*5
                                     : trk_pts + (size_t)(item-NDET)*PPTS*5;

    for (int i = tid; i < 320; i += 256) { int o = i/5, c = i%5; sW1[c*64+o] = w1[i]; }
    if (tid < 64)  sB1[tid] = b1[tid];
    if (tid < 128) sB2[tid] = b2[tid];
    for (int i = tid; i < 8192; i += 256) {
        int j = i >> 6, k = i & 63;
        __nv_bfloat16 hb, lb; bfsplit(w2[i], hb, lb);
        W2H[j*LDW2 + k] = hb; W2L[j*LDW2 + k] = lb;
    }
    for (int i = tid; i < 8192; i += 256) {
        int o = i >> 7, k = i & 127;
        __nv_bfloat16 hb, lb; bfsplit(w3[i], hb, lb);
        W3H[o*LDW3 + k] = hb; W3L[o*LDW3 + k] = lb;
    }
    __syncthreads();

    int band = warp*16;
    float* scr = SCR + warp*320;
    int rrow = lane & 15, rcolh = lane >> 4;
    float rmax[4] = {-3.4e38f, -3.4e38f, -3.4e38f, -3.4e38f};

    for (int t = 0; t < 4; t++) {
        {
            const float* xp = pts + (size_t)(t*128 + band + rrow)*5;
            float x0 = xp[0], x1 = xp[1], x2 = xp[2], x3 = xp[3], x4 = xp[4];
            int ob = rcolh*32;
            int rowb = (band + rrow)*LDA1;
            #pragma unroll
            for (int o2 = 0; o2 < 16; o2++) {
                int o = ob + 2*o2;
                float v0 = sB1[o]   + x0*sW1[o]     + x1*sW1[64+o]     + x2*sW1[128+o]
                                    + x3*sW1[192+o] + x4*sW1[256+o];
                float v1 = sB1[o+1] + x0*sW1[o+1]   + x1*sW1[64+o+1]   + x2*sW1[128+o+1]
                                    + x3*sW1[192+o+1] + x4*sW1[256+o+1];
                v0 = fmaxf(v0, 0.f); v1 = fmaxf(v1, 0.f);
                uint32_t hp = cvt2bf(v0, v1);
                float h0 = __uint_as_float(hp << 16);
                float h1 = __uint_as_float(hp & 0xffff0000u);
                uint32_t lp = cvt2bf(v0 - h0, v1 - h1);
                *(uint32_t*)&A1H[rowb + o] = hp;
                *(uint32_t*)&A1L[rowb + o] = lp;
            }
        }
        __syncwarp();
        {
            wmma::fragment<wmma::matrix_a, 16, 16, 16, __nv_bfloat16, wmma::row_major> Ah[4], Al[4];
            #pragma unroll
            for (int k = 0; k < 4; k++) {
                wmma::load_matrix_sync(Ah[k], &A1H[band*LDA1 + k*16], LDA1);
                wmma::load_matrix_sync(Al[k], &A1L[band*LDA1 + k*16], LDA1);
            }
            int r2 = lane >> 1, cb = (lane & 1)*8;
            #pragma unroll
            for (int j = 0; j < 8; j++) {
                wmma::fragment<wmma::accumulator, 16, 16, 16, float> C;
                wmma::fill_fragment(C, 0.f);
                #pragma unroll
                for (int k = 0; k < 4; k++) {
                    wmma::fragment<wmma::matrix_b, 16, 16, 16, __nv_bfloat16, wmma::col_major> Bh, Bl;
                    wmma::load_matrix_sync(Bh, &W2H[j*16*LDW2 + k*16], LDW2);
                    wmma::load_matrix_sync(Bl, &W2L[j*16*LDW2 + k*16], LDW2);
                    wmma::mma_sync(C, Ah[k], Bh, C);
                    wmma::mma_sync(C, Al[k], Bh, C);
                    wmma::mma_sync(C, Ah[k], Bl, C);
                }
                wmma::store_matrix_sync(scr, C, LDSC, wmma::mem_row_major);
                __syncwarp();
                int rowb = (band + r2)*LDA2 + j*16 + cb;
                #pragma unroll
                for (int cc = 0; cc < 8; cc += 2) {
                    float v0 = fmaxf(scr[r2*LDSC + cb + cc]     + sB2[j*16 + cb + cc],     0.f);
                    float v1 = fmaxf(scr[r2*LDSC + cb + cc + 1] + sB2[j*16 + cb + cc + 1], 0.f);
                    uint32_t hp = cvt2bf(v0, v1);
                    float h0 = __uint_as_float(hp << 16);
                    float h1 = __uint_as_float(hp & 0xffff0000u);
                    uint32_t lp = cvt2bf(v0 - h0, v1 - h1);
                    *(uint32_t*)&A2H[rowb + cc] = hp;
                    *(uint32_t*)&A2L[rowb + cc] = lp;
                }
                __syncwarp();
            }
        }
        {
            wmma::fragment<wmma::matrix_a, 16, 16, 16, __nv_bfloat16, wmma::row_major> Ah[8], Al[8];
            #pragma unroll
            for (int k = 0; k < 8; k++) {
                wmma::load_matrix_sync(Ah[k], &A2H[band*LDA2 + k*16], LDA2);
                wmma::load_matrix_sync(Al[k], &A2L[band*LDA2 + k*16], LDA2);
            }
            #pragma unroll
            for (int nt = 0; nt < 4; nt++) {
                wmma::fragment<wmma::accumulator, 16, 16, 16, float> C;
                wmma::fill_fragment(C, 0.f);
                #pragma unroll
                for (int k = 0; k < 8; k++) {
                    wmma::fragment<wmma::matrix_b, 16, 16, 16, __nv_bfloat16, wmma::col_major> Bh, Bl;
                    wmma::load_matrix_sync(Bh, &W3H[nt*16*LDW3 + k*16], LDW3);
                    wmma::load_matrix_sync(Bl, &W3L[nt*16*LDW3 + k*16], LDW3);
                    wmma::mma_sync(C, Ah[k], Bh, C);
                    wmma::mma_sync(C, Al[k], Bh, C);
                    wmma::mma_sync(C, Ah[k], Bl, C);
                }
                wmma::store_matrix_sync(scr, C, LDSC, wmma::mem_row_major);
                __syncwarp();
                if (lane < 16) {
                    float m = scr[lane];
                    #pragma unroll
                    for (int r = 1; r < 16; r++) m = fmaxf(m, scr[r*LDSC + lane]);
                    rmax[nt] = fmaxf(rmax[nt], m);
                }
                __syncwarp();
            }
        }
    }
    if (lane < 16) {
        #pragma unroll
        for (int nt = 0; nt < 4; nt++) sRED[warp*64 + nt*16 + lane] = rmax[nt];
    }
    __syncthreads();
    if (tid < 64) {
        float m = sRED[tid];
        #pragma unroll
        for (int w = 1; w < 8; w++) m = fmaxf(m, sRED[w*64 + tid]);
        g_h[item*128 + tid] = m + b3[tid];
    }
}

// ---------------- lstm body ----------------
__device__ void lstm_body(char* smc, int bid, const float* tb,
                          const float* wih0, const float* whh0,
                          const float* bih0, const float* bhh0,
                          const float* wih1, const float* whh1,
                          const float* bih1, const float* bhh1) {
    float* sm = (float*)smc;
    float* sWih0p = sm;
    float* sWih0s = sm + 2048;
    float* sWhh0p = sm + 2304;
    float* sWih1p = sm + 18688;
    float* sWhh1p = sm + 35072;
    float* sB0    = sm + 51456;
    float* sB1    = sm + 51712;
    float* sH     = sm + 51968;
    float* sHs0   = sm + 52096;
    float* sX     = sm + 53376;
    float* sG     = sm + 53576;

    int tid = threadIdx.x;
    int m0 = bid*2;

    for (int i = tid; i < 2304; i += 256) {
        int r = i/9, c = i%9; float v = wih0[i];
        if (c < 8) sWih0p[((c>>1)*256 + r)*2 + (c&1)] = v; else sWih0s[r] = v;
    }
    for (int i = tid; i < 16384; i += 256) { int r = i>>6, k = i&63; sWhh0p[((k>>1)*256+r)*2+(k&1)] = whh0[i]; }
    for (int i = tid; i < 16384; i += 256) { int r = i>>6, k = i&63; sWih1p[((k>>1)*256+r)*2+(k&1)] = wih1[i]; }
    for (int i = tid; i < 16384; i += 256) { int r = i>>6, k = i&63; sWhh1p[((k>>1)*256+r)*2+(k&1)] = whh1[i]; }
    if (tid < 256) { sB0[tid] = bih0[tid]+bhh0[tid]; sB1[tid] = bih1[tid]+bhh1[tid]; }
    for (int i = tid; i < 180; i += 256) {
        int tr = i/90, rest = i%90, t = rest/9, c = rest%9;
        sX[tr*100 + t*10 + c] = tb[(size_t)(m0+tr)*TSTE*9 + t*9 + c];
    }
    if (tid < 128) sH[tid] = 0.f;
    __syncthreads();

    int r = tid;
    int utr = tid >> 6, uu = tid & 63;
    float cc = 0.f;

    for (int t = 0; t < TSTE; t++) {
        ull a0 = 0ULL, a1 = 0ULL;
        const float* xb0 = sX + t*10;
        const float* xb1 = sX + 100 + t*10;
        #pragma unroll
        for (int c2 = 0; c2 < 4; c2++) {
            ull w = *(const ull*)&sWih0p[(c2*256 + r)*2];
            fma2(a0, *(const ull*)&xb0[2*c2], w);
            fma2(a1, *(const ull*)&xb1[2*c2], w);
        }
        float s0 = xb0[8]*sWih0s[r], s1 = xb1[8]*sWih0s[r];
        #pragma unroll 8
        for (int k2 = 0; k2 < 32; k2++) {
            ull w = *(const ull*)&sWhh0p[(k2*256 + r)*2];
            fma2(a0, *(const ull*)&sH[2*k2], w);
            fma2(a1, *(const ull*)&sH[64 + 2*k2], w);
        }
        float2 p0 = unpack2(a0), p1 = unpack2(a1);
        sG[r]     = p0.x + p0.y + s0 + sB0[r];
        sG[256+r] = p1.x + p1.y + s1 + sB0[r];
        __syncthreads();
        if (tid < 128) {
            float gi = sigmf(sG[utr*256 + uu]);
            float gf = sigmf(sG[utr*256 + 64 + uu]);
            float gg = tanhf_(sG[utr*256 + 128 + uu]);
            float go = sigmf(sG[utr*256 + 192 + uu]);
            cc = gf*cc + gi*gg;
            float hn = go*tanhf_(cc);
            sH[tid] = hn;
            sHs0[utr*640 + t*64 + uu] = hn;
        }
        __syncthreads();
    }
    if (tid < 128) sH[tid] = 0.f;
    cc = 0.f;
    __syncthreads();
    float hlast = 0.f;
    for (int t = 0; t < TSTE; t++) {
        ull a0 = 0ULL, a1 = 0ULL;
        #pragma unroll 8
        for (int k2 = 0; k2 < 32; k2++) {
            ull w = *(const ull*)&sWih1p[(k2*256 + r)*2];
            fma2(a0, *(const ull*)&sHs0[t*64 + 2*k2], w);
            fma2(a1, *(const ull*)&sHs0[640 + t*64 + 2*k2], w);
        }
        #pragma unroll 8
        for (int k2 = 0; k2 < 32; k2++) {
            ull w = *(const ull*)&sWhh1p[(k2*256 + r)*2];
            fma2(a0, *(const ull*)&sH[2*k2], w);
            fma2(a1, *(const ull*)&sH[64 + 2*k2], w);
        }
        float2 p0 = unpack2(a0), p1 = unpack2(a1);
        sG[r]     = p0.x + p0.y + sB1[r];
        sG[256+r] = p1.x + p1.y + sB1[r];
        __syncthreads();
        if (tid < 128) {
            float gi = sigmf(sG[utr*256 + uu]);
            float gf = sigmf(sG[utr*256 + 64 + uu]);
            float gg = tanhf_(sG[utr*256 + 128 + uu]);
            float go = sigmf(sG[utr*256 + 192 + uu]);
            cc = gf*cc + gi*gg;
            hlast = go*tanhf_(cc);
            sH[tid] = hlast;
        }
        __syncthreads();
    }
    if (tid < 128) g_h[(NDET + m0 + utr)*128 + 64 + uu] = hlast;
}

// ---------------- detmot body ----------------
__device__ void detmot_body(const float* boxes, const float* w1, const float* b1,
                            const float* w2, const float* b2) {
    int i = threadIdx.x;
    float x[9];
    #pragma unroll
    for (int c = 0; c < 9; c++) x[c] = boxes[i*9 + c];
    float h[32];
    #pragma unroll
    for (int r = 0; r < 32; r++) {
        float a = b1[r];
        #pragma unroll
        for (int c = 0; c < 9; c++) a += x[c]*w1[r*9 + c];
        h[r] = fmaxf(a, 0.f);
    }
    for (int o = 0; o < 64; o++) {
        float a = b2[o];
        #pragma unroll
        for (int r = 0; r < 32; r++) a += h[r]*w2[o*32 + r];
        g_h[i*128 + 64 + o] = a;
    }
}

// ---------------- mega kernel ----------------
__global__ __launch_bounds__(256) void mega_kernel(
    const float* det_pts, const float* trk_pts,
    const float* pn_w1, const float* pn_b1, const float* pn_w2, const float* pn_b2,
    const float* pn_w3, const float* pn_b3,
    const float* det_boxes, const float* dm_w1, const float* dm_b1,
    const float* dm_w2, const float* dm_b2,
    const float* tb, const float* wih0, const float* whh0,
    const float* bih0, const float* bhh0,
    const float* wih1, const float* whh1,
    const float* bih1, const float* bhh1) {
    extern __shared__ char smc[];
    int bid = blockIdx.x;
    if (bid < 128) {
        lstm_body(smc, bid, tb, wih0, whh0, bih0, bhh0, wih1, whh1, bih1, bhh1);
    } else if (bid == 128) {
        detmot_body(det_boxes, dm_w1, dm_b1, dm_w2, dm_b2);
    } else {
        pointnet_body(smc, bid - 129, det_pts, trk_pts,
                      pn_w1, pn_b1, pn_w2, pn_b2, pn_w3, pn_b3);
    }
}

// ---------------- EdgeConv A ----------------
__global__ void thq_kernel(int l) {
    __shared__ float sh[128];
    int i = blockIdx.x, c = threadIdx.x;
    sh[c] = g_h[i*128 + c];
    __syncthreads();
    const float* wtd = g_wtd + l*32768;
    ull acc = 0ULL;
    #pragma unroll 8
    for (int k = 0; k < 128; k++) {
        float hv = sh[k];
        ull w = *(const ull*)&wtd[(k*128 + c)*2];
        fma2(acc, pack2(hv, hv), w);
    }
    float2 p = unpack2(acc);
    g_Th[i*128 + c] = p.x;
    g_Q[i*128 + c]  = p.y + g_bsum[l*128 + c];
}

// ---------------- EdgeConv B: one node per CTA, predicated streaming max ----------------
__global__ void edge_kernel() {
    __shared__ unsigned smask[16];
    int i = blockIdx.x;     // node
    int c = threadIdx.x;    // channel
    if (c < 16) smask[c] = g_mask[i*16 + c];
    __syncthreads();
    const float* Th = g_Th + c;
    float m0 = -3.4e38f, m1 = m0, m2 = m0, m3 = m0;
    #pragma unroll 2
    for (int w = 0; w < 16; w++) {
        unsigned bits = smask[w];
        int jb = w*32;
        #pragma unroll
        for (int b = 0; b < 32; b += 4) {
            float v0 = Th[(jb + b)*128];
            float v1 = Th[(jb + b + 1)*128];
            float v2 = Th[(jb + b + 2)*128];
            float v3 = Th[(jb + b + 3)*128];
            if (bits & (1u << b))       m0 = fmaxf(m0, v0);
            if (bits & (1u << (b + 1))) m1 = fmaxf(m1, v1);
            if (bits & (1u << (b + 2))) m2 = fmaxf(m2, v2);
            if (bits & (1u << (b + 3))) m3 = fmaxf(m3, v3);
        }
    }
    float m = fmaxf(fmaxf(m0, m1), fmaxf(m2, m3));
    g_h[i*128 + c] = fmaxf(m + g_Q[i*128 + c], 0.f);
}

// ---------------- affinity projection ----------------
__global__ void pproj_kernel() {
    __shared__ float sh[128];
    int i = blockIdx.x, c = threadIdx.x;
    sh[c]      = g_h[i*128 + c];
    sh[64 + c] = g_h[i*128 + 64 + c];
    __syncthreads();
    ull acc = 0ULL;
    #pragma unroll 8
    for (int k2 = 0; k2 < 64; k2++) {
        ull hv = *(const ull*)&sh[2*k2];
        ull w = *(const ull*)&g_w1p[(k2*64 + c)*2];
        fma2(acc, hv, w);
    }
    float2 p = unpack2(acc);
    g_P[i*64 + c] = p.x + p.y;
}

// ---------------- pairwise head ----------------
__global__ void pair_kernel(const float* b1, const float* w2, const float* b2, float* out) {
    __shared__ float sPi[16*65], sPj[16*65], sw2[64], sb1v[64];
    int tid = threadIdx.x;
    int ib = (blockIdx.x >> 4)*16, jb = (blockIdx.x & 15)*16;
    for (int t = tid; t < 1024; t += 256) {
        int r = t >> 6, c = t & 63;
        sPi[r*65 + c] = g_P[(ib + r)*64 + c];
        sPj[r*65 + c] = g_P[(jb + r)*64 + c];
    }
    if (tid < 64) { sw2[tid] = w2[tid]; sb1v[tid] = b1[tid]; }
    __syncthreads();
    int ti = tid >> 4, tj = tid & 15;
    float s = b2[0];
    #pragma unroll 8
    for (int c = 0; c < 64; c++)
        s += sw2[c]*fmaxf(sPj[tj*65 + c] - sPi[ti*65 + c] + sb1v[c], 0.f);
    out[(ib + ti)*256 + jb + tj] = sigmf(s);
}

// ---------------- launch ----------------
extern "C" void kernel_launch(void* const* d_in, const int* in_sizes, int n_in,
                              void* d_out, int out_size) {
    const float* det_pts   = (const float*)d_in[0];
    const float* det_boxes = (const float*)d_in[1];
    const float* trk_pts   = (const float*)d_in[2];
    const float* trk_boxes = (const float*)d_in[3];
    const int*   adj       = (const int*)  d_in[4];
    const float* pn_w1 = (const float*)d_in[5];
    const float* pn_b1 = (const float*)d_in[6];
    const float* pn_w2 = (const float*)d_in[7];
    const float* pn_b2 = (const float*)d_in[8];
    const float* pn_w3 = (const float*)d_in[9];
    const float* pn_b3 = (const float*)d_in[10];
    const float* dm_w1 = (const float*)d_in[11];
    const float* dm_b1 = (const float*)d_in[12];
    const float* dm_w2 = (const float*)d_in[13];
    const float* dm_b2 = (const float*)d_in[14];
    const float* l0_wih = (const float*)d_in[15];
    const float* l0_whh = (const float*)d_in[16];
    const float* l0_bih = (const float*)d_in[17];
    const float* l0_bhh = (const float*)d_in[18];
    const float* l1_wih = (const float*)d_in[19];
    const float* l1_whh = (const float*)d_in[20];
    const float* l1_bih = (const float*)d_in[21];
    const float* l1_bhh = (const float*)d_in[22];
    const float* gc_wt = (const float*)d_in[23];
    const float* gc_bt = (const float*)d_in[24];
    const float* gc_wp = (const float*)d_in[25];
    const float* gc_bp = (const float*)d_in[26];
    const float* er_w1 = (const float*)d_in[27];
    const float* er_b1 = (const float*)d_in[28];
    const float* er_w2 = (const float*)d_in[29];
    const float* er_b2 = (const float*)d_in[30];
    float* out = (float*)d_out;

    cudaFuncSetAttribute(mega_kernel, cudaFuncAttributeMaxDynamicSharedMemorySize,
                         MEGA_SMEM);

    prep_kernel<<<256, 256>>>(gc_wt, gc_bt, gc_wp, gc_bp, er_w1, adj);
    mega_kernel<<<641, 256, MEGA_SMEM>>>(
        det_pts, trk_pts, pn_w1, pn_b1, pn_w2, pn_b2, pn_w3, pn_b3,
        det_boxes, dm_w1, dm_b1, dm_w2, dm_b2,
        trk_boxes, l0_wih, l0_whh, l0_bih, l0_bhh,
        l1_wih, l1_whh, l1_bih, l1_bhh);

    for (int l = 0; l < 4; l++) {
        thq_kernel<<<512, 128>>>(l);
        edge_kernel<<<512, 128>>>();
        if (l == 0) {
            pproj_kernel<<<256, 64>>>();
            pair_kernel<<<256, 256>>>(er_b1, er_w2, er_b2, out);
        }
    }
    pproj_kernel<<<256, 64>>>();
    pair_kernel<<<256, 256>>>(er_b1, er_w2, er_b2, out + 65536);
}

// round 7
// speedup vs baseline: 2.0498x; 1.0793x over previous
#include <cuda_runtime.h>
#include <cuda_bf16.h>
#include <mma.h>
#include <math.h>
#include <stdint.h>

using namespace nvcuda;

#define NDET 256
#define MTRK 256
#define VN   512
#define PPTS 512
#define TSTE 10

typedef unsigned long long ull;

__device__ __forceinline__ void fma2(ull &d, ull a, ull b) {
    asm("fma.rn.f32x2 %0, %1, %2, %0;" : "+l"(d) : "l"(a), "l"(b));
}
__device__ __forceinline__ ull pack2(float x, float y) {
    ull r; asm("mov.b64 %0, {%1, %2};" : "=l"(r) : "f"(x), "f"(y)); return r;
}
__device__ __forceinline__ float2 unpack2(ull v) {
    float2 r; asm("mov.b64 {%0, %1}, %2;" : "=f"(r.x), "=f"(r.y) : "l"(v)); return r;
}
__device__ __forceinline__ float ex2a(float x) { float y; asm("ex2.approx.f32 %0, %1;" : "=f"(y) : "f"(x)); return y; }
__device__ __forceinline__ float rcpa(float x) { float y; asm("rcp.approx.f32 %0, %1;" : "=f"(y) : "f"(x)); return y; }
__device__ __forceinline__ float sigmf(float x) { return rcpa(1.f + ex2a(-1.4426950408889634f * x)); }
__device__ __forceinline__ float tanhf_(float x) { return 2.f * sigmf(2.f * x) - 1.f; }
__device__ __forceinline__ uint32_t cvt2bf(float v_even, float v_odd) {
    uint32_t r; asm("cvt.rn.bf16x2.f32 %0, %1, %2;" : "=r"(r) : "f"(v_odd), "f"(v_even)); return r;
}

// ---------------- device scratch ----------------
__device__ float g_h[VN*128];
__device__ float g_Th[VN*128];
__device__ float g_Q[VN*128];
__device__ float g_P[NDET*64];
__device__ float g_wtd[4*128*128*2];
__device__ float g_bsum[4*128];
__device__ float g_w1p[64*128];
__device__ unsigned g_mask[VN*16];
__device__ float g_epart[VN*4*128];

// ---------------- prep body ----------------
__device__ void prep_body(int pbid, const float* gc_wt, const float* gc_bt,
                          const float* gc_wp, const float* gc_bp,
                          const float* er_w1, const int* adj) {
    int idx = pbid*256 + threadIdx.x;
    int stride = 256*256;
    for (int i = idx; i < 4*128*128; i += stride) {
        int l = i >> 14, r = (i >> 7) & 127, k = i & 127;
        float wt = gc_wt[i], wp = gc_wp[i];
        g_wtd[l*32768 + (k*128 + r)*2 + 0] = wt;
        g_wtd[l*32768 + (k*128 + r)*2 + 1] = wp - wt;
    }
    for (int i = idx; i < 4*128; i += stride) g_bsum[i] = gc_bt[i] + gc_bp[i];
    for (int i = idx; i < 64*128; i += stride) {
        int r = i >> 7, k = i & 127;
        g_w1p[((k >> 1)*64 + r)*2 + (k & 1)] = er_w1[i];
    }
    for (int w = idx; w < VN*16; w += stride) {
        int i = w >> 4, wo = w & 15;
        unsigned bits = 0;
        #pragma unroll
        for (int b = 0; b < 32; b++) {
            int j = wo*32 + b;
            if (adj[j*VN + i] != 0 || j == i) bits |= (1u << b);
        }
        g_mask[w] = bits;
    }
}

// ---------------- PointNet smem layout (bytes) ----------------
#define PN_A1H   0
#define PN_A1L   18432
#define PN_W2H   36864
#define PN_W2L   55296
#define PN_A2H   73728
#define PN_A2L   108544
#define PN_W3H   143360
#define PN_W3L   160768
#define PN_SCR   178176
#define PN_AUX   188416

#define LDA1 72
#define LDW2 72
#define LDA2 136
#define LDW3 136
#define LDSC 20

#define MEGA_SMEM 216352

__device__ __forceinline__ void bfsplit(float v, __nv_bfloat16 &hb, __nv_bfloat16 &lb) {
    hb = __float2bfloat16(v);
    lb = __float2bfloat16(v - __bfloat162float(hb));
}

// ---------------- pointnet body ----------------
__device__ void pointnet_body(char* smc, int item,
                              const float* det_pts, const float* trk_pts,
                              const float* w1, const float* b1,
                              const float* w2, const float* b2,
                              const float* w3, const float* b3) {
    __nv_bfloat16* A1H = (__nv_bfloat16*)(smc + PN_A1H);
    __nv_bfloat16* A1L = (__nv_bfloat16*)(smc + PN_A1L);
    __nv_bfloat16* W2H = (__nv_bfloat16*)(smc + PN_W2H);
    __nv_bfloat16* W2L = (__nv_bfloat16*)(smc + PN_W2L);
    __nv_bfloat16* A2H = (__nv_bfloat16*)(smc + PN_A2H);
    __nv_bfloat16* A2L = (__nv_bfloat16*)(smc + PN_A2L);
    __nv_bfloat16* W3H = (__nv_bfloat16*)(smc + PN_W3H);
    __nv_bfloat16* W3L = (__nv_bfloat16*)(smc + PN_W3L);
    float* SCR = (float*)(smc + PN_SCR);
    float* sW1 = (float*)(smc + PN_AUX);
    float* sB1 = sW1 + 320;
    float* sB2 = sB1 + 64;
    float* sRED = sB2 + 128;

    int tid = threadIdx.x, warp = tid >> 5, lane = tid & 31;
    const float* pts = (item < NDET) ? det_pts + (size_t)item*PPTS*5
                                     : trk_pts + (size_t)(item-NDET)*PPTS*5;

    for (int i = tid; i < 320; i += 256) { int o = i/5, c = i%5; sW1[c*64+o] = w1[i]; }
    if (tid < 64)  sB1[tid] = b1[tid];
    if (tid < 128) sB2[tid] = b2[tid];
    for (int i = tid; i < 8192; i += 256) {
        int j = i >> 6, k = i & 63;
        __nv_bfloat16 hb, lb; bfsplit(w2[i], hb, lb);
        W2H[j*LDW2 + k] = hb; W2L[j*LDW2 + k] = lb;
    }
    for (int i = tid; i < 8192; i += 256) {
        int o = i >> 7, k = i & 127;
        __nv_bfloat16 hb, lb; bfsplit(w3[i], hb, lb);
        W3H[o*LDW3 + k] = hb; W3L[o*LDW3 + k] = lb;
    }
    __syncthreads();

    int band = warp*16;
    float* scr = SCR + warp*320;
    int rrow = lane & 15, rcolh = lane >> 4;
    float rmax[4] = {-3.4e38f, -3.4e38f, -3.4e38f, -3.4e38f};

    for (int t = 0; t < 4; t++) {
        {
            const float* xp = pts + (size_t)(t*128 + band + rrow)*5;
            float x0 = xp[0], x1 = xp[1], x2 = xp[2], x3 = xp[3], x4 = xp[4];
            int ob = rcolh*32;
            int rowb = (band + rrow)*LDA1;
            #pragma unroll
            for (int o2 = 0; o2 < 16; o2++) {
                int o = ob + 2*o2;
                float v0 = sB1[o]   + x0*sW1[o]     + x1*sW1[64+o]     + x2*sW1[128+o]
                                    + x3*sW1[192+o] + x4*sW1[256+o];
                float v1 = sB1[o+1] + x0*sW1[o+1]   + x1*sW1[64+o+1]   + x2*sW1[128+o+1]
                                    + x3*sW1[192+o+1] + x4*sW1[256+o+1];
                v0 = fmaxf(v0, 0.f); v1 = fmaxf(v1, 0.f);
                uint32_t hp = cvt2bf(v0, v1);
                float h0 = __uint_as_float(hp << 16);
                float h1 = __uint_as_float(hp & 0xffff0000u);
                uint32_t lp = cvt2bf(v0 - h0, v1 - h1);
                *(uint32_t*)&A1H[rowb + o] = hp;
                *(uint32_t*)&A1L[rowb + o] = lp;
            }
        }
        __syncwarp();
        {
            wmma::fragment<wmma::matrix_a, 16, 16, 16, __nv_bfloat16, wmma::row_major> Ah[4], Al[4];
            #pragma unroll
            for (int k = 0; k < 4; k++) {
                wmma::load_matrix_sync(Ah[k], &A1H[band*LDA1 + k*16], LDA1);
                wmma::load_matrix_sync(Al[k], &A1L[band*LDA1 + k*16], LDA1);
            }
            int r2 = lane >> 1, cb = (lane & 1)*8;
            #pragma unroll
            for (int j = 0; j < 8; j++) {
                wmma::fragment<wmma::accumulator, 16, 16, 16, float> C;
                wmma::fill_fragment(C, 0.f);
                #pragma unroll
                for (int k = 0; k < 4; k++) {
                    wmma::fragment<wmma::matrix_b, 16, 16, 16, __nv_bfloat16, wmma::col_major> Bh, Bl;
                    wmma::load_matrix_sync(Bh, &W2H[j*16*LDW2 + k*16], LDW2);
                    wmma::load_matrix_sync(Bl, &W2L[j*16*LDW2 + k*16], LDW2);
                    wmma::mma_sync(C, Ah[k], Bh, C);
                    wmma::mma_sync(C, Al[k], Bh, C);
                    wmma::mma_sync(C, Ah[k], Bl, C);
                }
                wmma::store_matrix_sync(scr, C, LDSC, wmma::mem_row_major);
                __syncwarp();
                int rowb = (band + r2)*LDA2 + j*16 + cb;
                #pragma unroll
                for (int cc = 0; cc < 8; cc += 2) {
                    float v0 = fmaxf(scr[r2*LDSC + cb + cc]     + sB2[j*16 + cb + cc],     0.f);
                    float v1 = fmaxf(scr[r2*LDSC + cb + cc + 1] + sB2[j*16 + cb + cc + 1], 0.f);
                    uint32_t hp = cvt2bf(v0, v1);
                    float h0 = __uint_as_float(hp << 16);
                    float h1 = __uint_as_float(hp & 0xffff0000u);
                    uint32_t lp = cvt2bf(v0 - h0, v1 - h1);
                    *(uint32_t*)&A2H[rowb + cc] = hp;
                    *(uint32_t*)&A2L[rowb + cc] = lp;
                }
                __syncwarp();
            }
        }
        {
            wmma::fragment<wmma::matrix_a, 16, 16, 16, __nv_bfloat16, wmma::row_major> Ah[8], Al[8];
            #pragma unroll
            for (int k = 0; k < 8; k++) {
                wmma::load_matrix_sync(Ah[k], &A2H[band*LDA2 + k*16], LDA2);
                wmma::load_matrix_sync(Al[k], &A2L[band*LDA2 + k*16], LDA2);
            }
            #pragma unroll
            for (int nt = 0; nt < 4; nt++) {
                wmma::fragment<wmma::accumulator, 16, 16, 16, float> C;
                wmma::fill_fragment(C, 0.f);
                #pragma unroll
                for (int k = 0; k < 8; k++) {
                    wmma::fragment<wmma::matrix_b, 16, 16, 16, __nv_bfloat16, wmma::col_major> Bh, Bl;
                    wmma::load_matrix_sync(Bh, &W3H[nt*16*LDW3 + k*16], LDW3);
                    wmma::load_matrix_sync(Bl, &W3L[nt*16*LDW3 + k*16], LDW3);
                    wmma::mma_sync(C, Ah[k], Bh, C);
                    wmma::mma_sync(C, Al[k], Bh, C);
                    wmma::mma_sync(C, Ah[k], Bl, C);
                }
                wmma::store_matrix_sync(scr, C, LDSC, wmma::mem_row_major);
                __syncwarp();
                if (lane < 16) {
                    float m = scr[lane];
                    #pragma unroll
                    for (int r = 1; r < 16; r++) m = fmaxf(m, scr[r*LDSC + lane]);
                    rmax[nt] = fmaxf(rmax[nt], m);
                }
                __syncwarp();
            }
        }
    }
    if (lane < 16) {
        #pragma unroll
        for (int nt = 0; nt < 4; nt++) sRED[warp*64 + nt*16 + lane] = rmax[nt];
    }
    __syncthreads();
    if (tid < 64) {
        float m = sRED[tid];
        #pragma unroll
        for (int w = 1; w < 8; w++) m = fmaxf(m, sRED[w*64 + tid]);
        g_h[item*128 + tid] = m + b3[tid];
    }
}

// ---------------- lstm body ----------------
__device__ void lstm_body(char* smc, int bid, const float* tb,
                          const float* wih0, const float* whh0,
                          const float* bih0, const float* bhh0,
                          const float* wih1, const float* whh1,
                          const float* bih1, const float* bhh1) {
    float* sm = (float*)smc;
    float* sWih0p = sm;
    float* sWih0s = sm + 2048;
    float* sWhh0p = sm + 2304;
    float* sWih1p = sm + 18688;
    float* sWhh1p = sm + 35072;
    float* sB0    = sm + 51456;
    float* sB1    = sm + 51712;
    float* sH     = sm + 51968;
    float* sHs0   = sm + 52096;
    float* sX     = sm + 53376;
    float* sG     = sm + 53576;

    int tid = threadIdx.x;
    int m0 = bid*2;

    for (int i = tid; i < 2304; i += 256) {
        int r = i/9, c = i%9; float v = wih0[i];
        if (c < 8) sWih0p[((c>>1)*256 + r)*2 + (c&1)] = v; else sWih0s[r] = v;
    }
    for (int i = tid; i < 16384; i += 256) { int r = i>>6, k = i&63; sWhh0p[((k>>1)*256+r)*2+(k&1)] = whh0[i]; }
    for (int i = tid; i < 16384; i += 256) { int r = i>>6, k = i&63; sWih1p[((k>>1)*256+r)*2+(k&1)] = wih1[i]; }
    for (int i = tid; i < 16384; i += 256) { int r = i>>6, k = i&63; sWhh1p[((k>>1)*256+r)*2+(k&1)] = whh1[i]; }
    if (tid < 256) { sB0[tid] = bih0[tid]+bhh0[tid]; sB1[tid] = bih1[tid]+bhh1[tid]; }
    for (int i = tid; i < 180; i += 256) {
        int tr = i/90, rest = i%90, t = rest/9, c = rest%9;
        sX[tr*100 + t*10 + c] = tb[(size_t)(m0+tr)*TSTE*9 + t*9 + c];
    }
    if (tid < 128) sH[tid] = 0.f;
    __syncthreads();

    int r = tid;
    int utr = tid >> 6, uu = tid & 63;
    float cc = 0.f;

    for (int t = 0; t < TSTE; t++) {
        ull a0 = 0ULL, a1 = 0ULL;
        const float* xb0 = sX + t*10;
        const float* xb1 = sX + 100 + t*10;
        #pragma unroll
        for (int c2 = 0; c2 < 4; c2++) {
            ull w = *(const ull*)&sWih0p[(c2*256 + r)*2];
            fma2(a0, *(const ull*)&xb0[2*c2], w);
            fma2(a1, *(const ull*)&xb1[2*c2], w);
        }
        float s0 = xb0[8]*sWih0s[r], s1 = xb1[8]*sWih0s[r];
        #pragma unroll 8
        for (int k2 = 0; k2 < 32; k2++) {
            ull w = *(const ull*)&sWhh0p[(k2*256 + r)*2];
            fma2(a0, *(const ull*)&sH[2*k2], w);
            fma2(a1, *(const ull*)&sH[64 + 2*k2], w);
        }
        float2 p0 = unpack2(a0), p1 = unpack2(a1);
        sG[r]     = p0.x + p0.y + s0 + sB0[r];
        sG[256+r] = p1.x + p1.y + s1 + sB0[r];
        __syncthreads();
        if (tid < 128) {
            float gi = sigmf(sG[utr*256 + uu]);
            float gf = sigmf(sG[utr*256 + 64 + uu]);
            float gg = tanhf_(sG[utr*256 + 128 + uu]);
            float go = sigmf(sG[utr*256 + 192 + uu]);
            cc = gf*cc + gi*gg;
            float hn = go*tanhf_(cc);
            sH[tid] = hn;
            sHs0[utr*640 + t*64 + uu] = hn;
        }
        __syncthreads();
    }
    if (tid < 128) sH[tid] = 0.f;
    cc = 0.f;
    __syncthreads();
    float hlast = 0.f;
    for (int t = 0; t < TSTE; t++) {
        ull a0 = 0ULL, a1 = 0ULL;
        #pragma unroll 8
        for (int k2 = 0; k2 < 32; k2++) {
            ull w = *(const ull*)&sWih1p[(k2*256 + r)*2];
            fma2(a0, *(const ull*)&sHs0[t*64 + 2*k2], w);
            fma2(a1, *(const ull*)&sHs0[640 + t*64 + 2*k2], w);
        }
        #pragma unroll 8
        for (int k2 = 0; k2 < 32; k2++) {
            ull w = *(const ull*)&sWhh1p[(k2*256 + r)*2];
            fma2(a0, *(const ull*)&sH[2*k2], w);
            fma2(a1, *(const ull*)&sH[64 + 2*k2], w);
        }
        float2 p0 = unpack2(a0), p1 = unpack2(a1);
        sG[r]     = p0.x + p0.y + sB1[r];
        sG[256+r] = p1.x + p1.y + sB1[r];
        __syncthreads();
        if (tid < 128) {
            float gi = sigmf(sG[utr*256 + uu]);
            float gf = sigmf(sG[utr*256 + 64 + uu]);
            float gg = tanhf_(sG[utr*256 + 128 + uu]);
            float go = sigmf(sG[utr*256 + 192 + uu]);
            cc = gf*cc + gi*gg;
            hlast = go*tanhf_(cc);
            sH[tid] = hlast;
        }
        __syncthreads();
    }
    if (tid < 128) g_h[(NDET + m0 + utr)*128 + 64 + uu] = hlast;
}

// ---------------- detmot body ----------------
__device__ void detmot_body(const float* boxes, const float* w1, const float* b1,
                            const float* w2, const float* b2) {
    int i = threadIdx.x;
    float x[9];
    #pragma unroll
    for (int c = 0; c < 9; c++) x[c] = boxes[i*9 + c];
    float h[32];
    #pragma unroll
    for (int r = 0; r < 32; r++) {
        float a = b1[r];
        #pragma unroll
        for (int c = 0; c < 9; c++) a += x[c]*w1[r*9 + c];
        h[r] = fmaxf(a, 0.f);
    }
    for (int o = 0; o < 64; o++) {
        float a = b2[o];
        #pragma unroll
        for (int r = 0; r < 32; r++) a += h[r]*w2[o*32 + r];
        g_h[i*128 + 64 + o] = a;
    }
}

// ---------------- mega kernel ----------------
__global__ __launch_bounds__(256) void mega_kernel(
    const float* det_pts, const float* trk_pts,
    const float* pn_w1, const float* pn_b1, const float* pn_w2, const float* pn_b2,
    const float* pn_w3, const float* pn_b3,
    const float* det_boxes, const float* dm_w1, const float* dm_b1,
    const float* dm_w2, const float* dm_b2,
    const float* tb, const float* wih0, const float* whh0,
    const float* bih0, const float* bhh0,
    const float* wih1, const float* whh1,
    const float* bih1, const float* bhh1,
    const float* gc_wt, const float* gc_bt, const float* gc_wp, const float* gc_bp,
    const float* er_w1, const int* adj) {
    extern __shared__ char smc[];
    int bid = blockIdx.x;
    if (bid < 128) {
        lstm_body(smc, bid, tb, wih0, whh0, bih0, bhh0, wih1, whh1, bih1, bhh1);
    } else if (bid == 128) {
        detmot_body(det_boxes, dm_w1, dm_b1, dm_w2, dm_b2);
    } else if (bid < 641) {
        pointnet_body(smc, bid - 129, det_pts, trk_pts,
                      pn_w1, pn_b1, pn_w2, pn_b2, pn_w3, pn_b3);
    } else {
        prep_body(bid - 641, gc_wt, gc_bt, gc_wp, gc_bp, er_w1, adj);
    }
}

// ---------------- EdgeConv A: 2 nodes per CTA ----------------
__global__ void thq_kernel(int l) {
    __shared__ float sh[256];
    int tid = threadIdx.x;          // 256
    int sub = tid >> 7, c = tid & 127;
    int n = blockIdx.x*2 + sub;
    sh[tid] = g_h[n*128 + c];
    __syncthreads();
    const float* hv = sh + sub*128;
    const float* wtd = g_wtd + l*32768;
    ull acc = 0ULL;
    #pragma unroll 8
    for (int k = 0; k < 128; k++) {
        float h = hv[k];
        ull w = *(const ull*)&wtd[(k*128 + c)*2];
        fma2(acc, pack2(h, h), w);
    }
    float2 p = unpack2(acc);
    g_Th[n*128 + c] = p.x;
    g_Q[n*128 + c]  = p.y + g_bsum[l*128 + c];
}

// ---------------- EdgeConv B part: node x j-chunk partial max ----------------
__global__ void edge_part_kernel() {
    int bid = blockIdx.x;           // 2048 = 512 nodes x 4 chunks
    int i = bid >> 2, ch = bid & 3;
    int c = threadIdx.x;            // 128
    unsigned bw0 = g_mask[i*16 + ch*4 + 0];
    unsigned bw1 = g_mask[i*16 + ch*4 + 1];
    unsigned bw2 = g_mask[i*16 + ch*4 + 2];
    unsigned bw3 = g_mask[i*16 + ch*4 + 3];
    const float* Th = g_Th + (size_t)(ch*128)*128 + c;
    float m0 = -3.4e38f, m1 = m0, m2 = m0, m3 = m0;
    #pragma unroll
    for (int w = 0; w < 4; w++) {
        unsigned bits = (w == 0) ? bw0 : (w == 1) ? bw1 : (w == 2) ? bw2 : bw3;
        int jb = w*32;
        #pragma unroll
        for (int b = 0; b < 32; b += 4) {
            float v0 = Th[(jb + b)*128];
            float v1 = Th[(jb + b + 1)*128];
            float v2 = Th[(jb + b + 2)*128];
            float v3 = Th[(jb + b + 3)*128];
            if (bits & (1u << b))       m0 = fmaxf(m0, v0);
            if (bits & (1u << (b + 1))) m1 = fmaxf(m1, v1);
            if (bits & (1u << (b + 2))) m2 = fmaxf(m2, v2);
            if (bits & (1u << (b + 3))) m3 = fmaxf(m3, v3);
        }
    }
    g_epart[bid*128 + c] = fmaxf(fmaxf(m0, m1), fmaxf(m2, m3));
}

// ---------------- EdgeConv B finish: combine partials + relu ----------------
__global__ void edge_fin_kernel() {
    int i = blockIdx.x, c = threadIdx.x;
    float m = fmaxf(fmaxf(g_epart[(i*4 + 0)*128 + c], g_epart[(i*4 + 1)*128 + c]),
                    fmaxf(g_epart[(i*4 + 2)*128 + c], g_epart[(i*4 + 3)*128 + c]));
    g_h[i*128 + c] = fmaxf(m + g_Q[i*128 + c], 0.f);
}

// ---------------- affinity projection ----------------
__global__ void pproj_kernel() {
    __shared__ float sh[128];
    int i = blockIdx.x, c = threadIdx.x;
    sh[c]      = g_h[i*128 + c];
    sh[64 + c] = g_h[i*128 + 64 + c];
    __syncthreads();
    ull acc = 0ULL;
    #pragma unroll 8
    for (int k2 = 0; k2 < 64; k2++) {
        ull hv = *(const ull*)&sh[2*k2];
        ull w = *(const ull*)&g_w1p[(k2*64 + c)*2];
        fma2(acc, hv, w);
    }
    float2 p = unpack2(acc);
    g_P[i*64 + c] = p.x + p.y;
}

// ---------------- pairwise head ----------------
__global__ void pair_kernel(const float* b1, const float* w2, const float* b2, float* out) {
    __shared__ float sPi[16*65], sPj[16*65], sw2[64], sb1v[64];
    int tid = threadIdx.x;
    int ib = (blockIdx.x >> 4)*16, jb = (blockIdx.x & 15)*16;
    for (int t = tid; t < 1024; t += 256) {
        int r = t >> 6, c = t & 63;
        sPi[r*65 + c] = g_P[(ib + r)*64 + c];
        sPj[r*65 + c] = g_P[(jb + r)*64 + c];
    }
    if (tid < 64) { sw2[tid] = w2[tid]; sb1v[tid] = b1[tid]; }
    __syncthreads();
    int ti = tid >> 4, tj = tid & 15;
    float s = b2[0];
    #pragma unroll 8
    for (int c = 0; c < 64; c++)
        s += sw2[c]*fmaxf(sPj[tj*65 + c] - sPi[ti*65 + c] + sb1v[c], 0.f);
    out[(ib + ti)*256 + jb + tj] = sigmf(s);
}

// ---------------- launch ----------------
extern "C" void kernel_launch(void* const* d_in, const int* in_sizes, int n_in,
                              void* d_out, int out_size) {
    const float* det_pts   = (const float*)d_in[0];
    const float* det_boxes = (const float*)d_in[1];
    const float* trk_pts   = (const float*)d_in[2];
    const float* trk_boxes = (const float*)d_in[3];
    const int*   adj       = (const int*)  d_in[4];
    const float* pn_w1 = (const float*)d_in[5];
    const float* pn_b1 = (const float*)d_in[6];
    const float* pn_w2 = (const float*)d_in[7];
    const float* pn_b2 = (const float*)d_in[8];
    const float* pn_w3 = (const float*)d_in[9];
    const float* pn_b3 = (const float*)d_in[10];
    const float* dm_w1 = (const float*)d_in[11];
    const float* dm_b1 = (const float*)d_in[12];
    const float* dm_w2 = (const float*)d_in[13];
    const float* dm_b2 = (const float*)d_in[14];
    const float* l0_wih = (const float*)d_in[15];
    const float* l0_whh = (const float*)d_in[16];
    const float* l0_bih = (const float*)d_in[17];
    const float* l0_bhh = (const float*)d_in[18];
    const float* l1_wih = (const float*)d_in[19];
    const float* l1_whh = (const float*)d_in[20];
    const float* l1_bih = (const float*)d_in[21];
    const float* l1_bhh = (const float*)d_in[22];
    const float* gc_wt = (const float*)d_in[23];
    const float* gc_bt = (const float*)d_in[24];
    const float* gc_wp = (const float*)d_in[25];
    const float* gc_bp = (const float*)d_in[26];
    const float* er_w1 = (const float*)d_in[27];
    const float* er_b1 = (const float*)d_in[28];
    const float* er_w2 = (const float*)d_in[29];
    const float* er_b2 = (const float*)d_in[30];
    float* out = (float*)d_out;

    cudaFuncSetAttribute(mega_kernel, cudaFuncAttributeMaxDynamicSharedMemorySize,
                         MEGA_SMEM);

    mega_kernel<<<897, 256, MEGA_SMEM>>>(
        det_pts, trk_pts, pn_w1, pn_b1, pn_w2, pn_b2, pn_w3, pn_b3,
        det_boxes, dm_w1, dm_b1, dm_w2, dm_b2,
        trk_boxes, l0_wih, l0_whh, l0_bih, l0_bhh,
        l1_wih, l1_whh, l1_bih, l1_bhh,
        gc_wt, gc_bt, gc_wp, gc_bp, er_w1, adj);

    for (int l = 0; l < 4; l++) {
        thq_kernel<<<256, 256>>>(l);
        edge_part_kernel<<<2048, 128>>>();
        edge_fin_kernel<<<512, 128>>>();
        if (l == 0) {
            pproj_kernel<<<256, 64>>>();
            pair_kernel<<<256, 256>>>(er_b1, er_w2, er_b2, out);
        }
    }
    pproj_kernel<<<256, 64>>>();
    pair_kernel<<<256, 256>>>(er_b1, er_w2, er_b2, out + 65536);
}

// round 8
// speedup vs baseline: 2.2785x; 1.1116x over previous
#include <cuda_runtime.h>
#include <cuda_bf16.h>
#include <mma.h>
#include <math.h>
#include <stdint.h>

using namespace nvcuda;

#define NDET 256
#define MTRK 256
#define VN   512
#define PPTS 512
#define TSTE 10

typedef unsigned long long ull;

__device__ __forceinline__ void fma2(ull &d, ull a, ull b) {
    asm("fma.rn.f32x2 %0, %1, %2, %0;" : "+l"(d) : "l"(a), "l"(b));
}
__device__ __forceinline__ ull pack2(float x, float y) {
    ull r; asm("mov.b64 %0, {%1, %2};" : "=l"(r) : "f"(x), "f"(y)); return r;
}
__device__ __forceinline__ float2 unpack2(ull v) {
    float2 r; asm("mov.b64 {%0, %1}, %2;" : "=f"(r.x), "=f"(r.y) : "l"(v)); return r;
}
__device__ __forceinline__ float ex2a(float x) { float y; asm("ex2.approx.f32 %0, %1;" : "=f"(y) : "f"(x)); return y; }
__device__ __forceinline__ float rcpa(float x) { float y; asm("rcp.approx.f32 %0, %1;" : "=f"(y) : "f"(x)); return y; }
__device__ __forceinline__ float sigmf(float x) { return rcpa(1.f + ex2a(-1.4426950408889634f * x)); }
__device__ __forceinline__ float tanhf_(float x) { return 2.f * sigmf(2.f * x) - 1.f; }
__device__ __forceinline__ uint32_t cvt2bf(float v_even, float v_odd) {
    uint32_t r; asm("cvt.rn.bf16x2.f32 %0, %1, %2;" : "=r"(r) : "f"(v_odd), "f"(v_even)); return r;
}

// ---------------- device scratch ----------------
__device__ float g_h[VN*128];
__device__ float g_Th[VN*128];
__device__ float g_Q[VN*128];
__device__ float g_P[NDET*64];
__device__ float g_wtd[4*128*128*2];
__device__ float g_bsum[4*128];
__device__ float g_w1p[64*128];
__device__ unsigned g_mask[VN*16];
__device__ float g_epart[VN*4*128];

// ---------------- prep body ----------------
__device__ void prep_body(int pbid, const float* gc_wt, const float* gc_bt,
                          const float* gc_wp, const float* gc_bp,
                          const float* er_w1, const int* adj) {
    int idx = pbid*256 + threadIdx.x;
    int stride = 256*256;
    for (int i = idx; i < 4*128*128; i += stride) {
        int l = i >> 14, r = (i >> 7) & 127, k = i & 127;
        float wt = gc_wt[i], wp = gc_wp[i];
        g_wtd[l*32768 + (k*128 + r)*2 + 0] = wt;
        g_wtd[l*32768 + (k*128 + r)*2 + 1] = wp - wt;
    }
    for (int i = idx; i < 4*128; i += stride) g_bsum[i] = gc_bt[i] + gc_bp[i];
    for (int i = idx; i < 64*128; i += stride) {
        int r = i >> 7, k = i & 127;
        g_w1p[((k >> 1)*64 + r)*2 + (k & 1)] = er_w1[i];
    }
    for (int w = idx; w < VN*16; w += stride) {
        int i = w >> 4, wo = w & 15;
        unsigned bits = 0;
        #pragma unroll
        for (int b = 0; b < 32; b++) {
            int j = wo*32 + b;
            if (adj[j*VN + i] != 0 || j == i) bits |= (1u << b);
        }
        g_mask[w] = bits;
    }
}

// ---------------- PointNet smem layout (bytes) ----------------
#define PN_A1H   0
#define PN_A1L   18432
#define PN_W2H   36864
#define PN_W2L   55296
#define PN_A2H   73728
#define PN_A2L   108544
#define PN_W3H   143360
#define PN_W3L   160768
#define PN_AUX   178176

#define LDA1 72
#define LDW2 72
#define LDA2 136
#define LDW3 136

#define MEGA_SMEM 216352

__device__ __forceinline__ void bfsplit(float v, __nv_bfloat16 &hb, __nv_bfloat16 &lb) {
    hb = __float2bfloat16(v);
    lb = __float2bfloat16(v - __bfloat162float(hb));
}

// ---------------- pointnet body ----------------
__device__ void pointnet_body(char* smc, int item,
                              const float* det_pts, const float* trk_pts,
                              const float* w1, const float* b1,
                              const float* w2, const float* b2,
                              const float* w3, const float* b3) {
    __nv_bfloat16* A1H = (__nv_bfloat16*)(smc + PN_A1H);
    __nv_bfloat16* A1L = (__nv_bfloat16*)(smc + PN_A1L);
    __nv_bfloat16* W2H = (__nv_bfloat16*)(smc + PN_W2H);
    __nv_bfloat16* W2L = (__nv_bfloat16*)(smc + PN_W2L);
    __nv_bfloat16* A2H = (__nv_bfloat16*)(smc + PN_A2H);
    __nv_bfloat16* A2L = (__nv_bfloat16*)(smc + PN_A2L);
    __nv_bfloat16* W3H = (__nv_bfloat16*)(smc + PN_W3H);
    __nv_bfloat16* W3L = (__nv_bfloat16*)(smc + PN_W3L);
    float* sW1 = (float*)(smc + PN_AUX);
    float* sB1 = sW1 + 320;
    float* sB2 = sB1 + 64;
    float* sRED = sB2 + 128;

    int tid = threadIdx.x, warp = tid >> 5, lane = tid & 31;
    const float* pts = (item < NDET) ? det_pts + (size_t)item*PPTS*5
                                     : trk_pts + (size_t)(item-NDET)*PPTS*5;

    for (int i = tid; i < 320; i += 256) { int o = i/5, c = i%5; sW1[c*64+o] = w1[i]; }
    if (tid < 64)  sB1[tid] = b1[tid];
    if (tid < 128) sB2[tid] = b2[tid];
    for (int i = tid; i < 8192; i += 256) {
        int j = i >> 6, k = i & 63;
        __nv_bfloat16 hb, lb; bfsplit(w2[i], hb, lb);
        W2H[j*LDW2 + k] = hb; W2L[j*LDW2 + k] = lb;
    }
    for (int i = tid; i < 8192; i += 256) {
        int o = i >> 7, k = i & 127;
        __nv_bfloat16 hb, lb; bfsplit(w3[i], hb, lb);
        W3H[o*LDW3 + k] = hb; W3L[o*LDW3 + k] = lb;
    }
    __syncthreads();

    // accumulator-fragment element mapping (m16n16k16, two m16n8 halves):
    //   row(i) = (lane>>2) + 8*((i>>1)&1),  col(i) = (lane&3)*2 + (i&1) + 8*(i>>2)
    int rbase = lane >> 2, cbase = (lane & 3)*2;
    int r2 = warp >> 1, c2 = warp & 1;   // L2 2D split
    int band = warp*16;                  // L1/L3 band
    float cm[4][4];                      // L3 per-column running max [nt][4]
    #pragma unroll
    for (int nt = 0; nt < 4; nt++)
        #pragma unroll
        for (int q = 0; q < 4; q++) cm[nt][q] = -3.4e38f;

    for (int t = 0; t < 4; t++) {
        // ---- L1: 5->64 relu, warp band rows ----
        {
            int rrow = lane & 15, rcolh = lane >> 4;
            const float* xp = pts + (size_t)(t*128 + band + rrow)*5;
            float x0 = xp[0], x1 = xp[1], x2 = xp[2], x3 = xp[3], x4 = xp[4];
            int ob = rcolh*32;
            int rowb = (band + rrow)*LDA1;
            #pragma unroll
            for (int o2 = 0; o2 < 16; o2++) {
                int o = ob + 2*o2;
                float v0 = sB1[o]   + x0*sW1[o]     + x1*sW1[64+o]     + x2*sW1[128+o]
                                    + x3*sW1[192+o] + x4*sW1[256+o];
                float v1 = sB1[o+1] + x0*sW1[o+1]   + x1*sW1[64+o+1]   + x2*sW1[128+o+1]
                                    + x3*sW1[192+o+1] + x4*sW1[256+o+1];
                v0 = fmaxf(v0, 0.f); v1 = fmaxf(v1, 0.f);
                uint32_t hp = cvt2bf(v0, v1);
                float h0 = __uint_as_float(hp << 16);
                float h1 = __uint_as_float(hp & 0xffff0000u);
                uint32_t lp = cvt2bf(v0 - h0, v1 - h1);
                *(uint32_t*)&A1H[rowb + o] = hp;
                *(uint32_t*)&A1L[rowb + o] = lp;
            }
        }
        __syncthreads();
        // ---- L2: warp (r2,c2): rows 32*r2..+31, cols c2*64..+63 ----
        {
            wmma::fragment<wmma::matrix_a, 16, 16, 16, __nv_bfloat16, wmma::row_major> Ah[2][4], Al[2][4];
            #pragma unroll
            for (int m2 = 0; m2 < 2; m2++)
                #pragma unroll
                for (int k = 0; k < 4; k++) {
                    wmma::load_matrix_sync(Ah[m2][k], &A1H[(32*r2 + 16*m2)*LDA1 + k*16], LDA1);
                    wmma::load_matrix_sync(Al[m2][k], &A1L[(32*r2 + 16*m2)*LDA1 + k*16], LDA1);
                }
            #pragma unroll
            for (int j = 0; j < 4; j++) {
                int jg = c2*64 + j*16;
                wmma::fragment<wmma::matrix_b, 16, 16, 16, __nv_bfloat16, wmma::col_major> Bh[4], Bl[4];
                #pragma unroll
                for (int k = 0; k < 4; k++) {
                    wmma::load_matrix_sync(Bh[k], &W2H[jg*LDW2 + k*16], LDW2);
                    wmma::load_matrix_sync(Bl[k], &W2L[jg*LDW2 + k*16], LDW2);
                }
                #pragma unroll
                for (int m2 = 0; m2 < 2; m2++) {
                    wmma::fragment<wmma::accumulator, 16, 16, 16, float> C;
                    wmma::fill_fragment(C, 0.f);
                    #pragma unroll
                    for (int k = 0; k < 4; k++) {
                        wmma::mma_sync(C, Ah[m2][k], Bh[k], C);
                        wmma::mma_sync(C, Al[m2][k], Bh[k], C);
                        wmma::mma_sync(C, Ah[m2][k], Bl[k], C);
                    }
                    // direct epilogue: bias+relu+split, pairs (i, i+1) are col-adjacent
                    int rowg0 = 32*r2 + 16*m2 + rbase;
                    #pragma unroll
                    for (int p = 0; p < 4; p++) {
                        int i0 = p*2;
                        int row = rowg0 + 8*((i0 >> 1) & 1);
                        int col = jg + cbase + 8*(i0 >> 2);
                        float v0 = fmaxf(C.x[i0]   + sB2[col],     0.f);
                        float v1 = fmaxf(C.x[i0+1] + sB2[col + 1], 0.f);
                        uint32_t hp = cvt2bf(v0, v1);
                        float h0 = __uint_as_float(hp << 16);
                        float h1 = __uint_as_float(hp & 0xffff0000u);
                        uint32_t lp = cvt2bf(v0 - h0, v1 - h1);
                        *(uint32_t*)&A2H[row*LDA2 + col] = hp;
                        *(uint32_t*)&A2L[row*LDA2 + col] = lp;
                    }
                }
            }
        }
        __syncthreads();
        // ---- L3: warp band rows, all 64 cols; direct column-max epilogue ----
        {
            wmma::fragment<wmma::matrix_a, 16, 16, 16, __nv_bfloat16, wmma::row_major> Ah[8], Al[8];
            #pragma unroll
            for (int k = 0; k < 8; k++) {
                wmma::load_matrix_sync(Ah[k], &A2H[band*LDA2 + k*16], LDA2);
                wmma::load_matrix_sync(Al[k], &A2L[band*LDA2 + k*16], LDA2);
            }
            #pragma unroll
            for (int nt = 0; nt < 4; nt++) {
                wmma::fragment<wmma::accumulator, 16, 16, 16, float> C;
                wmma::fill_fragment(C, 0.f);
                #pragma unroll
                for (int k = 0; k < 8; k++) {
                    wmma::fragment<wmma::matrix_b, 16, 16, 16, __nv_bfloat16, wmma::col_major> Bh, Bl;
                    wmma::load_matrix_sync(Bh, &W3H[nt*16*LDW3 + k*16], LDW3);
                    wmma::load_matrix_sync(Bl, &W3L[nt*16*LDW3 + k*16], LDW3);
                    wmma::mma_sync(C, Ah[k], Bh, C);
                    wmma::mma_sync(C, Al[k], Bh, C);
                    wmma::mma_sync(C, Ah[k], Bl, C);
                }
                // per-thread row-pair max: cols cbase, cbase+1, cbase+8, cbase+9
                cm[nt][0] = fmaxf(cm[nt][0], fmaxf(C.x[0], C.x[2]));
                cm[nt][1] = fmaxf(cm[nt][1], fmaxf(C.x[1], C.x[3]));
                cm[nt][2] = fmaxf(cm[nt][2], fmaxf(C.x[4], C.x[6]));
                cm[nt][3] = fmaxf(cm[nt][3], fmaxf(C.x[5], C.x[7]));
            }
        }
        __syncthreads();   // protect A1/A2 rewrite next tile
    }
    // cross-lane column max (lanes sharing lane&3 hold the same columns)
    #pragma unroll
    for (int nt = 0; nt < 4; nt++)
        #pragma unroll
        for (int q = 0; q < 4; q++) {
            float v = cm[nt][q];
            v = fmaxf(v, __shfl_xor_sync(0xffffffffu, v, 4));
            v = fmaxf(v, __shfl_xor_sync(0xffffffffu, v, 8));
            v = fmaxf(v, __shfl_xor_sync(0xffffffffu, v, 16));
            cm[nt][q] = v;
        }
    if (lane < 4) {
        #pragma unroll
        for (int nt = 0; nt < 4; nt++) {
            sRED[warp*64 + nt*16 + lane*2]     = cm[nt][0];
            sRED[warp*64 + nt*16 + lane*2 + 1] = cm[nt][1];
            sRED[warp*64 + nt*16 + lane*2 + 8] = cm[nt][2];
            sRED[warp*64 + nt*16 + lane*2 + 9] = cm[nt][3];
        }
    }
    __syncthreads();
    if (tid < 64) {
        float m = sRED[tid];
        #pragma unroll
        for (int w = 1; w < 8; w++) m = fmaxf(m, sRED[w*64 + tid]);
        g_h[item*128 + tid] = m + b3[tid];
    }
}

// ---------------- lstm body ----------------
__device__ void lstm_body(char* smc, int bid, const float* tb,
                          const float* wih0, const float* whh0,
                          const float* bih0, const float* bhh0,
                          const float* wih1, const float* whh1,
                          const float* bih1, const float* bhh1) {
    float* sm = (float*)smc;
    float* sWih0p = sm;
    float* sWih0s = sm + 2048;
    float* sWhh0p = sm + 2304;
    float* sWih1p = sm + 18688;
    float* sWhh1p = sm + 35072;
    float* sB0    = sm + 51456;
    float* sB1    = sm + 51712;
    float* sH     = sm + 51968;
    float* sHs0   = sm + 52096;
    float* sX     = sm + 53376;
    float* sG     = sm + 53576;

    int tid = threadIdx.x;
    int m0 = bid*2;

    for (int i = tid; i < 2304; i += 256) {
        int r = i/9, c = i%9; float v = wih0[i];
        if (c < 8) sWih0p[((c>>1)*256 + r)*2 + (c&1)] = v; else sWih0s[r] = v;
    }
    for (int i = tid; i < 16384; i += 256) { int r = i>>6, k = i&63; sWhh0p[((k>>1)*256+r)*2+(k&1)] = whh0[i]; }
    for (int i = tid; i < 16384; i += 256) { int r = i>>6, k = i&63; sWih1p[((k>>1)*256+r)*2+(k&1)] = wih1[i]; }
    for (int i = tid; i < 16384; i += 256) { int r = i>>6, k = i&63; sWhh1p[((k>>1)*256+r)*2+(k&1)] = whh1[i]; }
    if (tid < 256) { sB0[tid] = bih0[tid]+bhh0[tid]; sB1[tid] = bih1[tid]+bhh1[tid]; }
    for (int i = tid; i < 180; i += 256) {
        int tr = i/90, rest = i%90, t = rest/9, c = rest%9;
        sX[tr*100 + t*10 + c] = tb[(size_t)(m0+tr)*TSTE*9 + t*9 + c];
    }
    if (tid < 128) sH[tid] = 0.f;
    __syncthreads();

    int r = tid;
    int utr = tid >> 6, uu = tid & 63;
    float cc = 0.f;

    for (int t = 0; t < TSTE; t++) {
        ull a0 = 0ULL, a1 = 0ULL;
        const float* xb0 = sX + t*10;
        const float* xb1 = sX + 100 + t*10;
        #pragma unroll
        for (int c2 = 0; c2 < 4; c2++) {
            ull w = *(const ull*)&sWih0p[(c2*256 + r)*2];
            fma2(a0, *(const ull*)&xb0[2*c2], w);
            fma2(a1, *(const ull*)&xb1[2*c2], w);
        }
        float s0 = xb0[8]*sWih0s[r], s1 = xb1[8]*sWih0s[r];
        #pragma unroll 8
        for (int k2 = 0; k2 < 32; k2++) {
            ull w = *(const ull*)&sWhh0p[(k2*256 + r)*2];
            fma2(a0, *(const ull*)&sH[2*k2], w);
            fma2(a1, *(const ull*)&sH[64 + 2*k2], w);
        }
        float2 p0 = unpack2(a0), p1 = unpack2(a1);
        sG[r]     = p0.x + p0.y + s0 + sB0[r];
        sG[256+r] = p1.x + p1.y + s1 + sB0[r];
        __syncthreads();
        if (tid < 128) {
            float gi = sigmf(sG[utr*256 + uu]);
            float gf = sigmf(sG[utr*256 + 64 + uu]);
            float gg = tanhf_(sG[utr*256 + 128 + uu]);
            float go = sigmf(sG[utr*256 + 192 + uu]);
            cc = gf*cc + gi*gg;
            float hn = go*tanhf_(cc);
            sH[tid] = hn;
            sHs0[utr*640 + t*64 + uu] = hn;
        }
        __syncthreads();
    }
    if (tid < 128) sH[tid] = 0.f;
    cc = 0.f;
    __syncthreads();
    float hlast = 0.f;
    for (int t = 0; t < TSTE; t++) {
        ull a0 = 0ULL, a1 = 0ULL;
        #pragma unroll 8
        for (int k2 = 0; k2 < 32; k2++) {
            ull w = *(const ull*)&sWih1p[(k2*256 + r)*2];
            fma2(a0, *(const ull*)&sHs0[t*64 + 2*k2], w);
            fma2(a1, *(const ull*)&sHs0[640 + t*64 + 2*k2], w);
        }
        #pragma unroll 8
        for (int k2 = 0; k2 < 32; k2++) {
            ull w = *(const ull*)&sWhh1p[(k2*256 + r)*2];
            fma2(a0, *(const ull*)&sH[2*k2], w);
            fma2(a1, *(const ull*)&sH[64 + 2*k2], w);
        }
        float2 p0 = unpack2(a0), p1 = unpack2(a1);
        sG[r]     = p0.x + p0.y + sB1[r];
        sG[256+r] = p1.x + p1.y + sB1[r];
        __syncthreads();
        if (tid < 128) {
            float gi = sigmf(sG[utr*256 + uu]);
            float gf = sigmf(sG[utr*256 + 64 + uu]);
            float gg = tanhf_(sG[utr*256 + 128 + uu]);
            float go = sigmf(sG[utr*256 + 192 + uu]);
            cc = gf*cc + gi*gg;
            hlast = go*tanhf_(cc);
            sH[tid] = hlast;
        }
        __syncthreads();
    }
    if (tid < 128) g_h[(NDET + m0 + utr)*128 + 64 + uu] = hlast;
}

// ---------------- detmot body ----------------
__device__ void detmot_body(const float* boxes, const float* w1, const float* b1,
                            const float* w2, const float* b2) {
    int i = threadIdx.x;
    float x[9];
    #pragma unroll
    for (int c = 0; c < 9; c++) x[c] = boxes[i*9 + c];
    float h[32];
    #pragma unroll
    for (int r = 0; r < 32; r++) {
        float a = b1[r];
        #pragma unroll
        for (int c = 0; c < 9; c++) a += x[c]*w1[r*9 + c];
        h[r] = fmaxf(a, 0.f);
    }
    for (int o = 0; o < 64; o++) {
        float a = b2[o];
        #pragma unroll
        for (int r = 0; r < 32; r++) a += h[r]*w2[o*32 + r];
        g_h[i*128 + 64 + o] = a;
    }
}

// ---------------- mega kernel ----------------
__global__ __launch_bounds__(256) void mega_kernel(
    const float* det_pts, const float* trk_pts,
    const float* pn_w1, const float* pn_b1, const float* pn_w2, const float* pn_b2,
    const float* pn_w3, const float* pn_b3,
    const float* det_boxes, const float* dm_w1, const float* dm_b1,
    const float* dm_w2, const float* dm_b2,
    const float* tb, const float* wih0, const float* whh0,
    const float* bih0, const float* bhh0,
    const float* wih1, const float* whh1,
    const float* bih1, const float* bhh1,
    const float* gc_wt, const float* gc_bt, const float* gc_wp, const float* gc_bp,
    const float* er_w1, const int* adj) {
    extern __shared__ char smc[];
    int bid = blockIdx.x;
    if (bid < 128) {
        lstm_body(smc, bid, tb, wih0, whh0, bih0, bhh0, wih1, whh1, bih1, bhh1);
    } else if (bid == 128) {
        detmot_body(det_boxes, dm_w1, dm_b1, dm_w2, dm_b2);
    } else if (bid < 641) {
        pointnet_body(smc, bid - 129, det_pts, trk_pts,
                      pn_w1, pn_b1, pn_w2, pn_b2, pn_w3, pn_b3);
    } else {
        prep_body(bid - 641, gc_wt, gc_bt, gc_wp, gc_bp, er_w1, adj);
    }
}

// ---------------- EdgeConv A: 2 nodes per CTA, optional h reconstruction ----------------
__global__ void thq_kernel(int l, int rec) {
    __shared__ float sh[256];
    int tid = threadIdx.x;          // 256
    int sub = tid >> 7, c = tid & 127;
    int n = blockIdx.x*2 + sub;
    float hval;
    if (rec) {
        float m = fmaxf(fmaxf(g_epart[(n*4 + 0)*128 + c], g_epart[(n*4 + 1)*128 + c]),
                        fmaxf(g_epart[(n*4 + 2)*128 + c], g_epart[(n*4 + 3)*128 + c]));
        hval = fmaxf(m + g_Q[n*128 + c], 0.f);
        g_h[n*128 + c] = hval;   // keep g_h fresh (read by pproj for aff1)
    } else {
        hval = g_h[n*128 + c];
    }
    sh[tid] = hval;
    __syncthreads();
    const float* hv = sh + sub*128;
    const float* wtd = g_wtd + l*32768;
    ull acc = 0ULL;
    #pragma unroll 8
    for (int k = 0; k < 128; k++) {
        float h = hv[k];
        ull w = *(const ull*)&wtd[(k*128 + c)*2];
        fma2(acc, pack2(h, h), w);
    }
    float2 p = unpack2(acc);
    g_Th[n*128 + c] = p.x;
    g_Q[n*128 + c]  = p.y + g_bsum[l*128 + c];
}

// ---------------- EdgeConv B part: node x j-chunk partial max ----------------
__global__ void edge_part_kernel() {
    int bid = blockIdx.x;           // 2048 = 512 nodes x 4 chunks
    int i = bid >> 2, ch = bid & 3;
    int c = threadIdx.x;            // 128
    unsigned bw0 = g_mask[i*16 + ch*4 + 0];
    unsigned bw1 = g_mask[i*16 + ch*4 + 1];
    unsigned bw2 = g_mask[i*16 + ch*4 + 2];
    unsigned bw3 = g_mask[i*16 + ch*4 + 3];
    const float* Th = g_Th + (size_t)(ch*128)*128 + c;
    float m0 = -3.4e38f, m1 = m0, m2 = m0, m3 = m0;
    #pragma unroll
    for (int w = 0; w < 4; w++) {
        unsigned bits = (w == 0) ? bw0 : (w == 1) ? bw1 : (w == 2) ? bw2 : bw3;
        int jb = w*32;
        #pragma unroll
        for (int b = 0; b < 32; b += 4) {
            float v0 = Th[(jb + b)*128];
            float v1 = Th[(jb + b + 1)*128];
            float v2 = Th[(jb + b + 2)*128];
            float v3 = Th[(jb + b + 3)*128];
            if (bits & (1u << b))       m0 = fmaxf(m0, v0);
            if (bits & (1u << (b + 1))) m1 = fmaxf(m1, v1);
            if (bits & (1u << (b + 2))) m2 = fmaxf(m2, v2);
            if (bits & (1u << (b + 3))) m3 = fmaxf(m3, v3);
        }
    }
    g_epart[bid*128 + c] = fmaxf(fmaxf(m0, m1), fmaxf(m2, m3));
}

// ---------------- affinity projection (optional h reconstruction) ----------------
__global__ void pproj_kernel(int rec) {
    __shared__ float sh[128];
    int i = blockIdx.x, c = threadIdx.x;   // 64 threads, dets only
    float hv0, hv1;
    if (rec) {
        int c1 = c + 64;
        float m0 = fmaxf(fmaxf(g_epart[(i*4 + 0)*128 + c], g_epart[(i*4 + 1)*128 + c]),
                         fmaxf(g_epart[(i*4 + 2)*128 + c], g_epart[(i*4 + 3)*128 + c]));
        float m1 = fmaxf(fmaxf(g_epart[(i*4 + 0)*128 + c1], g_epart[(i*4 + 1)*128 + c1]),
                         fmaxf(g_epart[(i*4 + 2)*128 + c1], g_epart[(i*4 + 3)*128 + c1]));
        hv0 = fmaxf(m0 + g_Q[i*128 + c],  0.f);
        hv1 = fmaxf(m1 + g_Q[i*128 + c1], 0.f);
    } else {
        hv0 = g_h[i*128 + c];
        hv1 = g_h[i*128 + 64 + c];
    }
    sh[c]      = hv0;
    sh[64 + c] = hv1;
    __syncthreads();
    ull acc = 0ULL;
    #pragma unroll 8
    for (int k2 = 0; k2 < 64; k2++) {
        ull hv = *(const ull*)&sh[2*k2];
        ull w = *(const ull*)&g_w1p[(k2*64 + c)*2];
        fma2(acc, hv, w);
    }
    float2 p = unpack2(acc);
    g_P[i*64 + c] = p.x + p.y;
}

// ---------------- pairwise head ----------------
__global__ void pair_kernel(const float* b1, const float* w2, const float* b2, float* out) {
    __shared__ float sPi[16*65], sPj[16*65], sw2[64], sb1v[64];
    int tid = threadIdx.x;
    int ib = (blockIdx.x >> 4)*16, jb = (blockIdx.x & 15)*16;
    for (int t = tid; t < 1024; t += 256) {
        int r = t >> 6, c = t & 63;
        sPi[r*65 + c] = g_P[(ib + r)*64 + c];
        sPj[r*65 + c] = g_P[(jb + r)*64 + c];
    }
    if (tid < 64) { sw2[tid] = w2[tid]; sb1v[tid] = b1[tid]; }
    __syncthreads();
    int ti = tid >> 4, tj = tid & 15;
    float s = b2[0];
    #pragma unroll 8
    for (int c = 0; c < 64; c++)
        s += sw2[c]*fmaxf(sPj[tj*65 + c] - sPi[ti*65 + c] + sb1v[c], 0.f);
    out[(ib + ti)*256 + jb + tj] = sigmf(s);
}

// ---------------- launch ----------------
extern "C" void kernel_launch(void* const* d_in, const int* in_sizes, int n_in,
                              void* d_out, int out_size) {
    const float* det_pts   = (const float*)d_in[0];
    const float* det_boxes = (const float*)d_in[1];
    const float* trk_pts   = (const float*)d_in[2];
    const float* trk_boxes = (const float*)d_in[3];
    const int*   adj       = (const int*)  d_in[4];
    const float* pn_w1 = (const float*)d_in[5];
    const float* pn_b1 = (const float*)d_in[6];
    const float* pn_w2 = (const float*)d_in[7];
    const float* pn_b2 = (const float*)d_in[8];
    const float* pn_w3 = (const float*)d_in[9];
    const float* pn_b3 = (const float*)d_in[10];
    const float* dm_w1 = (const float*)d_in[11];
    const float* dm_b1 = (const float*)d_in[12];
    const float* dm_w2 = (const float*)d_in[13];
    const float* dm_b2 = (const float*)d_in[14];
    const float* l0_wih = (const float*)d_in[15];
    const float* l0_whh = (const float*)d_in[16];
    const float* l0_bih = (const float*)d_in[17];
    const float* l0_bhh = (const float*)d_in[18];
    const float* l1_wih = (const float*)d_in[19];
    const float* l1_whh = (const float*)d_in[20];
    const float* l1_bih = (const float*)d_in[21];
    const float* l1_bhh = (const float*)d_in[22];
    const float* gc_wt = (const float*)d_in[23];
    const float* gc_bt = (const float*)d_in[24];
    const float* gc_wp = (const float*)d_in[25];
    const float* gc_bp = (const float*)d_in[26];
    const float* er_w1 = (const float*)d_in[27];
    const float* er_b1 = (const float*)d_in[28];
    const float* er_w2 = (const float*)d_in[29];
    const float* er_b2 = (const float*)d_in[30];
    float* out = (float*)d_out;

    cudaFuncSetAttribute(mega_kernel, cudaFuncAttributeMaxDynamicSharedMemorySize,
                         MEGA_SMEM);

    mega_kernel<<<897, 256, MEGA_SMEM>>>(
        det_pts, trk_pts, pn_w1, pn_b1, pn_w2, pn_b2, pn_w3, pn_b3,
        det_boxes, dm_w1, dm_b1, dm_w2, dm_b2,
        trk_boxes, l0_wih, l0_whh, l0_bih, l0_bhh,
        l1_wih, l1_whh, l1_bih, l1_bhh,
        gc_wt, gc_bt, gc_wp, gc_bp, er_w1, adj);

    thq_kernel<<<256, 256>>>(0, 0);
    edge_part_kernel<<<2048, 128>>>();
    thq_kernel<<<256, 256>>>(1, 1);
    edge_part_kernel<<<2048, 128>>>();
    pproj_kernel<<<256, 64>>>(0);
    pair_kernel<<<256, 256>>>(er_b1, er_w2, er_b2, out);
    thq_kernel<<<256, 256>>>(2, 1);
    edge_part_kernel<<<2048, 128>>>();
    thq_kernel<<<256, 256>>>(3, 1);
    edge_part_kernel<<<2048, 128>>>();
    pproj_kernel<<<256, 64>>>(1);
    pair_kernel<<<256, 256>>>(er_b1, er_w2, er_b2, out + 65536);
}

// round 9
// speedup vs baseline: 2.2933x; 1.0065x over previous
#include <cuda_runtime.h>
#include <cuda_bf16.h>
#include <mma.h>
#include <math.h>
#include <stdint.h>

using namespace nvcuda;

#define NDET 256
#define MTRK 256
#define VN   512
#define PPTS 512
#define TSTE 10

typedef unsigned long long ull;

__device__ __forceinline__ void fma2(ull &d, ull a, ull b) {
    asm("fma.rn.f32x2 %0, %1, %2, %0;" : "+l"(d) : "l"(a), "l"(b));
}
__device__ __forceinline__ ull pack2(float x, float y) {
    ull r; asm("mov.b64 %0, {%1, %2};" : "=l"(r) : "f"(x), "f"(y)); return r;
}
__device__ __forceinline__ float2 unpack2(ull v) {
    float2 r; asm("mov.b64 {%0, %1}, %2;" : "=f"(r.x), "=f"(r.y) : "l"(v)); return r;
}
__device__ __forceinline__ float ex2a(float x) { float y; asm("ex2.approx.f32 %0, %1;" : "=f"(y) : "f"(x)); return y; }
__device__ __forceinline__ float rcpa(float x) { float y; asm("rcp.approx.f32 %0, %1;" : "=f"(y) : "f"(x)); return y; }
__device__ __forceinline__ float sigmf(float x) { return rcpa(1.f + ex2a(-1.4426950408889634f * x)); }
__device__ __forceinline__ float tanhf_(float x) { return 2.f * sigmf(2.f * x) - 1.f; }
__device__ __forceinline__ uint32_t cvt2bf(float v_even, float v_odd) {
    uint32_t r; asm("cvt.rn.bf16x2.f32 %0, %1, %2;" : "=r"(r) : "f"(v_odd), "f"(v_even)); return r;
}

// ---------------- device scratch ----------------
__device__ float g_h[VN*128];
__device__ float g_Th[VN*128];
__device__ float g_Q[VN*128];
__device__ float g_P[NDET*64];
__device__ float g_wtd[4*128*128*2];
__device__ float g_bsum[4*128];
__device__ float g_w1p[64*128];
__device__ unsigned g_mask[VN*16];
__device__ float g_epart[VN*4*128];

// ---------------- prep body ----------------
__device__ void prep_body(int pbid, const float* gc_wt, const float* gc_bt,
                          const float* gc_wp, const float* gc_bp,
                          const float* er_w1, const int* adj) {
    int idx = pbid*256 + threadIdx.x;
    int stride = 256*256;
    for (int i = idx; i < 4*128*128; i += stride) {
        int l = i >> 14, r = (i >> 7) & 127, k = i & 127;
        float wt = gc_wt[i], wp = gc_wp[i];
        g_wtd[l*32768 + (k*128 + r)*2 + 0] = wt;
        g_wtd[l*32768 + (k*128 + r)*2 + 1] = wp - wt;
    }
    for (int i = idx; i < 4*128; i += stride) g_bsum[i] = gc_bt[i] + gc_bp[i];
    for (int i = idx; i < 64*128; i += stride) {
        int r = i >> 7, k = i & 127;
        g_w1p[((k >> 1)*64 + r)*2 + (k & 1)] = er_w1[i];
    }
    for (int w = idx; w < VN*16; w += stride) {
        int i = w >> 4, wo = w & 15;
        unsigned bits = 0;
        #pragma unroll
        for (int b = 0; b < 32; b++) {
            int j = wo*32 + b;
            if (adj[j*VN + i] != 0 || j == i) bits |= (1u << b);
        }
        g_mask[w] = bits;
    }
}

// ---------------- PointNet smem layout (bytes) ----------------
#define PN_A1H   0
#define PN_A1L   18432
#define PN_W2H   36864
#define PN_W2L   55296
#define PN_A2H   73728
#define PN_A2L   108544
#define PN_W3H   143360
#define PN_W3L   160768
#define PN_AUX   178176

#define LDA1 72
#define LDW2 72
#define LDA2 136
#define LDW3 136

#define MEGA_SMEM 216352

__device__ __forceinline__ void bfsplit(float v, __nv_bfloat16 &hb, __nv_bfloat16 &lb) {
    hb = __float2bfloat16(v);
    lb = __float2bfloat16(v - __bfloat162float(hb));
}

// ---------------- pointnet body ----------------
__device__ void pointnet_body(char* smc, int item,
                              const float* det_pts, const float* trk_pts,
                              const float* w1, const float* b1,
                              const float* w2, const float* b2,
                              const float* w3, const float* b3) {
    __nv_bfloat16* A1H = (__nv_bfloat16*)(smc + PN_A1H);
    __nv_bfloat16* A1L = (__nv_bfloat16*)(smc + PN_A1L);
    __nv_bfloat16* W2H = (__nv_bfloat16*)(smc + PN_W2H);
    __nv_bfloat16* W2L = (__nv_bfloat16*)(smc + PN_W2L);
    __nv_bfloat16* A2H = (__nv_bfloat16*)(smc + PN_A2H);
    __nv_bfloat16* A2L = (__nv_bfloat16*)(smc + PN_A2L);
    __nv_bfloat16* W3H = (__nv_bfloat16*)(smc + PN_W3H);
    __nv_bfloat16* W3L = (__nv_bfloat16*)(smc + PN_W3L);
    float* sW1 = (float*)(smc + PN_AUX);
    float* sB1 = sW1 + 320;
    float* sB2 = sB1 + 64;
    float* sRED = sB2 + 128;

    int tid = threadIdx.x, warp = tid >> 5, lane = tid & 31;
    const float* pts = (item < NDET) ? det_pts + (size_t)item*PPTS*5
                                     : trk_pts + (size_t)(item-NDET)*PPTS*5;

    for (int i = tid; i < 320; i += 256) { int o = i/5, c = i%5; sW1[c*64+o] = w1[i]; }
    if (tid < 64)  sB1[tid] = b1[tid];
    if (tid < 128) sB2[tid] = b2[tid];
    for (int i = tid; i < 8192; i += 256) {
        int j = i >> 6, k = i & 63;
        __nv_bfloat16 hb, lb; bfsplit(w2[i], hb, lb);
        W2H[j*LDW2 + k] = hb; W2L[j*LDW2 + k] = lb;
    }
    for (int i = tid; i < 8192; i += 256) {
        int o = i >> 7, k = i & 127;
        __nv_bfloat16 hb, lb; bfsplit(w3[i], hb, lb);
        W3H[o*LDW3 + k] = hb; W3L[o*LDW3 + k] = lb;
    }
    __syncthreads();

    int rbase = lane >> 2, cbase = (lane & 3)*2;
    int r2 = warp >> 1, c2 = warp & 1;
    int band = warp*16;
    float cm[4][4];
    #pragma unroll
    for (int nt = 0; nt < 4; nt++)
        #pragma unroll
        for (int q = 0; q < 4; q++) cm[nt][q] = -3.4e38f;

    for (int t = 0; t < 4; t++) {
        {
            int rrow = lane & 15, rcolh = lane >> 4;
            const float* xp = pts + (size_t)(t*128 + band + rrow)*5;
            float x0 = xp[0], x1 = xp[1], x2 = xp[2], x3 = xp[3], x4 = xp[4];
            int ob = rcolh*32;
            int rowb = (band + rrow)*LDA1;
            #pragma unroll
            for (int o2 = 0; o2 < 16; o2++) {
                int o = ob + 2*o2;
                float v0 = sB1[o]   + x0*sW1[o]     + x1*sW1[64+o]     + x2*sW1[128+o]
                                    + x3*sW1[192+o] + x4*sW1[256+o];
                float v1 = sB1[o+1] + x0*sW1[o+1]   + x1*sW1[64+o+1]   + x2*sW1[128+o+1]
                                    + x3*sW1[192+o+1] + x4*sW1[256+o+1];
                v0 = fmaxf(v0, 0.f); v1 = fmaxf(v1, 0.f);
                uint32_t hp = cvt2bf(v0, v1);
                float h0 = __uint_as_float(hp << 16);
                float h1 = __uint_as_float(hp & 0xffff0000u);
                uint32_t lp = cvt2bf(v0 - h0, v1 - h1);
                *(uint32_t*)&A1H[rowb + o] = hp;
                *(uint32_t*)&A1L[rowb + o] = lp;
            }
        }
        __syncthreads();
        {
            wmma::fragment<wmma::matrix_a, 16, 16, 16, __nv_bfloat16, wmma::row_major> Ah[2][4], Al[2][4];
            #pragma unroll
            for (int m2 = 0; m2 < 2; m2++)
                #pragma unroll
                for (int k = 0; k < 4; k++) {
                    wmma::load_matrix_sync(Ah[m2][k], &A1H[(32*r2 + 16*m2)*LDA1 + k*16], LDA1);
                    wmma::load_matrix_sync(Al[m2][k], &A1L[(32*r2 + 16*m2)*LDA1 + k*16], LDA1);
                }
            #pragma unroll
            for (int j = 0; j < 4; j++) {
                int jg = c2*64 + j*16;
                wmma::fragment<wmma::matrix_b, 16, 16, 16, __nv_bfloat16, wmma::col_major> Bh[4], Bl[4];
                #pragma unroll
                for (int k = 0; k < 4; k++) {
                    wmma::load_matrix_sync(Bh[k], &W2H[jg*LDW2 + k*16], LDW2);
                    wmma::load_matrix_sync(Bl[k], &W2L[jg*LDW2 + k*16], LDW2);
                }
                #pragma unroll
                for (int m2 = 0; m2 < 2; m2++) {
                    wmma::fragment<wmma::accumulator, 16, 16, 16, float> C;
                    wmma::fill_fragment(C, 0.f);
                    #pragma unroll
                    for (int k = 0; k < 4; k++) {
                        wmma::mma_sync(C, Ah[m2][k], Bh[k], C);
                        wmma::mma_sync(C, Al[m2][k], Bh[k], C);
                        wmma::mma_sync(C, Ah[m2][k], Bl[k], C);
                    }
                    int rowg0 = 32*r2 + 16*m2 + rbase;
                    #pragma unroll
                    for (int p = 0; p < 4; p++) {
                        int i0 = p*2;
                        int row = rowg0 + 8*((i0 >> 1) & 1);
                        int col = jg + cbase + 8*(i0 >> 2);
                        float v0 = fmaxf(C.x[i0]   + sB2[col],     0.f);
                        float v1 = fmaxf(C.x[i0+1] + sB2[col + 1], 0.f);
                        uint32_t hp = cvt2bf(v0, v1);
                        float h0 = __uint_as_float(hp << 16);
                        float h1 = __uint_as_float(hp & 0xffff0000u);
                        uint32_t lp = cvt2bf(v0 - h0, v1 - h1);
                        *(uint32_t*)&A2H[row*LDA2 + col] = hp;
                        *(uint32_t*)&A2L[row*LDA2 + col] = lp;
                    }
                }
            }
        }
        __syncthreads();
        {
            wmma::fragment<wmma::matrix_a, 16, 16, 16, __nv_bfloat16, wmma::row_major> Ah[8], Al[8];
            #pragma unroll
            for (int k = 0; k < 8; k++) {
                wmma::load_matrix_sync(Ah[k], &A2H[band*LDA2 + k*16], LDA2);
                wmma::load_matrix_sync(Al[k], &A2L[band*LDA2 + k*16], LDA2);
            }
            #pragma unroll
            for (int nt = 0; nt < 4; nt++) {
                wmma::fragment<wmma::accumulator, 16, 16, 16, float> C;
                wmma::fill_fragment(C, 0.f);
                #pragma unroll
                for (int k = 0; k < 8; k++) {
                    wmma::fragment<wmma::matrix_b, 16, 16, 16, __nv_bfloat16, wmma::col_major> Bh, Bl;
                    wmma::load_matrix_sync(Bh, &W3H[nt*16*LDW3 + k*16], LDW3);
                    wmma::load_matrix_sync(Bl, &W3L[nt*16*LDW3 + k*16], LDW3);
                    wmma::mma_sync(C, Ah[k], Bh, C);
                    wmma::mma_sync(C, Al[k], Bh, C);
                    wmma::mma_sync(C, Ah[k], Bl, C);
                }
                cm[nt][0] = fmaxf(cm[nt][0], fmaxf(C.x[0], C.x[2]));
                cm[nt][1] = fmaxf(cm[nt][1], fmaxf(C.x[1], C.x[3]));
                cm[nt][2] = fmaxf(cm[nt][2], fmaxf(C.x[4], C.x[6]));
                cm[nt][3] = fmaxf(cm[nt][3], fmaxf(C.x[5], C.x[7]));
            }
        }
        __syncthreads();
    }
    #pragma unroll
    for (int nt = 0; nt < 4; nt++)
        #pragma unroll
        for (int q = 0; q < 4; q++) {
            float v = cm[nt][q];
            v = fmaxf(v, __shfl_xor_sync(0xffffffffu, v, 4));
            v = fmaxf(v, __shfl_xor_sync(0xffffffffu, v, 8));
            v = fmaxf(v, __shfl_xor_sync(0xffffffffu, v, 16));
            cm[nt][q] = v;
        }
    if (lane < 4) {
        #pragma unroll
        for (int nt = 0; nt < 4; nt++) {
            sRED[warp*64 + nt*16 + lane*2]     = cm[nt][0];
            sRED[warp*64 + nt*16 + lane*2 + 1] = cm[nt][1];
            sRED[warp*64 + nt*16 + lane*2 + 8] = cm[nt][2];
            sRED[warp*64 + nt*16 + lane*2 + 9] = cm[nt][3];
        }
    }
    __syncthreads();
    if (tid < 64) {
        float m = sRED[tid];
        #pragma unroll
        for (int w = 1; w < 8; w++) m = fmaxf(m, sRED[w*64 + tid]);
        g_h[item*128 + tid] = m + b3[tid];
    }
}

// ---------------- lstm body ----------------
__device__ void lstm_body(char* smc, int bid, const float* tb,
                          const float* wih0, const float* whh0,
                          const float* bih0, const float* bhh0,
                          const float* wih1, const float* whh1,
                          const float* bih1, const float* bhh1) {
    float* sm = (float*)smc;
    float* sWih0p = sm;
    float* sWih0s = sm + 2048;
    float* sWhh0p = sm + 2304;
    float* sWih1p = sm + 18688;
    float* sWhh1p = sm + 35072;
    float* sB0    = sm + 51456;
    float* sB1    = sm + 51712;
    float* sH     = sm + 51968;
    float* sHs0   = sm + 52096;
    float* sX     = sm + 53376;
    float* sG     = sm + 53576;

    int tid = threadIdx.x;
    int m0 = bid*2;

    for (int i = tid; i < 2304; i += 256) {
        int r = i/9, c = i%9; float v = wih0[i];
        if (c < 8) sWih0p[((c>>1)*256 + r)*2 + (c&1)] = v; else sWih0s[r] = v;
    }
    for (int i = tid; i < 16384; i += 256) { int r = i>>6, k = i&63; sWhh0p[((k>>1)*256+r)*2+(k&1)] = whh0[i]; }
    for (int i = tid; i < 16384; i += 256) { int r = i>>6, k = i&63; sWih1p[((k>>1)*256+r)*2+(k&1)] = wih1[i]; }
    for (int i = tid; i < 16384; i += 256) { int r = i>>6, k = i&63; sWhh1p[((k>>1)*256+r)*2+(k&1)] = whh1[i]; }
    if (tid < 256) { sB0[tid] = bih0[tid]+bhh0[tid]; sB1[tid] = bih1[tid]+bhh1[tid]; }
    for (int i = tid; i < 180; i += 256) {
        int tr = i/90, rest = i%90, t = rest/9, c = rest%9;
        sX[tr*100 + t*10 + c] = tb[(size_t)(m0+tr)*TSTE*9 + t*9 + c];
    }
    if (tid < 128) sH[tid] = 0.f;
    __syncthreads();

    int r = tid;
    int utr = tid >> 6, uu = tid & 63;
    float cc = 0.f;

    for (int t = 0; t < TSTE; t++) {
        ull a0 = 0ULL, a1 = 0ULL;
        const float* xb0 = sX + t*10;
        const float* xb1 = sX + 100 + t*10;
        #pragma unroll
        for (int c2 = 0; c2 < 4; c2++) {
            ull w = *(const ull*)&sWih0p[(c2*256 + r)*2];
            fma2(a0, *(const ull*)&xb0[2*c2], w);
            fma2(a1, *(const ull*)&xb1[2*c2], w);
        }
        float s0 = xb0[8]*sWih0s[r], s1 = xb1[8]*sWih0s[r];
        #pragma unroll 8
        for (int k2 = 0; k2 < 32; k2++) {
            ull w = *(const ull*)&sWhh0p[(k2*256 + r)*2];
            fma2(a0, *(const ull*)&sH[2*k2], w);
            fma2(a1, *(const ull*)&sH[64 + 2*k2], w);
        }
        float2 p0 = unpack2(a0), p1 = unpack2(a1);
        sG[r]     = p0.x + p0.y + s0 + sB0[r];
        sG[256+r] = p1.x + p1.y + s1 + sB0[r];
        __syncthreads();
        if (tid < 128) {
            float gi = sigmf(sG[utr*256 + uu]);
            float gf = sigmf(sG[utr*256 + 64 + uu]);
            float gg = tanhf_(sG[utr*256 + 128 + uu]);
            float go = sigmf(sG[utr*256 + 192 + uu]);
            cc = gf*cc + gi*gg;
            float hn = go*tanhf_(cc);
            sH[tid] = hn;
            sHs0[utr*640 + t*64 + uu] = hn;
        }
        __syncthreads();
    }
    if (tid < 128) sH[tid] = 0.f;
    cc = 0.f;
    __syncthreads();
    float hlast = 0.f;
    for (int t = 0; t < TSTE; t++) {
        ull a0 = 0ULL, a1 = 0ULL;
        #pragma unroll 8
        for (int k2 = 0; k2 < 32; k2++) {
            ull w = *(const ull*)&sWih1p[(k2*256 + r)*2];
            fma2(a0, *(const ull*)&sHs0[t*64 + 2*k2], w);
            fma2(a1, *(const ull*)&sHs0[640 + t*64 + 2*k2], w);
        }
        #pragma unroll 8
        for (int k2 = 0; k2 < 32; k2++) {
            ull w = *(const ull*)&sWhh1p[(k2*256 + r)*2];
            fma2(a0, *(const ull*)&sH[2*k2], w);
            fma2(a1, *(const ull*)&sH[64 + 2*k2], w);
        }
        float2 p0 = unpack2(a0), p1 = unpack2(a1);
        sG[r]     = p0.x + p0.y + sB1[r];
        sG[256+r] = p1.x + p1.y + sB1[r];
        __syncthreads();
        if (tid < 128) {
            float gi = sigmf(sG[utr*256 + uu]);
            float gf = sigmf(sG[utr*256 + 64 + uu]);
            float gg = tanhf_(sG[utr*256 + 128 + uu]);
            float go = sigmf(sG[utr*256 + 192 + uu]);
            cc = gf*cc + gi*gg;
            hlast = go*tanhf_(cc);
            sH[tid] = hlast;
        }
        __syncthreads();
    }
    if (tid < 128) g_h[(NDET + m0 + utr)*128 + 64 + uu] = hlast;
}

// ---------------- detmot body ----------------
__device__ void detmot_body(const float* boxes, const float* w1, const float* b1,
                            const float* w2, const float* b2) {
    int i = threadIdx.x;
    float x[9];
    #pragma unroll
    for (int c = 0; c < 9; c++) x[c] = boxes[i*9 + c];
    float h[32];
    #pragma unroll
    for (int r = 0; r < 32; r++) {
        float a = b1[r];
        #pragma unroll
        for (int c = 0; c < 9; c++) a += x[c]*w1[r*9 + c];
        h[r] = fmaxf(a, 0.f);
    }
    for (int o = 0; o < 64; o++) {
        float a = b2[o];
        #pragma unroll
        for (int r = 0; r < 32; r++) a += h[r]*w2[o*32 + r];
        g_h[i*128 + 64 + o] = a;
    }
}

// ---------------- mega kernel ----------------
__global__ __launch_bounds__(256) void mega_kernel(
    const float* det_pts, const float* trk_pts,
    const float* pn_w1, const float* pn_b1, const float* pn_w2, const float* pn_b2,
    const float* pn_w3, const float* pn_b3,
    const float* det_boxes, const float* dm_w1, const float* dm_b1,
    const float* dm_w2, const float* dm_b2,
    const float* tb, const float* wih0, const float* whh0,
    const float* bih0, const float* bhh0,
    const float* wih1, const float* whh1,
    const float* bih1, const float* bhh1,
    const float* gc_wt, const float* gc_bt, const float* gc_wp, const float* gc_bp,
    const float* er_w1, const int* adj) {
    extern __shared__ char smc[];
    int bid = blockIdx.x;
    if (bid < 128) {
        lstm_body(smc, bid, tb, wih0, whh0, bih0, bhh0, wih1, whh1, bih1, bhh1);
    } else if (bid == 128) {
        detmot_body(det_boxes, dm_w1, dm_b1, dm_w2, dm_b2);
    } else if (bid < 641) {
        pointnet_body(smc, bid - 129, det_pts, trk_pts,
                      pn_w1, pn_b1, pn_w2, pn_b2, pn_w3, pn_b3);
    } else {
        prep_body(bid - 641, gc_wt, gc_bt, gc_wp, gc_bp, er_w1, adj);
    }
}

// ---------------- EdgeConv A: 2 nodes per CTA, 4 independent accumulator chains ----------------
__global__ void thq_kernel(int l, int rec) {
    __shared__ float sh[256];
    int tid = threadIdx.x;          // 256
    int sub = tid >> 7, c = tid & 127;
    int n = blockIdx.x*2 + sub;
    float hval;
    if (rec) {
        float m = fmaxf(fmaxf(g_epart[(n*4 + 0)*128 + c], g_epart[(n*4 + 1)*128 + c]),
                        fmaxf(g_epart[(n*4 + 2)*128 + c], g_epart[(n*4 + 3)*128 + c]));
        hval = fmaxf(m + g_Q[n*128 + c], 0.f);
        g_h[n*128 + c] = hval;   // keep g_h fresh (read by pproj for aff1)
    } else {
        hval = g_h[n*128 + c];
    }
    sh[tid] = hval;
    __syncthreads();
    const float* hv = sh + sub*128;
    const float* wtd = g_wtd + l*32768;
    ull ac0 = 0ULL, ac1 = 0ULL, ac2 = 0ULL, ac3 = 0ULL;
    #pragma unroll 4
    for (int k = 0; k < 128; k += 4) {
        float h0 = hv[k],   h1 = hv[k+1], h2 = hv[k+2], h3 = hv[k+3];
        ull w0 = *(const ull*)&wtd[((k  )*128 + c)*2];
        ull w1 = *(const ull*)&wtd[((k+1)*128 + c)*2];
        ull w2 = *(const ull*)&wtd[((k+2)*128 + c)*2];
        ull w3 = *(const ull*)&wtd[((k+3)*128 + c)*2];
        fma2(ac0, pack2(h0, h0), w0);
        fma2(ac1, pack2(h1, h1), w1);
        fma2(ac2, pack2(h2, h2), w2);
        fma2(ac3, pack2(h3, h3), w3);
    }
    float2 p0 = unpack2(ac0), p1 = unpack2(ac1), p2 = unpack2(ac2), p3 = unpack2(ac3);
    g_Th[n*128 + c] = (p0.x + p1.x) + (p2.x + p3.x);
    g_Q[n*128 + c]  = (p0.y + p1.y) + (p2.y + p3.y) + g_bsum[l*128 + c];
}

// ---------------- EdgeConv B part: node x j-chunk partial max ----------------
__global__ void edge_part_kernel() {
    int bid = blockIdx.x;           // 2048 = 512 nodes x 4 chunks
    int i = bid >> 2, ch = bid & 3;
    int c = threadIdx.x;            // 128
    unsigned bw0 = g_mask[i*16 + ch*4 + 0];
    unsigned bw1 = g_mask[i*16 + ch*4 + 1];
    unsigned bw2 = g_mask[i*16 + ch*4 + 2];
    unsigned bw3 = g_mask[i*16 + ch*4 + 3];
    const float* Th = g_Th + (size_t)(ch*128)*128 + c;
    float m0 = -3.4e38f, m1 = m0, m2 = m0, m3 = m0;
    #pragma unroll
    for (int w = 0; w < 4; w++) {
        unsigned bits = (w == 0) ? bw0 : (w == 1) ? bw1 : (w == 2) ? bw2 : bw3;
        int jb = w*32;
        #pragma unroll
        for (int b = 0; b < 32; b += 4) {
            float v0 = Th[(jb + b)*128];
            float v1 = Th[(jb + b + 1)*128];
            float v2 = Th[(jb + b + 2)*128];
            float v3 = Th[(jb + b + 3)*128];
            if (bits & (1u << b))       m0 = fmaxf(m0, v0);
            if (bits & (1u << (b + 1))) m1 = fmaxf(m1, v1);
            if (bits & (1u << (b + 2))) m2 = fmaxf(m2, v2);
            if (bits & (1u << (b + 3))) m3 = fmaxf(m3, v3);
        }
    }
    g_epart[bid*128 + c] = fmaxf(fmaxf(m0, m1), fmaxf(m2, m3));
}

// ---------------- affinity projection (2 chains) ----------------
__global__ void pproj_kernel(int rec) {
    __shared__ float sh[128];
    int i = blockIdx.x, c = threadIdx.x;   // 64 threads, dets only
    float hv0, hv1;
    if (rec) {
        int c1 = c + 64;
        float m0 = fmaxf(fmaxf(g_epart[(i*4 + 0)*128 + c], g_epart[(i*4 + 1)*128 + c]),
                         fmaxf(g_epart[(i*4 + 2)*128 + c], g_epart[(i*4 + 3)*128 + c]));
        float m1 = fmaxf(fmaxf(g_epart[(i*4 + 0)*128 + c1], g_epart[(i*4 + 1)*128 + c1]),
                         fmaxf(g_epart[(i*4 + 2)*128 + c1], g_epart[(i*4 + 3)*128 + c1]));
        hv0 = fmaxf(m0 + g_Q[i*128 + c],  0.f);
        hv1 = fmaxf(m1 + g_Q[i*128 + c1], 0.f);
    } else {
        hv0 = g_h[i*128 + c];
        hv1 = g_h[i*128 + 64 + c];
    }
    sh[c]      = hv0;
    sh[64 + c] = hv1;
    __syncthreads();
    ull acA = 0ULL, acB = 0ULL;
    #pragma unroll 8
    for (int k2 = 0; k2 < 64; k2 += 2) {
        fma2(acA, *(const ull*)&sh[2*k2],     *(const ull*)&g_w1p[(k2*64 + c)*2]);
        fma2(acB, *(const ull*)&sh[2*k2 + 2], *(const ull*)&g_w1p[((k2 + 1)*64 + c)*2]);
    }
    float2 pA = unpack2(acA), pB = unpack2(acB);
    g_P[i*64 + c] = (pA.x + pA.y) + (pB.x + pB.y);
}

// ---------------- pairwise head (2 chains) ----------------
__global__ void pair_kernel(const float* b1, const float* w2, const float* b2, float* out) {
    __shared__ float sPi[16*65], sPj[16*65], sw2[64], sb1v[64];
    int tid = threadIdx.x;
    int ib = (blockIdx.x >> 4)*16, jb = (blockIdx.x & 15)*16;
    for (int t = tid; t < 1024; t += 256) {
        int r = t >> 6, c = t & 63;
        sPi[r*65 + c] = g_P[(ib + r)*64 + c];
        sPj[r*65 + c] = g_P[(jb + r)*64 + c];
    }
    if (tid < 64) { sw2[tid] = w2[tid]; sb1v[tid] = b1[tid]; }
    __syncthreads();
    int ti = tid >> 4, tj = tid & 15;
    float sA = 0.f, sB = 0.f;
    #pragma unroll 8
    for (int c = 0; c < 64; c += 2) {
        sA += sw2[c]    *fmaxf(sPj[tj*65 + c]     - sPi[ti*65 + c]     + sb1v[c],     0.f);
        sB += sw2[c + 1]*fmaxf(sPj[tj*65 + c + 1] - sPi[ti*65 + c + 1] + sb1v[c + 1], 0.f);
    }
    out[(ib + ti)*256 + jb + tj] = sigmf(sA + sB + b2[0]);
}

// ---------------- launch ----------------
extern "C" void kernel_launch(void* const* d_in, const int* in_sizes, int n_in,
                              void* d_out, int out_size) {
    const float* det_pts   = (const float*)d_in[0];
    const float* det_boxes = (const float*)d_in[1];
    const float* trk_pts   = (const float*)d_in[2];
    const float* trk_boxes = (const float*)d_in[3];
    const int*   adj       = (const int*)  d_in[4];
    const float* pn_w1 = (const float*)d_in[5];
    const float* pn_b1 = (const float*)d_in[6];
    const float* pn_w2 = (const float*)d_in[7];
    const float* pn_b2 = (const float*)d_in[8];
    const float* pn_w3 = (const float*)d_in[9];
    const float* pn_b3 = (const float*)d_in[10];
    const float* dm_w1 = (const float*)d_in[11];
    const float* dm_b1 = (const float*)d_in[12];
    const float* dm_w2 = (const float*)d_in[13];
    const float* dm_b2 = (const float*)d_in[14];
    const float* l0_wih = (const float*)d_in[15];
    const float* l0_whh = (const float*)d_in[16];
    const float* l0_bih = (const float*)d_in[17];
    const float* l0_bhh = (const float*)d_in[18];
    const float* l1_wih = (const float*)d_in[19];
    const float* l1_whh = (const float*)d_in[20];
    const float* l1_bih = (const float*)d_in[21];
    const float* l1_bhh = (const float*)d_in[22];
    const float* gc_wt = (const float*)d_in[23];
    const float* gc_bt = (const float*)d_in[24];
    const float* gc_wp = (const float*)d_in[25];
    const float* gc_bp = (const float*)d_in[26];
    const float* er_w1 = (const float*)d_in[27];
    const float* er_b1 = (const float*)d_in[28];
    const float* er_w2 = (const float*)d_in[29];
    const float* er_b2 = (const float*)d_in[30];
    float* out = (float*)d_out;

    cudaFuncSetAttribute(mega_kernel, cudaFuncAttributeMaxDynamicSharedMemorySize,
                         MEGA_SMEM);

    mega_kernel<<<897, 256, MEGA_SMEM>>>(
        det_pts, trk_pts, pn_w1, pn_b1, pn_w2, pn_b2, pn_w3, pn_b3,
        det_boxes, dm_w1, dm_b1, dm_w2, dm_b2,
        trk_boxes, l0_wih, l0_whh, l0_bih, l0_bhh,
        l1_wih, l1_whh, l1_bih, l1_bhh,
        gc_wt, gc_bt, gc_wp, gc_bp, er_w1, adj);

    thq_kernel<<<256, 256>>>(0, 0);
    edge_part_kernel<<<2048, 128>>>();
    thq_kernel<<<256, 256>>>(1, 1);
    edge_part_kernel<<<2048, 128>>>();
    pproj_kernel<<<256, 64>>>(0);
    pair_kernel<<<256, 256>>>(er_b1, er_w2, er_b2, out);
    thq_kernel<<<256, 256>>>(2, 1);
    edge_part_kernel<<<2048, 128>>>();
    thq_kernel<<<256, 256>>>(3, 1);
    edge_part_kernel<<<2048, 128>>>();
    pproj_kernel<<<256, 64>>>(1);
    pair_kernel<<<256, 256>>>(er_b1, er_w2, er_b2, out + 65536);
}